// round 4
// baseline (speedup 1.0000x reference)
#include <cuda_runtime.h>
#include <math.h>
#include <stdint.h>

#define Bb 8
#define Ll 512
#define Dd 1024
#define Hh 16
#define DKk 64
#define DVv 64
#define EPSF 1e-20f

#define BH (Bb*Hh)           // 128
#define NPOS (Bb*Hh*Ll)      // 65536
#define MROWS (Bb*Ll)        // 4096

// ---------------- scratch (static device globals; no allocation) ----------------
__device__ float g_q[NPOS*DKk];          // [B,H,L,DK]  (pre-scaled by 8)
__device__ float g_k[NPOS*DKk];
__device__ float g_v[NPOS*DVv];
__device__ float g_S[(size_t)BH*Ll*Ll];  // scores -> att_s  (134 MB)
__device__ float g_ao[MROWS*Dd];         // attn out reordered [B,L,H*DV]
__device__ float g_pp[8*NPOS];           // prior partials
__device__ float g_dotg[NPOS];
__device__ float g_alpha[NPOS];
__device__ double g_kl;
// tf32 split buffers (reused sequentially across the 4 projections)
__device__ float g_ah[MROWS*Dd];         // activation hi
__device__ float g_al[MROWS*Dd];         // activation lo
__device__ float g_wh[Dd*Dd];            // weight^T hi  [N,K]
__device__ float g_wl[Dd*Dd];            // weight^T lo

// ---------------- helpers ----------------
__device__ __forceinline__ float tf32_rn(float a) {
    uint32_t r;
    asm("cvt.rna.tf32.f32 %0, %1;" : "=r"(r) : "f"(a));
    return __uint_as_float(r);
}

__device__ __forceinline__ void mma_tf32(float* c, const uint32_t* a, const uint32_t* b) {
    asm volatile(
        "mma.sync.aligned.m16n8k8.row.col.f32.tf32.tf32.f32 "
        "{%0,%1,%2,%3}, {%4,%5,%6,%7}, {%8,%9}, {%0,%1,%2,%3};"
        : "+f"(c[0]), "+f"(c[1]), "+f"(c[2]), "+f"(c[3])
        : "r"(a[0]), "r"(a[1]), "r"(a[2]), "r"(a[3]), "r"(b[0]), "r"(b[1]));
}

// ---------------- tf32 split kernels ----------------
__global__ __launch_bounds__(256) void split_act(const float* __restrict__ in,
                                                 float* __restrict__ hi,
                                                 float* __restrict__ lo) {
    int i = (blockIdx.x * 256 + threadIdx.x) * 4;
    float4 a = *(const float4*)(in + i);
    float4 h, l;
    h.x = tf32_rn(a.x); l.x = tf32_rn(a.x - h.x);
    h.y = tf32_rn(a.y); l.y = tf32_rn(a.y - h.y);
    h.z = tf32_rn(a.z); l.z = tf32_rn(a.z - h.z);
    h.w = tf32_rn(a.w); l.w = tf32_rn(a.w - h.w);
    *(float4*)(hi + i) = h;
    *(float4*)(lo + i) = l;
}

// W [K=1024, N=1024] row-major -> W^T hi/lo [N, K]
__global__ void split_w_t(const float* __restrict__ W,
                          float* __restrict__ Th, float* __restrict__ Tl) {
    __shared__ float t[32][33];
    int bx = blockIdx.x * 32, by = blockIdx.y * 32;
    int tx = threadIdx.x, ty = threadIdx.y;     // 32 x 8
    #pragma unroll
    for (int j = 0; j < 4; j++)
        t[ty + 8 * j][tx] = W[(size_t)(by + ty + 8 * j) * 1024 + bx + tx];
    __syncthreads();
    #pragma unroll
    for (int j = 0; j < 4; j++) {
        float a = t[tx][ty + 8 * j];
        float h = tf32_rn(a);
        size_t o = (size_t)(bx + ty + 8 * j) * 1024 + by + tx;
        Th[o] = h;
        Tl[o] = tf32_rn(a - h);
    }
}

// ---------------- 3xTF32 mma.sync GEMM: [4096,1024] x [1024,1024] ----------------
// A hi/lo [M,K] row-major; Bt hi/lo [N,K] row-major (= W^T, k-contiguous = col-major B).
// C = A @ W + bias, scale; scatter=1 -> head layout [B,H,L,64]
// CTA tile 128x128, kb=16, double-buffered smem (stride 20 floats -> conflict-free frags).
#define KB 16
#define KSTR 20
#define MATF 2560            // 128*20 floats per matrix per stage
#define STAGEF 10240         // 4 matrices per stage
__global__ __launch_bounds__(256, 1) void mma_gemm(const float* __restrict__ Ah,
                                                   const float* __restrict__ Al,
                                                   const float* __restrict__ Bh,
                                                   const float* __restrict__ Bl,
                                                   const float* __restrict__ bias,
                                                   float* __restrict__ C,
                                                   int scatter, float scale)
{
    extern __shared__ float sm[];      // 2 stages * 4 matrices * 128*20 floats = 80KB
    int tid = threadIdx.x;
    int lane = tid & 31, wid = tid >> 5;
    int g = lane >> 2, t4 = lane & 3;
    int warp_m = wid & 1;              // 2 warps over M (64 rows each)
    int warp_n = wid >> 1;             // 4 warps over N (32 cols each)
    int row0 = blockIdx.y * 128;
    int col0 = blockIdx.x * 128;

    float acc[4][4][4];
    #pragma unroll
    for (int mt = 0; mt < 4; mt++)
        #pragma unroll
        for (int nt = 0; nt < 4; nt++)
            #pragma unroll
            for (int q = 0; q < 4; q++) acc[mt][nt][q] = 0.f;

    // global load indices: 512 float4 per matrix-stage, 256 threads -> 2 each
    int r0i = tid >> 2,        s0i = tid & 3;          // idx = tid
    int r1i = (tid + 256) >> 2, s1i = tid & 3;         // idx = tid + 256 (seg same)
    const float* pAh0 = Ah + (size_t)(row0 + r0i) * 1024 + s0i * 4;
    const float* pAh1 = Ah + (size_t)(row0 + r1i) * 1024 + s1i * 4;
    const float* pAl0 = Al + (size_t)(row0 + r0i) * 1024 + s0i * 4;
    const float* pAl1 = Al + (size_t)(row0 + r1i) * 1024 + s1i * 4;
    const float* pBh0 = Bh + (size_t)(col0 + r0i) * 1024 + s0i * 4;
    const float* pBh1 = Bh + (size_t)(col0 + r1i) * 1024 + s1i * 4;
    const float* pBl0 = Bl + (size_t)(col0 + r0i) * 1024 + s0i * 4;
    const float* pBl1 = Bl + (size_t)(col0 + r1i) * 1024 + s1i * 4;
    // smem store offsets (floats)
    int so0 = r0i * KSTR + s0i * 4;
    int so1 = r1i * KSTR + s1i * 4;

    // preload stage 0
    {
        *(float4*)(sm + 0*MATF + so0) = *(const float4*)(pAh0);
        *(float4*)(sm + 0*MATF + so1) = *(const float4*)(pAh1);
        *(float4*)(sm + 1*MATF + so0) = *(const float4*)(pAl0);
        *(float4*)(sm + 1*MATF + so1) = *(const float4*)(pAl1);
        *(float4*)(sm + 2*MATF + so0) = *(const float4*)(pBh0);
        *(float4*)(sm + 2*MATF + so1) = *(const float4*)(pBh1);
        *(float4*)(sm + 3*MATF + so0) = *(const float4*)(pBl0);
        *(float4*)(sm + 3*MATF + so1) = *(const float4*)(pBl1);
    }
    __syncthreads();

    const int NSTAGE = 1024 / KB;      // 64
    for (int ks = 0; ks < NSTAGE; ks++) {
        int buf = ks & 1;
        float4 vah0, vah1, val0, val1, vbh0, vbh1, vbl0, vbl1;
        bool more = (ks + 1 < NSTAGE);
        if (more) {
            int k0 = (ks + 1) * KB;
            vah0 = *(const float4*)(pAh0 + k0);
            vah1 = *(const float4*)(pAh1 + k0);
            val0 = *(const float4*)(pAl0 + k0);
            val1 = *(const float4*)(pAl1 + k0);
            vbh0 = *(const float4*)(pBh0 + k0);
            vbh1 = *(const float4*)(pBh1 + k0);
            vbl0 = *(const float4*)(pBl0 + k0);
            vbl1 = *(const float4*)(pBl1 + k0);
        }

        const float* base = sm + buf * STAGEF;
        const float* Abh = base + 0*MATF + warp_m * 64 * KSTR;
        const float* Abl = base + 1*MATF + warp_m * 64 * KSTR;
        const float* Bbh = base + 2*MATF + warp_n * 32 * KSTR;
        const float* Bbl = base + 3*MATF + warp_n * 32 * KSTR;

        #pragma unroll
        for (int step = 0; step < 2; step++) {
            int k8 = step * 8;
            uint32_t ah[4][4], al[4][4], bh[4][2], bl[4][2];
            #pragma unroll
            for (int mt = 0; mt < 4; mt++) {
                int rA = (mt * 16 + g) * KSTR + k8 + t4;
                int rB = rA + 8 * KSTR;
                ah[mt][0] = __float_as_uint(Abh[rA]);
                ah[mt][1] = __float_as_uint(Abh[rB]);
                ah[mt][2] = __float_as_uint(Abh[rA + 4]);
                ah[mt][3] = __float_as_uint(Abh[rB + 4]);
                al[mt][0] = __float_as_uint(Abl[rA]);
                al[mt][1] = __float_as_uint(Abl[rB]);
                al[mt][2] = __float_as_uint(Abl[rA + 4]);
                al[mt][3] = __float_as_uint(Abl[rB + 4]);
            }
            #pragma unroll
            for (int nt = 0; nt < 4; nt++) {
                int rN = (nt * 8 + g) * KSTR + k8 + t4;
                bh[nt][0] = __float_as_uint(Bbh[rN]);
                bh[nt][1] = __float_as_uint(Bbh[rN + 4]);
                bl[nt][0] = __float_as_uint(Bbl[rN]);
                bl[nt][1] = __float_as_uint(Bbl[rN + 4]);
            }
            #pragma unroll
            for (int mt = 0; mt < 4; mt++)
                #pragma unroll
                for (int nt = 0; nt < 4; nt++)
                    mma_tf32(acc[mt][nt], ah[mt], bh[nt]);
            #pragma unroll
            for (int mt = 0; mt < 4; mt++)
                #pragma unroll
                for (int nt = 0; nt < 4; nt++)
                    mma_tf32(acc[mt][nt], ah[mt], bl[nt]);
            #pragma unroll
            for (int mt = 0; mt < 4; mt++)
                #pragma unroll
                for (int nt = 0; nt < 4; nt++)
                    mma_tf32(acc[mt][nt], al[mt], bh[nt]);
        }

        if (more) {
            float* nb = sm + ((ks + 1) & 1) * STAGEF;
            __syncthreads();
            *(float4*)(nb + 0*MATF + so0) = vah0;
            *(float4*)(nb + 0*MATF + so1) = vah1;
            *(float4*)(nb + 1*MATF + so0) = val0;
            *(float4*)(nb + 1*MATF + so1) = val1;
            *(float4*)(nb + 2*MATF + so0) = vbh0;
            *(float4*)(nb + 2*MATF + so1) = vbh1;
            *(float4*)(nb + 3*MATF + so0) = vbl0;
            *(float4*)(nb + 3*MATF + so1) = vbl1;
            __syncthreads();
        }
    }

    // epilogue
    #pragma unroll
    for (int mt = 0; mt < 4; mt++) {
        int r0r = row0 + warp_m * 64 + mt * 16 + g;
        int r1r = r0r + 8;
        #pragma unroll
        for (int nt = 0; nt < 4; nt++) {
            int c = col0 + warp_n * 32 + nt * 8 + 2 * t4;
            float b0 = __ldg(bias + c), b1 = __ldg(bias + c + 1);
            float2 v0 = make_float2((acc[mt][nt][0] + b0) * scale,
                                    (acc[mt][nt][1] + b1) * scale);
            float2 v1 = make_float2((acc[mt][nt][2] + b0) * scale,
                                    (acc[mt][nt][3] + b1) * scale);
            if (scatter) {
                int h_ = c >> 6, d_ = c & 63;
                int b0_ = r0r >> 9, l0_ = r0r & 511;
                int b1_ = r1r >> 9, l1_ = r1r & 511;
                *(float2*)(C + (((size_t)(b0_ * Hh + h_) * Ll) + l0_) * 64 + d_) = v0;
                *(float2*)(C + (((size_t)(b1_ * Hh + h_) * Ll) + l1_) * 64 + d_) = v1;
            } else {
                *(float2*)(C + (size_t)r0r * 1024 + c) = v0;
                *(float2*)(C + (size_t)r1r * 1024 + c) = v1;
            }
        }
    }
}

// ---------------- block reduction helper ----------------
__device__ __forceinline__ float blkred(float v, bool ismax, float* sred) {
    #pragma unroll
    for (int o = 16; o; o >>= 1) {
        float w = __shfl_xor_sync(0xffffffffu, v, o);
        v = ismax ? fmaxf(v, w) : v + w;
    }
    int wid = threadIdx.x >> 5, lid = threadIdx.x & 31;
    int nw = blockDim.x >> 5;
    if (lid == 0) sred[wid] = v;
    __syncthreads();
    if (wid == 0) {
        v = (lid < nw) ? sred[lid] : (ismax ? -3.402823e38f : 0.f);
        #pragma unroll
        for (int o = 16; o; o >>= 1) {
            float w = __shfl_xor_sync(0xffffffffu, v, o);
            v = ismax ? fmaxf(v, w) : v + w;
        }
        if (lid == 0) sred[0] = v;
    }
    __syncthreads();
    float r = sred[0];
    __syncthreads();
    return r;
}

// ---------------- fast branchless lgamma ----------------
__device__ __forceinline__ float lgamma_fast(float x) {
    bool refl = (x < 0.5f);
    float z = refl ? 1.0f - x : x;
    float p = 1.0f;
    #pragma unroll
    for (int i = 0; i < 8; i++) {
        if (z < 8.0f) { p *= z; z += 1.0f; }
    }
    float invz  = 1.0f / z;
    float invz2 = invz * invz;
    float lz = __logf(z);
    float lg = (z - 0.5f) * lz - z + 0.91893853320467274f
             + invz * (8.3333333333e-2f
             + invz2 * (-2.7777777778e-3f + 7.9365079365e-4f * invz2));
    lg -= __logf(p);
    if (refl) {
        float s = sinpif(x);
        lg = 1.1447298858494002f - __logf(fabsf(s)) - lg;
    }
    return lg;
}

// ---------------- prior MLP GEMM (SIMT): [65536,64] x Wp1[64,1024], fused leaky + Wp2 ----------------
__global__ __launch_bounds__(256, 2) void prior_gemm(const float* __restrict__ Wp1,
                                                     const float* __restrict__ bp1,
                                                     const float* __restrict__ Wp2)
{
    __shared__ float As[2][8][128];
    __shared__ float Bs[2][8][128];
    int tid = threadIdx.x;
    int row0 = blockIdx.y * 128;
    int col0 = blockIdx.x * 128;
    int tx = tid & 15, ty = tid >> 4;

    float acc[8][8];
    #pragma unroll
    for (int i = 0; i < 8; i++)
        #pragma unroll
        for (int j = 0; j < 8; j++) acc[i][j] = 0.f;

    int arow = tid >> 1, acol = (tid & 1) * 4;
    int brow = tid >> 5, bcol = (tid & 31) * 4;
    const float* Aptr = g_k + (size_t)(row0 + arow) * 64 + acol;
    const float* Bptr = Wp1 + (size_t)brow * 1024 + col0 + bcol;

    {
        float4 av = *(const float4*)(Aptr);
        As[0][acol + 0][arow] = av.x;
        As[0][acol + 1][arow] = av.y;
        As[0][acol + 2][arow] = av.z;
        As[0][acol + 3][arow] = av.w;
        *(float4*)&Bs[0][brow][bcol] = *(const float4*)(Bptr);
    }
    __syncthreads();

    for (int kb = 0; kb < 8; kb++) {
        int cur = kb & 1;
        float4 av2, bv2;
        bool more = (kb + 1 < 8);
        if (more) {
            av2 = *(const float4*)(Aptr + (kb + 1) * 8);
            bv2 = *(const float4*)(Bptr + (size_t)(kb + 1) * 8 * 1024);
        }
        #pragma unroll
        for (int kk = 0; kk < 8; kk++) {
            float a[8], b[8];
            *(float4*)(a)     = *(const float4*)&As[cur][kk][ty * 4];
            *(float4*)(a + 4) = *(const float4*)&As[cur][kk][64 + ty * 4];
            *(float4*)(b)     = *(const float4*)&Bs[cur][kk][tx * 4];
            *(float4*)(b + 4) = *(const float4*)&Bs[cur][kk][64 + tx * 4];
            #pragma unroll
            for (int i = 0; i < 8; i++)
                #pragma unroll
                for (int j = 0; j < 8; j++)
                    acc[i][j] = fmaf(a[i], b[j], acc[i][j]);
        }
        if (more) {
            int nxt = cur ^ 1;
            As[nxt][acol + 0][arow] = av2.x;
            As[nxt][acol + 1][arow] = av2.y;
            As[nxt][acol + 2][arow] = av2.z;
            As[nxt][acol + 3][arow] = av2.w;
            *(float4*)&Bs[nxt][brow][bcol] = bv2;
            __syncthreads();
        }
    }

    #pragma unroll
    for (int i = 0; i < 8; i++) {
        int rl = (i < 4) ? ty * 4 + i : 64 + ty * 4 + i - 4;
        float s = 0.f;
        #pragma unroll
        for (int j = 0; j < 8; j++) {
            int c = col0 + ((j < 4) ? tx * 4 + j : 64 + tx * 4 + j - 4);
            float hv = acc[i][j] + bp1[c];
            hv = (hv >= 0.f) ? hv : 0.01f * hv;
            s = fmaf(hv, Wp2[c], s);
        }
        #pragma unroll
        for (int o = 8; o; o >>= 1) s += __shfl_xor_sync(0xffffffffu, s, o);
        if (tx == 0) g_pp[(size_t)blockIdx.x * NPOS + row0 + rl] = s;
    }
}

__global__ void combine_dotg(const float* __restrict__ bp2) {
    int i = blockIdx.x * 256 + threadIdx.x;
    float s = 0.f;
    #pragma unroll
    for (int t = 0; t < 8; t++) s += g_pp[(size_t)t * NPOS + i];
    g_dotg[i] = s + bp2[0];
}

// ---------------- alpha softmax + per-(b,h) KL constant terms ----------------
__global__ __launch_bounds__(512) void alpha_kernel() {
    __shared__ float sred[32];
    int bh = blockIdx.x;
    int t = threadIdx.x;
    float x = g_dotg[bh * Ll + t];
    float m = blkred(x, true, sred);
    float e = expf(x - m);
    float den = blkred(e, false, sred);
    float a = e / den;
    g_alpha[bh * Ll + t] = a;
    const float lg1 = 0.69314718f;
    const float EG  = 0.5772156649f;
    float C = a * lg1 + 2.f * EG * a + lgammaf(a + EPSF);
    float sc = blkred(C, false, sred);
    if (t == 0) atomicAdd(&g_kl, (double)(512.0f * sc));
}

// ---------------- batched QK^T (NT), double-buffered; q pre-scaled by 8 ----------------
__global__ __launch_bounds__(256, 2) void score_nt() {
    int bh = blockIdx.z;
    const float* A  = g_q + (size_t)bh * Ll * DKk;
    const float* Bp = g_k + (size_t)bh * Ll * DKk;
    float* Sp = g_S + (size_t)bh * Ll * Ll;
    __shared__ float As[2][8][128];
    __shared__ float Bs[2][8][128];
    int tid = threadIdx.x;
    int row0 = blockIdx.y * 128, col0 = blockIdx.x * 128;
    int tx = tid & 15, ty = tid >> 4;
    float acc[8][8];
    #pragma unroll
    for (int i = 0; i < 8; i++)
        #pragma unroll
        for (int j = 0; j < 8; j++) acc[i][j] = 0.f;
    int arow = tid >> 1, acol = (tid & 1) * 4;
    const float* Aptr = A  + (size_t)(row0 + arow) * DKk + acol;
    const float* Bptr = Bp + (size_t)(col0 + arow) * DKk + acol;

    {
        float4 av = *(const float4*)(Aptr);
        As[0][acol + 0][arow] = av.x;
        As[0][acol + 1][arow] = av.y;
        As[0][acol + 2][arow] = av.z;
        As[0][acol + 3][arow] = av.w;
        float4 bv = *(const float4*)(Bptr);
        Bs[0][acol + 0][arow] = bv.x;
        Bs[0][acol + 1][arow] = bv.y;
        Bs[0][acol + 2][arow] = bv.z;
        Bs[0][acol + 3][arow] = bv.w;
    }
    __syncthreads();

    for (int kb = 0; kb < 8; kb++) {
        int cur = kb & 1;
        float4 av2, bv2;
        bool more = (kb + 1 < 8);
        if (more) {
            av2 = *(const float4*)(Aptr + (kb + 1) * 8);
            bv2 = *(const float4*)(Bptr + (kb + 1) * 8);
        }
        #pragma unroll
        for (int kk = 0; kk < 8; kk++) {
            float a[8], b[8];
            *(float4*)(a)     = *(const float4*)&As[cur][kk][ty * 4];
            *(float4*)(a + 4) = *(const float4*)&As[cur][kk][64 + ty * 4];
            *(float4*)(b)     = *(const float4*)&Bs[cur][kk][tx * 4];
            *(float4*)(b + 4) = *(const float4*)&Bs[cur][kk][64 + tx * 4];
            #pragma unroll
            for (int i = 0; i < 8; i++)
                #pragma unroll
                for (int j = 0; j < 8; j++)
                    acc[i][j] = fmaf(a[i], b[j], acc[i][j]);
        }
        if (more) {
            int nxt = cur ^ 1;
            As[nxt][acol + 0][arow] = av2.x;
            As[nxt][acol + 1][arow] = av2.y;
            As[nxt][acol + 2][arow] = av2.z;
            As[nxt][acol + 3][arow] = av2.w;
            Bs[nxt][acol + 0][arow] = bv2.x;
            Bs[nxt][acol + 1][arow] = bv2.y;
            Bs[nxt][acol + 2][arow] = bv2.z;
            Bs[nxt][acol + 3][arow] = bv2.w;
            __syncthreads();
        }
    }
    #pragma unroll
    for (int i = 0; i < 8; i++) {
        int r = row0 + ((i < 4) ? ty * 4 + i : 64 + ty * 4 + i - 4);
        #pragma unroll
        for (int j = 0; j < 8; j++) {
            int c = col0 + ((j < 4) ? tx * 4 + j : 64 + tx * 4 + j - 4);
            Sp[(size_t)r * Ll + c] = acc[i][j];
        }
    }
}

// ---------------- fused row pass ----------------
__global__ __launch_bounds__(256) void row_fused(const float* __restrict__ U) {
    __shared__ float sred[32];
    int row = blockIdx.x;
    int bh = row >> 9;
    size_t base = (size_t)row * 512;
    int t = threadIdx.x;

    float s0 = g_S[base + t], s1 = g_S[base + 256 + t];
    float m = blkred(fmaxf(s0, s1), true, sred);
    float e0 = __expf(s0 - m), e1 = __expf(s1 - m);
    float den = blkred(e0 + e1, false, sred);
    float inv = 1.f / den;
    float logden = __logf(den);
    float p0 = e0 * inv, p1 = e1 * inv;
    float r0 = s0 - m - logden, r1 = s1 - m - logden;
    float lp0 = (r0 >= -36.f) ? r0 : __logf(p0 + EPSF);
    float lp1 = (r1 >= -36.f) ? r1 : __logf(p1 + EPSF);

    float u0 = U[base + t], u1 = U[base + 256 + t];
    float w0 = -logf(1.f - u0 + EPSF);
    float w1 = -logf(1.f - u1 + EPSF);
    float gw0 = __logf(w0 + EPSF);
    float gw1 = __logf(w1 + EPSF);
    float t0 = lp0 - lgamma_fast(3.f + 2.f * gw0);
    float t1 = lp1 - lgamma_fast(3.f + 2.f * gw1);

    float m2 = blkred(fmaxf(t0, t1), true, sred);
    float q0 = __expf(t0 - m2), q1 = __expf(t1 - m2);
    float d2 = blkred(q0 + q1, false, sred);
    float i2 = 1.f / d2;
    g_S[base + t] = q0 * i2;
    g_S[base + 256 + t] = q1 * i2;

    float a0 = g_alpha[bh * 512 + t], a1 = g_alpha[bh * 512 + 256 + t];
    float kl = fmaf(-a0, lp0, p0) + fmaf(-a1, lp1, p1);
    float ks = blkred(kl, false, sred);
    if (t == 0) atomicAdd(&g_kl, (double)ks);
}

// ---------------- batched att_s @ V (128x64 tiles, double-buffered) ----------------
__global__ __launch_bounds__(256, 2) void pv_gemm() {
    int bh = blockIdx.y;
    int b_ = bh >> 4, h_ = bh & 15;
    const float* A  = g_S + (size_t)bh * Ll * Ll;
    const float* Bv = g_v + (size_t)bh * Ll * DVv;
    __shared__ float As[2][16][128];
    __shared__ float Bs[2][16][64];
    int tid = threadIdx.x;
    int tx = tid & 15, ty = tid >> 4;
    int row0 = blockIdx.x * 128;
    float acc[8][4];
    #pragma unroll
    for (int i = 0; i < 8; i++)
        #pragma unroll
        for (int j = 0; j < 4; j++) acc[i][j] = 0.f;

    int arow = tid >> 1, acol = (tid & 1) * 8;
    int brow = tid >> 4, bcol = (tid & 15) * 4;
    const float* Aptr = A + (size_t)(row0 + arow) * Ll + acol;
    const float* Bptr = Bv + (size_t)brow * DVv + bcol;

    {
        float4 a0 = *(const float4*)(Aptr);
        float4 a1 = *(const float4*)(Aptr + 4);
        As[0][acol + 0][arow] = a0.x;
        As[0][acol + 1][arow] = a0.y;
        As[0][acol + 2][arow] = a0.z;
        As[0][acol + 3][arow] = a0.w;
        As[0][acol + 4][arow] = a1.x;
        As[0][acol + 5][arow] = a1.y;
        As[0][acol + 6][arow] = a1.z;
        As[0][acol + 7][arow] = a1.w;
        *(float4*)&Bs[0][brow][bcol] = *(const float4*)(Bptr);
    }
    __syncthreads();

    for (int kb = 0; kb < 32; kb++) {
        int cur = kb & 1;
        float4 a0n, a1n, bvn;
        bool more = (kb + 1 < 32);
        if (more) {
            a0n = *(const float4*)(Aptr + (kb + 1) * 16);
            a1n = *(const float4*)(Aptr + (kb + 1) * 16 + 4);
            bvn = *(const float4*)(Bptr + (size_t)(kb + 1) * 16 * DVv);
        }
        #pragma unroll
        for (int kk = 0; kk < 16; kk++) {
            float a[8], b[4];
            *(float4*)(a)     = *(const float4*)&As[cur][kk][ty * 4];
            *(float4*)(a + 4) = *(const float4*)&As[cur][kk][64 + ty * 4];
            *(float4*)(b)     = *(const float4*)&Bs[cur][kk][tx * 4];
            #pragma unroll
            for (int i = 0; i < 8; i++)
                #pragma unroll
                for (int j = 0; j < 4; j++)
                    acc[i][j] = fmaf(a[i], b[j], acc[i][j]);
        }
        if (more) {
            int nxt = cur ^ 1;
            As[nxt][acol + 0][arow] = a0n.x;
            As[nxt][acol + 1][arow] = a0n.y;
            As[nxt][acol + 2][arow] = a0n.z;
            As[nxt][acol + 3][arow] = a0n.w;
            As[nxt][acol + 4][arow] = a1n.x;
            As[nxt][acol + 5][arow] = a1n.y;
            As[nxt][acol + 6][arow] = a1n.z;
            As[nxt][acol + 7][arow] = a1n.w;
            *(float4*)&Bs[nxt][brow][bcol] = bvn;
            __syncthreads();
        }
    }

    #pragma unroll
    for (int i = 0; i < 8; i++) {
        int r = row0 + ((i < 4) ? ty * 4 + i : 64 + ty * 4 + i - 4);
        #pragma unroll
        for (int j = 0; j < 4; j++) {
            int c = tx * 4 + j;
            g_ao[((size_t)b_ * Ll + r) * Dd + h_ * DVv + c] = acc[i][j];
        }
    }
}

// ---------------- misc ----------------
__global__ void zero_kernel() { g_kl = 0.0; }

__global__ void finalize_kernel(float* out, int out_size) {
    if (out_size > Bb * Ll * Dd)
        out[Bb * Ll * Dd] = (float)(g_kl / 33554432.0);
}

// ---------------- launch ----------------
extern "C" void kernel_launch(void* const* d_in, const int* in_sizes, int n_in,
                              void* d_out, int out_size) {
    const float* queries = (const float*)d_in[0];
    const float* keys    = (const float*)d_in[1];
    const float* values  = (const float*)d_in[2];
    const float* unif    = (const float*)d_in[3];
    const float* Wq = (const float*)d_in[4];
    const float* bq = (const float*)d_in[5];
    const float* Wk = (const float*)d_in[6];
    const float* bk = (const float*)d_in[7];
    const float* Wv = (const float*)d_in[8];
    const float* bv = (const float*)d_in[9];
    const float* Wo = (const float*)d_in[10];
    const float* bo = (const float*)d_in[11];
    const float* Wp1 = (const float*)d_in[12];
    const float* bp1 = (const float*)d_in[13];
    const float* Wp2 = (const float*)d_in[14];
    const float* bp2 = (const float*)d_in[15];
    float* out = (float*)d_out;

    float *pq, *pk, *pv_, *pao, *pah, *pal, *pwh, *pwl;
    cudaGetSymbolAddress((void**)&pq, g_q);
    cudaGetSymbolAddress((void**)&pk, g_k);
    cudaGetSymbolAddress((void**)&pv_, g_v);
    cudaGetSymbolAddress((void**)&pao, g_ao);
    cudaGetSymbolAddress((void**)&pah, g_ah);
    cudaGetSymbolAddress((void**)&pal, g_al);
    cudaGetSymbolAddress((void**)&pwh, g_wh);
    cudaGetSymbolAddress((void**)&pwl, g_wl);

    const int GSMEM = 2 * STAGEF * 4;   // 81920 bytes
    static int smem_set = 0;
    if (!smem_set) {
        cudaFuncSetAttribute(mma_gemm, cudaFuncAttributeMaxDynamicSharedMemorySize, GSMEM);
        smem_set = 1;
    }

    zero_kernel<<<1, 1>>>();

    dim3 gmm(8, 32);
    dim3 tr(32, 8);
    const int nblk_act = (MROWS * Dd) / (256 * 4);

    // Q projection (scale 8 = sqrt(DK))
    split_act<<<nblk_act, 256>>>(queries, pah, pal);
    split_w_t<<<dim3(32, 32), tr>>>(Wq, pwh, pwl);
    mma_gemm<<<gmm, 256, GSMEM>>>(pah, pal, pwh, pwl, bq, pq, 1, 8.0f);

    // K projection
    split_act<<<nblk_act, 256>>>(keys, pah, pal);
    split_w_t<<<dim3(32, 32), tr>>>(Wk, pwh, pwl);
    mma_gemm<<<gmm, 256, GSMEM>>>(pah, pal, pwh, pwl, bk, pk, 1, 1.0f);

    // V projection
    split_act<<<nblk_act, 256>>>(values, pah, pal);
    split_w_t<<<dim3(32, 32), tr>>>(Wv, pwh, pwl);
    mma_gemm<<<gmm, 256, GSMEM>>>(pah, pal, pwh, pwl, bv, pv_, 1, 1.0f);

    prior_gemm<<<dim3(8, 512), 256>>>(Wp1, bp1, Wp2);
    combine_dotg<<<256, 256>>>(bp2);
    alpha_kernel<<<BH, 512>>>();

    score_nt<<<dim3(4, 4, BH), 256>>>();
    row_fused<<<NPOS, 256>>>(unif);
    pv_gemm<<<dim3(4, BH), 256>>>();

    // out projection
    split_act<<<nblk_act, 256>>>(pao, pah, pal);
    split_w_t<<<dim3(32, 32), tr>>>(Wo, pwh, pwl);
    mma_gemm<<<gmm, 256, GSMEM>>>(pah, pal, pwh, pwl, bo, out, 0, 1.0f);

    finalize_kernel<<<1, 1>>>(out, out_size);
}

// round 6
// speedup vs baseline: 1.1124x; 1.1124x over previous
#include <cuda_runtime.h>
#include <math.h>
#include <stdint.h>

#define Bb 8
#define Ll 512
#define Dd 1024
#define Hh 16
#define DKk 64
#define DVv 64
#define EPSF 1e-20f

#define BH (Bb*Hh)           // 128
#define NPOS (Bb*Hh*Ll)      // 65536
#define MROWS (Bb*Ll)        // 4096

// ---------------- scratch (static device globals; no allocation) ----------------
__device__ float g_q[NPOS*DKk];          // [B,H,L,DK]  (pre-scaled by 8)
__device__ float g_k[NPOS*DKk];
__device__ float g_v[NPOS*DVv];
__device__ float g_S[(size_t)BH*Ll*Ll];  // scores -> att_s  (134 MB)
__device__ float g_ao[MROWS*Dd];         // attn out reordered [B,L,H*DV]
__device__ float g_pp[8*NPOS];           // prior partials
__device__ float g_dotg[NPOS];
__device__ float g_alpha[NPOS];
__device__ double g_kl;
__device__ float g_wt[Dd*Dd];            // weight^T fp32 [N,K] (reused per projection)

// ---------------- helpers ----------------
__device__ __forceinline__ float tf32_rn(float a) {
    uint32_t r;
    asm("cvt.rna.tf32.f32 %0, %1;" : "=r"(r) : "f"(a));
    return __uint_as_float(r);
}

__device__ __forceinline__ void mma_tf32(float* c, const uint32_t* a, const uint32_t* b) {
    asm volatile(
        "mma.sync.aligned.m16n8k8.row.col.f32.tf32.tf32.f32 "
        "{%0,%1,%2,%3}, {%4,%5,%6,%7}, {%8,%9}, {%0,%1,%2,%3};"
        : "+f"(c[0]), "+f"(c[1]), "+f"(c[2]), "+f"(c[3])
        : "r"(a[0]), "r"(a[1]), "r"(a[2]), "r"(a[3]), "r"(b[0]), "r"(b[1]));
}

// W [K=1024, N=1024] row-major -> W^T fp32 [N, K]
__global__ void w_transpose(const float* __restrict__ W, float* __restrict__ T) {
    __shared__ float t[32][33];
    int bx = blockIdx.x * 32, by = blockIdx.y * 32;
    int tx = threadIdx.x, ty = threadIdx.y;     // 32 x 8
    #pragma unroll
    for (int j = 0; j < 4; j++)
        t[ty + 8 * j][tx] = W[(size_t)(by + ty + 8 * j) * 1024 + bx + tx];
    __syncthreads();
    #pragma unroll
    for (int j = 0; j < 4; j++)
        T[(size_t)(bx + ty + 8 * j) * 1024 + by + tx] = t[tx][ty + 8 * j];
}

// ---------------- 3xTF32 mma.sync GEMM, fp32 smem tiles, in-register split ----------------
// A [M,K] row-major fp32; Bt [N,K] row-major fp32 (= W^T).  C = A@W + bias, *scale.
// CTA tile 128x128, kb=16, double-buffered 20KB stages -> 2 CTAs/SM.
#define KB 16
#define KSTR 20
#define MATF 2560            // 128*20 floats per matrix
#define STAGEF 5120          // 2 matrices per stage
__global__ __launch_bounds__(256, 2) void mma_gemm(const float* __restrict__ A,
                                                   const float* __restrict__ Bt,
                                                   const float* __restrict__ bias,
                                                   float* __restrict__ C,
                                                   int scatter, float scale)
{
    extern __shared__ float sm[];      // 2 stages * 2 matrices * 2560 floats = 40KB
    int tid = threadIdx.x;
    int lane = tid & 31, wid = tid >> 5;
    int g = lane >> 2, t4 = lane & 3;
    int warp_m = wid & 1;              // 2 warps over M (64 rows each)
    int warp_n = wid >> 1;             // 4 warps over N (32 cols each)
    int row0 = blockIdx.y * 128;
    int col0 = blockIdx.x * 128;

    float acc[4][4][4];
    #pragma unroll
    for (int mt = 0; mt < 4; mt++)
        #pragma unroll
        for (int nt = 0; nt < 4; nt++)
            #pragma unroll
            for (int q = 0; q < 4; q++) acc[mt][nt][q] = 0.f;

    // global loads: 512 float4 per matrix-stage, 256 threads -> 2 each
    int r0i = tid >> 2, s0i = tid & 3;
    const float* pA0 = A  + (size_t)(row0 + r0i) * 1024 + s0i * 4;
    const float* pA1 = A  + (size_t)(row0 + 64 + r0i) * 1024 + s0i * 4;
    const float* pB0 = Bt + (size_t)(col0 + r0i) * 1024 + s0i * 4;
    const float* pB1 = Bt + (size_t)(col0 + 64 + r0i) * 1024 + s0i * 4;
    int so0 = r0i * KSTR + s0i * 4;
    int so1 = (r0i + 64) * KSTR + s0i * 4;

    // preload stage 0
    *(float4*)(sm + so0)        = *(const float4*)(pA0);
    *(float4*)(sm + so1)        = *(const float4*)(pA1);
    *(float4*)(sm + MATF + so0) = *(const float4*)(pB0);
    *(float4*)(sm + MATF + so1) = *(const float4*)(pB1);
    __syncthreads();

    const int NSTAGE = 1024 / KB;      // 64
    for (int ks = 0; ks < NSTAGE; ks++) {
        int buf = ks & 1;
        float4 va0, va1, vb0, vb1;
        bool more = (ks + 1 < NSTAGE);
        if (more) {
            int k0 = (ks + 1) * KB;
            va0 = *(const float4*)(pA0 + k0);
            va1 = *(const float4*)(pA1 + k0);
            vb0 = *(const float4*)(pB0 + k0);
            vb1 = *(const float4*)(pB1 + k0);
        }

        const float* Asmp = sm + buf * STAGEF + warp_m * 64 * KSTR;
        const float* Bsmp = sm + buf * STAGEF + MATF + warp_n * 32 * KSTR;

        #pragma unroll
        for (int step = 0; step < 2; step++) {
            int k8 = step * 8;
            uint32_t bhf[4][2], blf[4][2];
            #pragma unroll
            for (int nt = 0; nt < 4; nt++) {
                int rN = (nt * 8 + g) * KSTR + k8 + t4;
                float b0 = Bsmp[rN], b1 = Bsmp[rN + 4];
                float h0 = tf32_rn(b0), h1 = tf32_rn(b1);
                bhf[nt][0] = __float_as_uint(h0);
                bhf[nt][1] = __float_as_uint(h1);
                blf[nt][0] = __float_as_uint(tf32_rn(b0 - h0));
                blf[nt][1] = __float_as_uint(tf32_rn(b1 - h1));
            }
            #pragma unroll
            for (int mt = 0; mt < 4; mt++) {
                int rA = (mt * 16 + g) * KSTR + k8 + t4;
                int rB = rA + 8 * KSTR;
                float a0 = Asmp[rA], a1 = Asmp[rB], a2 = Asmp[rA + 4], a3 = Asmp[rB + 4];
                float h0 = tf32_rn(a0), h1 = tf32_rn(a1), h2 = tf32_rn(a2), h3 = tf32_rn(a3);
                uint32_t ah[4] = { __float_as_uint(h0), __float_as_uint(h1),
                                   __float_as_uint(h2), __float_as_uint(h3) };
                uint32_t al[4] = { __float_as_uint(tf32_rn(a0 - h0)),
                                   __float_as_uint(tf32_rn(a1 - h1)),
                                   __float_as_uint(tf32_rn(a2 - h2)),
                                   __float_as_uint(tf32_rn(a3 - h3)) };
                #pragma unroll
                for (int nt = 0; nt < 4; nt++) mma_tf32(acc[mt][nt], ah, bhf[nt]);
                #pragma unroll
                for (int nt = 0; nt < 4; nt++) mma_tf32(acc[mt][nt], ah, blf[nt]);
                #pragma unroll
                for (int nt = 0; nt < 4; nt++) mma_tf32(acc[mt][nt], al, bhf[nt]);
            }
        }

        if (more) {
            float* nb = sm + ((ks + 1) & 1) * STAGEF;
            __syncthreads();
            *(float4*)(nb + so0)        = va0;
            *(float4*)(nb + so1)        = va1;
            *(float4*)(nb + MATF + so0) = vb0;
            *(float4*)(nb + MATF + so1) = vb1;
            __syncthreads();
        }
    }

    // epilogue
    #pragma unroll
    for (int mt = 0; mt < 4; mt++) {
        int r0r = row0 + warp_m * 64 + mt * 16 + g;
        int r1r = r0r + 8;
        #pragma unroll
        for (int nt = 0; nt < 4; nt++) {
            int c = col0 + warp_n * 32 + nt * 8 + 2 * t4;
            float b0 = __ldg(bias + c), b1 = __ldg(bias + c + 1);
            float2 v0 = make_float2((acc[mt][nt][0] + b0) * scale,
                                    (acc[mt][nt][1] + b1) * scale);
            float2 v1 = make_float2((acc[mt][nt][2] + b0) * scale,
                                    (acc[mt][nt][3] + b1) * scale);
            if (scatter) {
                int h_ = c >> 6, d_ = c & 63;
                int b0_ = r0r >> 9, l0_ = r0r & 511;
                int b1_ = r1r >> 9, l1_ = r1r & 511;
                *(float2*)(C + (((size_t)(b0_ * Hh + h_) * Ll) + l0_) * 64 + d_) = v0;
                *(float2*)(C + (((size_t)(b1_ * Hh + h_) * Ll) + l1_) * 64 + d_) = v1;
            } else {
                *(float2*)(C + (size_t)r0r * 1024 + c) = v0;
                *(float2*)(C + (size_t)r1r * 1024 + c) = v1;
            }
        }
    }
}

// ---------------- block reduction helper ----------------
__device__ __forceinline__ float blkred(float v, bool ismax, float* sred) {
    #pragma unroll
    for (int o = 16; o; o >>= 1) {
        float w = __shfl_xor_sync(0xffffffffu, v, o);
        v = ismax ? fmaxf(v, w) : v + w;
    }
    int wid = threadIdx.x >> 5, lid = threadIdx.x & 31;
    int nw = blockDim.x >> 5;
    if (lid == 0) sred[wid] = v;
    __syncthreads();
    if (wid == 0) {
        v = (lid < nw) ? sred[lid] : (ismax ? -3.402823e38f : 0.f);
        #pragma unroll
        for (int o = 16; o; o >>= 1) {
            float w = __shfl_xor_sync(0xffffffffu, v, o);
            v = ismax ? fmaxf(v, w) : v + w;
        }
        if (lid == 0) sred[0] = v;
    }
    __syncthreads();
    float r = sred[0];
    __syncthreads();
    return r;
}

// ---------------- fast branchless lgamma ----------------
__device__ __forceinline__ float lgamma_fast(float x) {
    bool refl = (x < 0.5f);
    float z = refl ? 1.0f - x : x;
    float p = 1.0f;
    #pragma unroll
    for (int i = 0; i < 8; i++) {
        if (z < 8.0f) { p *= z; z += 1.0f; }
    }
    float invz  = 1.0f / z;
    float invz2 = invz * invz;
    float lz = __logf(z);
    float lg = (z - 0.5f) * lz - z + 0.91893853320467274f
             + invz * (8.3333333333e-2f
             + invz2 * (-2.7777777778e-3f + 7.9365079365e-4f * invz2));
    lg -= __logf(p);
    if (refl) {
        float s = sinpif(x);
        lg = 1.1447298858494002f - __logf(fabsf(s)) - lg;
    }
    return lg;
}

// ---------------- prior MLP GEMM (SIMT): [65536,64] x Wp1[64,1024], fused leaky + Wp2 ----------------
__global__ __launch_bounds__(256, 2) void prior_gemm(const float* __restrict__ Wp1,
                                                     const float* __restrict__ bp1,
                                                     const float* __restrict__ Wp2)
{
    __shared__ float As[2][8][128];
    __shared__ float Bs[2][8][128];
    int tid = threadIdx.x;
    int row0 = blockIdx.y * 128;
    int col0 = blockIdx.x * 128;
    int tx = tid & 15, ty = tid >> 4;

    float acc[8][8];
    #pragma unroll
    for (int i = 0; i < 8; i++)
        #pragma unroll
        for (int j = 0; j < 8; j++) acc[i][j] = 0.f;

    int arow = tid >> 1, acol = (tid & 1) * 4;
    int brow = tid >> 5, bcol = (tid & 31) * 4;
    const float* Aptr = g_k + (size_t)(row0 + arow) * 64 + acol;
    const float* Bptr = Wp1 + (size_t)brow * 1024 + col0 + bcol;

    {
        float4 av = *(const float4*)(Aptr);
        As[0][acol + 0][arow] = av.x;
        As[0][acol + 1][arow] = av.y;
        As[0][acol + 2][arow] = av.z;
        As[0][acol + 3][arow] = av.w;
        *(float4*)&Bs[0][brow][bcol] = *(const float4*)(Bptr);
    }
    __syncthreads();

    for (int kb = 0; kb < 8; kb++) {
        int cur = kb & 1;
        float4 av2, bv2;
        bool more = (kb + 1 < 8);
        if (more) {
            av2 = *(const float4*)(Aptr + (kb + 1) * 8);
            bv2 = *(const float4*)(Bptr + (size_t)(kb + 1) * 8 * 1024);
        }
        #pragma unroll
        for (int kk = 0; kk < 8; kk++) {
            float a[8], b[8];
            *(float4*)(a)     = *(const float4*)&As[cur][kk][ty * 4];
            *(float4*)(a + 4) = *(const float4*)&As[cur][kk][64 + ty * 4];
            *(float4*)(b)     = *(const float4*)&Bs[cur][kk][tx * 4];
            *(float4*)(b + 4) = *(const float4*)&Bs[cur][kk][64 + tx * 4];
            #pragma unroll
            for (int i = 0; i < 8; i++)
                #pragma unroll
                for (int j = 0; j < 8; j++)
                    acc[i][j] = fmaf(a[i], b[j], acc[i][j]);
        }
        if (more) {
            int nxt = cur ^ 1;
            As[nxt][acol + 0][arow] = av2.x;
            As[nxt][acol + 1][arow] = av2.y;
            As[nxt][acol + 2][arow] = av2.z;
            As[nxt][acol + 3][arow] = av2.w;
            *(float4*)&Bs[nxt][brow][bcol] = bv2;
            __syncthreads();
        }
    }

    #pragma unroll
    for (int i = 0; i < 8; i++) {
        int rl = (i < 4) ? ty * 4 + i : 64 + ty * 4 + i - 4;
        float s = 0.f;
        #pragma unroll
        for (int j = 0; j < 8; j++) {
            int c = col0 + ((j < 4) ? tx * 4 + j : 64 + tx * 4 + j - 4);
            float hv = acc[i][j] + bp1[c];
            hv = (hv >= 0.f) ? hv : 0.01f * hv;
            s = fmaf(hv, Wp2[c], s);
        }
        #pragma unroll
        for (int o = 8; o; o >>= 1) s += __shfl_xor_sync(0xffffffffu, s, o);
        if (tx == 0) g_pp[(size_t)blockIdx.x * NPOS + row0 + rl] = s;
    }
}

__global__ void combine_dotg(const float* __restrict__ bp2) {
    int i = blockIdx.x * 256 + threadIdx.x;
    float s = 0.f;
    #pragma unroll
    for (int t = 0; t < 8; t++) s += g_pp[(size_t)t * NPOS + i];
    g_dotg[i] = s + bp2[0];
}

// ---------------- alpha softmax + per-(b,h) KL constant terms ----------------
__global__ __launch_bounds__(512) void alpha_kernel() {
    __shared__ float sred[32];
    int bh = blockIdx.x;
    int t = threadIdx.x;
    float x = g_dotg[bh * Ll + t];
    float m = blkred(x, true, sred);
    float e = expf(x - m);
    float den = blkred(e, false, sred);
    float a = e / den;
    g_alpha[bh * Ll + t] = a;
    const float lg1 = 0.69314718f;
    const float EG  = 0.5772156649f;
    float C = a * lg1 + 2.f * EG * a + lgammaf(a + EPSF);
    float sc = blkred(C, false, sred);
    if (t == 0) atomicAdd(&g_kl, (double)(512.0f * sc));
}

// ---------------- batched QK^T (NT), double-buffered; q pre-scaled by 8 ----------------
__global__ __launch_bounds__(256, 2) void score_nt() {
    int bh = blockIdx.z;
    const float* A  = g_q + (size_t)bh * Ll * DKk;
    const float* Bp = g_k + (size_t)bh * Ll * DKk;
    float* Sp = g_S + (size_t)bh * Ll * Ll;
    __shared__ float As[2][8][128];
    __shared__ float Bs[2][8][128];
    int tid = threadIdx.x;
    int row0 = blockIdx.y * 128, col0 = blockIdx.x * 128;
    int tx = tid & 15, ty = tid >> 4;
    float acc[8][8];
    #pragma unroll
    for (int i = 0; i < 8; i++)
        #pragma unroll
        for (int j = 0; j < 8; j++) acc[i][j] = 0.f;
    int arow = tid >> 1, acol = (tid & 1) * 4;
    const float* Aptr = A  + (size_t)(row0 + arow) * DKk + acol;
    const float* Bptr = Bp + (size_t)(col0 + arow) * DKk + acol;

    {
        float4 av = *(const float4*)(Aptr);
        As[0][acol + 0][arow] = av.x;
        As[0][acol + 1][arow] = av.y;
        As[0][acol + 2][arow] = av.z;
        As[0][acol + 3][arow] = av.w;
        float4 bv = *(const float4*)(Bptr);
        Bs[0][acol + 0][arow] = bv.x;
        Bs[0][acol + 1][arow] = bv.y;
        Bs[0][acol + 2][arow] = bv.z;
        Bs[0][acol + 3][arow] = bv.w;
    }
    __syncthreads();

    for (int kb = 0; kb < 8; kb++) {
        int cur = kb & 1;
        float4 av2, bv2;
        bool more = (kb + 1 < 8);
        if (more) {
            av2 = *(const float4*)(Aptr + (kb + 1) * 8);
            bv2 = *(const float4*)(Bptr + (kb + 1) * 8);
        }
        #pragma unroll
        for (int kk = 0; kk < 8; kk++) {
            float a[8], b[8];
            *(float4*)(a)     = *(const float4*)&As[cur][kk][ty * 4];
            *(float4*)(a + 4) = *(const float4*)&As[cur][kk][64 + ty * 4];
            *(float4*)(b)     = *(const float4*)&Bs[cur][kk][tx * 4];
            *(float4*)(b + 4) = *(const float4*)&Bs[cur][kk][64 + tx * 4];
            #pragma unroll
            for (int i = 0; i < 8; i++)
                #pragma unroll
                for (int j = 0; j < 8; j++)
                    acc[i][j] = fmaf(a[i], b[j], acc[i][j]);
        }
        if (more) {
            int nxt = cur ^ 1;
            As[nxt][acol + 0][arow] = av2.x;
            As[nxt][acol + 1][arow] = av2.y;
            As[nxt][acol + 2][arow] = av2.z;
            As[nxt][acol + 3][arow] = av2.w;
            Bs[nxt][acol + 0][arow] = bv2.x;
            Bs[nxt][acol + 1][arow] = bv2.y;
            Bs[nxt][acol + 2][arow] = bv2.z;
            Bs[nxt][acol + 3][arow] = bv2.w;
            __syncthreads();
        }
    }
    #pragma unroll
    for (int i = 0; i < 8; i++) {
        int r = row0 + ((i < 4) ? ty * 4 + i : 64 + ty * 4 + i - 4);
        #pragma unroll
        for (int j = 0; j < 8; j++) {
            int c = col0 + ((j < 4) ? tx * 4 + j : 64 + tx * 4 + j - 4);
            Sp[(size_t)r * Ll + c] = acc[i][j];
        }
    }
}

// ---------------- fused row pass ----------------
__global__ __launch_bounds__(256) void row_fused(const float* __restrict__ U) {
    __shared__ float sred[32];
    int row = blockIdx.x;
    int bh = row >> 9;
    size_t base = (size_t)row * 512;
    int t = threadIdx.x;

    float s0 = g_S[base + t], s1 = g_S[base + 256 + t];
    float m = blkred(fmaxf(s0, s1), true, sred);
    float e0 = __expf(s0 - m), e1 = __expf(s1 - m);
    float den = blkred(e0 + e1, false, sred);
    float inv = 1.f / den;
    float logden = __logf(den);
    float p0 = e0 * inv, p1 = e1 * inv;
    float r0 = s0 - m - logden, r1 = s1 - m - logden;
    float lp0 = (r0 >= -36.f) ? r0 : __logf(p0 + EPSF);
    float lp1 = (r1 >= -36.f) ? r1 : __logf(p1 + EPSF);

    float u0 = U[base + t], u1 = U[base + 256 + t];
    float w0 = -logf(1.f - u0 + EPSF);
    float w1 = -logf(1.f - u1 + EPSF);
    float gw0 = __logf(w0 + EPSF);
    float gw1 = __logf(w1 + EPSF);
    float t0 = lp0 - lgamma_fast(3.f + 2.f * gw0);
    float t1 = lp1 - lgamma_fast(3.f + 2.f * gw1);

    float m2 = blkred(fmaxf(t0, t1), true, sred);
    float q0 = __expf(t0 - m2), q1 = __expf(t1 - m2);
    float d2 = blkred(q0 + q1, false, sred);
    float i2 = 1.f / d2;
    g_S[base + t] = q0 * i2;
    g_S[base + 256 + t] = q1 * i2;

    float a0 = g_alpha[bh * 512 + t], a1 = g_alpha[bh * 512 + 256 + t];
    float kl = fmaf(-a0, lp0, p0) + fmaf(-a1, lp1, p1);
    float ks = blkred(kl, false, sred);
    if (t == 0) atomicAdd(&g_kl, (double)ks);
}

// ---------------- batched att_s @ V (128x64 tiles, double-buffered) ----------------
__global__ __launch_bounds__(256, 2) void pv_gemm() {
    int bh = blockIdx.y;
    int b_ = bh >> 4, h_ = bh & 15;
    const float* A  = g_S + (size_t)bh * Ll * Ll;
    const float* Bv = g_v + (size_t)bh * Ll * DVv;
    __shared__ float As[2][16][128];
    __shared__ float Bs[2][16][64];
    int tid = threadIdx.x;
    int tx = tid & 15, ty = tid >> 4;
    int row0 = blockIdx.x * 128;
    float acc[8][4];
    #pragma unroll
    for (int i = 0; i < 8; i++)
        #pragma unroll
        for (int j = 0; j < 4; j++) acc[i][j] = 0.f;

    int arow = tid >> 1, acol = (tid & 1) * 8;
    int brow = tid >> 4, bcol = (tid & 15) * 4;
    const float* Aptr = A + (size_t)(row0 + arow) * Ll + acol;
    const float* Bptr = Bv + (size_t)brow * DVv + bcol;

    {
        float4 a0 = *(const float4*)(Aptr);
        float4 a1 = *(const float4*)(Aptr + 4);
        As[0][acol + 0][arow] = a0.x;
        As[0][acol + 1][arow] = a0.y;
        As[0][acol + 2][arow] = a0.z;
        As[0][acol + 3][arow] = a0.w;
        As[0][acol + 4][arow] = a1.x;
        As[0][acol + 5][arow] = a1.y;
        As[0][acol + 6][arow] = a1.z;
        As[0][acol + 7][arow] = a1.w;
        *(float4*)&Bs[0][brow][bcol] = *(const float4*)(Bptr);
    }
    __syncthreads();

    for (int kb = 0; kb < 32; kb++) {
        int cur = kb & 1;
        float4 a0n, a1n, bvn;
        bool more = (kb + 1 < 32);
        if (more) {
            a0n = *(const float4*)(Aptr + (kb + 1) * 16);
            a1n = *(const float4*)(Aptr + (kb + 1) * 16 + 4);
            bvn = *(const float4*)(Bptr + (size_t)(kb + 1) * 16 * DVv);
        }
        #pragma unroll
        for (int kk = 0; kk < 16; kk++) {
            float a[8], b[4];
            *(float4*)(a)     = *(const float4*)&As[cur][kk][ty * 4];
            *(float4*)(a + 4) = *(const float4*)&As[cur][kk][64 + ty * 4];
            *(float4*)(b)     = *(const float4*)&Bs[cur][kk][tx * 4];
            #pragma unroll
            for (int i = 0; i < 8; i++)
                #pragma unroll
                for (int j = 0; j < 4; j++)
                    acc[i][j] = fmaf(a[i], b[j], acc[i][j]);
        }
        if (more) {
            int nxt = cur ^ 1;
            As[nxt][acol + 0][arow] = a0n.x;
            As[nxt][acol + 1][arow] = a0n.y;
            As[nxt][acol + 2][arow] = a0n.z;
            As[nxt][acol + 3][arow] = a0n.w;
            As[nxt][acol + 4][arow] = a1n.x;
            As[nxt][acol + 5][arow] = a1n.y;
            As[nxt][acol + 6][arow] = a1n.z;
            As[nxt][acol + 7][arow] = a1n.w;
            *(float4*)&Bs[nxt][brow][bcol] = bvn;
            __syncthreads();
        }
    }

    #pragma unroll
    for (int i = 0; i < 8; i++) {
        int r = row0 + ((i < 4) ? ty * 4 + i : 64 + ty * 4 + i - 4);
        #pragma unroll
        for (int j = 0; j < 4; j++) {
            int c = tx * 4 + j;
            g_ao[((size_t)b_ * Ll + r) * Dd + h_ * DVv + c] = acc[i][j];
        }
    }
}

// ---------------- misc ----------------
__global__ void zero_kernel() { g_kl = 0.0; }

__global__ void finalize_kernel(float* out, int out_size) {
    if (out_size > Bb * Ll * Dd)
        out[Bb * Ll * Dd] = (float)(g_kl / 33554432.0);
}

// ---------------- launch ----------------
extern "C" void kernel_launch(void* const* d_in, const int* in_sizes, int n_in,
                              void* d_out, int out_size) {
    const float* queries = (const float*)d_in[0];
    const float* keys    = (const float*)d_in[1];
    const float* values  = (const float*)d_in[2];
    const float* unif    = (const float*)d_in[3];
    const float* Wq = (const float*)d_in[4];
    const float* bq = (const float*)d_in[5];
    const float* Wk = (const float*)d_in[6];
    const float* bk = (const float*)d_in[7];
    const float* Wv = (const float*)d_in[8];
    const float* bv = (const float*)d_in[9];
    const float* Wo = (const float*)d_in[10];
    const float* bo = (const float*)d_in[11];
    const float* Wp1 = (const float*)d_in[12];
    const float* bp1 = (const float*)d_in[13];
    const float* Wp2 = (const float*)d_in[14];
    const float* bp2 = (const float*)d_in[15];
    float* out = (float*)d_out;

    float *pq, *pk, *pv_, *pao, *pwt;
    cudaGetSymbolAddress((void**)&pq, g_q);
    cudaGetSymbolAddress((void**)&pk, g_k);
    cudaGetSymbolAddress((void**)&pv_, g_v);
    cudaGetSymbolAddress((void**)&pao, g_ao);
    cudaGetSymbolAddress((void**)&pwt, g_wt);

    const int GSMEM = 2 * STAGEF * 4;   // 40960 bytes
    static int smem_set = 0;
    if (!smem_set) {
        cudaFuncSetAttribute(mma_gemm, cudaFuncAttributeMaxDynamicSharedMemorySize, GSMEM);
        smem_set = 1;
    }

    zero_kernel<<<1, 1>>>();

    dim3 gmm(8, 32);
    dim3 tr(32, 8);

    // Q projection (scale 8 = sqrt(DK))
    w_transpose<<<dim3(32, 32), tr>>>(Wq, pwt);
    mma_gemm<<<gmm, 256, GSMEM>>>(queries, pwt, bq, pq, 1, 8.0f);

    // K projection
    w_transpose<<<dim3(32, 32), tr>>>(Wk, pwt);
    mma_gemm<<<gmm, 256, GSMEM>>>(keys, pwt, bk, pk, 1, 1.0f);

    // V projection
    w_transpose<<<dim3(32, 32), tr>>>(Wv, pwt);
    mma_gemm<<<gmm, 256, GSMEM>>>(values, pwt, bv, pv_, 1, 1.0f);

    prior_gemm<<<dim3(8, 512), 256>>>(Wp1, bp1, Wp2);
    combine_dotg<<<256, 256>>>(bp2);
    alpha_kernel<<<BH, 512>>>();

    score_nt<<<dim3(4, 4, BH), 256>>>();
    row_fused<<<NPOS, 256>>>(unif);
    pv_gemm<<<dim3(4, BH), 256>>>();

    // out projection
    w_transpose<<<dim3(32, 32), tr>>>(Wo, pwt);
    mma_gemm<<<gmm, 256, GSMEM>>>(pao, pwt, bo, out, 0, 1.0f);

    finalize_kernel<<<1, 1>>>(out, out_size);
}

// round 7
// speedup vs baseline: 1.1632x; 1.0457x over previous
#include <cuda_runtime.h>
#include <math.h>
#include <stdint.h>

#define Bb 8
#define Ll 512
#define Dd 1024
#define Hh 16
#define DKk 64
#define DVv 64
#define EPSF 1e-20f

#define BH (Bb*Hh)           // 128
#define NPOS (Bb*Hh*Ll)      // 65536
#define MROWS (Bb*Ll)        // 4096

// ---------------- scratch ----------------
__device__ float g_q[NPOS*DKk];          // [B,H,L,DK] (pre-scaled by 8)
__device__ float g_k[NPOS*DKk];
__device__ float g_v[NPOS*DVv];          // [B,H,L,DV]
__device__ float g_S[(size_t)BH*Ll*Ll];  // scores -> att_s
__device__ float g_ao[MROWS*Dd];         // attn out [B,L,H*DV]
__device__ float g_pp[8*NPOS];
__device__ float g_dotg[NPOS];
__device__ float g_alpha[NPOS];
__device__ double g_kl;
__device__ float g_wt[Dd*Dd];            // weight^T fp32 [N,K]

// ---------------- helpers ----------------
__device__ __forceinline__ float tf32_rn(float a) {
    uint32_t r;
    asm("cvt.rna.tf32.f32 %0, %1;" : "=r"(r) : "f"(a));
    return __uint_as_float(r);
}

__device__ __forceinline__ void mma_tf32(float* c, const uint32_t* a, const uint32_t* b) {
    asm volatile(
        "mma.sync.aligned.m16n8k8.row.col.f32.tf32.tf32.f32 "
        "{%0,%1,%2,%3}, {%4,%5,%6,%7}, {%8,%9}, {%0,%1,%2,%3};"
        : "+f"(c[0]), "+f"(c[1]), "+f"(c[2]), "+f"(c[3])
        : "r"(a[0]), "r"(a[1]), "r"(a[2]), "r"(a[3]), "r"(b[0]), "r"(b[1]));
}

// split one fp32 into tf32 hi/lo (as uint bits)
__device__ __forceinline__ void split2(float x, uint32_t& h, uint32_t& l) {
    float hf = tf32_rn(x);
    h = __float_as_uint(hf);
    l = __float_as_uint(tf32_rn(x - hf));
}

// W [K=1024, N=1024] row-major -> W^T fp32 [N, K]
__global__ void w_transpose(const float* __restrict__ W, float* __restrict__ T) {
    __shared__ float t[32][33];
    int bx = blockIdx.x * 32, by = blockIdx.y * 32;
    int tx = threadIdx.x, ty = threadIdx.y;     // 32 x 8
    #pragma unroll
    for (int j = 0; j < 4; j++)
        t[ty + 8 * j][tx] = W[(size_t)(by + ty + 8 * j) * 1024 + bx + tx];
    __syncthreads();
    #pragma unroll
    for (int j = 0; j < 4; j++)
        T[(size_t)(bx + ty + 8 * j) * 1024 + by + tx] = t[tx][ty + 8 * j];
}

// ---------------- 3xTF32 projection GEMM (as round 6) ----------------
#define KB 16
#define KSTR 20
#define MATF 2560
#define STAGEF 5120
__global__ __launch_bounds__(256, 2) void mma_gemm(const float* __restrict__ A,
                                                   const float* __restrict__ Bt,
                                                   const float* __restrict__ bias,
                                                   float* __restrict__ C,
                                                   int scatter, float scale)
{
    extern __shared__ float sm[];
    int tid = threadIdx.x;
    int lane = tid & 31, wid = tid >> 5;
    int g = lane >> 2, t4 = lane & 3;
    int warp_m = wid & 1;
    int warp_n = wid >> 1;
    int row0 = blockIdx.y * 128;
    int col0 = blockIdx.x * 128;

    float acc[4][4][4];
    #pragma unroll
    for (int mt = 0; mt < 4; mt++)
        #pragma unroll
        for (int nt = 0; nt < 4; nt++)
            #pragma unroll
            for (int q = 0; q < 4; q++) acc[mt][nt][q] = 0.f;

    int r0i = tid >> 2, s0i = tid & 3;
    const float* pA0 = A  + (size_t)(row0 + r0i) * 1024 + s0i * 4;
    const float* pA1 = A  + (size_t)(row0 + 64 + r0i) * 1024 + s0i * 4;
    const float* pB0 = Bt + (size_t)(col0 + r0i) * 1024 + s0i * 4;
    const float* pB1 = Bt + (size_t)(col0 + 64 + r0i) * 1024 + s0i * 4;
    int so0 = r0i * KSTR + s0i * 4;
    int so1 = (r0i + 64) * KSTR + s0i * 4;

    *(float4*)(sm + so0)        = *(const float4*)(pA0);
    *(float4*)(sm + so1)        = *(const float4*)(pA1);
    *(float4*)(sm + MATF + so0) = *(const float4*)(pB0);
    *(float4*)(sm + MATF + so1) = *(const float4*)(pB1);
    __syncthreads();

    const int NSTAGE = 1024 / KB;
    for (int ks = 0; ks < NSTAGE; ks++) {
        int buf = ks & 1;
        float4 va0, va1, vb0, vb1;
        bool more = (ks + 1 < NSTAGE);
        if (more) {
            int k0 = (ks + 1) * KB;
            va0 = *(const float4*)(pA0 + k0);
            va1 = *(const float4*)(pA1 + k0);
            vb0 = *(const float4*)(pB0 + k0);
            vb1 = *(const float4*)(pB1 + k0);
        }

        const float* Asmp = sm + buf * STAGEF + warp_m * 64 * KSTR;
        const float* Bsmp = sm + buf * STAGEF + MATF + warp_n * 32 * KSTR;

        #pragma unroll
        for (int step = 0; step < 2; step++) {
            int k8 = step * 8;
            uint32_t bhf[4][2], blf[4][2];
            #pragma unroll
            for (int nt = 0; nt < 4; nt++) {
                int rN = (nt * 8 + g) * KSTR + k8 + t4;
                split2(Bsmp[rN],     bhf[nt][0], blf[nt][0]);
                split2(Bsmp[rN + 4], bhf[nt][1], blf[nt][1]);
            }
            #pragma unroll
            for (int mt = 0; mt < 4; mt++) {
                int rA = (mt * 16 + g) * KSTR + k8 + t4;
                int rB = rA + 8 * KSTR;
                uint32_t ah[4], al[4];
                split2(Asmp[rA],     ah[0], al[0]);
                split2(Asmp[rB],     ah[1], al[1]);
                split2(Asmp[rA + 4], ah[2], al[2]);
                split2(Asmp[rB + 4], ah[3], al[3]);
                #pragma unroll
                for (int nt = 0; nt < 4; nt++) mma_tf32(acc[mt][nt], ah, bhf[nt]);
                #pragma unroll
                for (int nt = 0; nt < 4; nt++) mma_tf32(acc[mt][nt], ah, blf[nt]);
                #pragma unroll
                for (int nt = 0; nt < 4; nt++) mma_tf32(acc[mt][nt], al, bhf[nt]);
            }
        }

        if (more) {
            float* nb = sm + ((ks + 1) & 1) * STAGEF;
            __syncthreads();
            *(float4*)(nb + so0)        = va0;
            *(float4*)(nb + so1)        = va1;
            *(float4*)(nb + MATF + so0) = vb0;
            *(float4*)(nb + MATF + so1) = vb1;
            __syncthreads();
        }
    }

    #pragma unroll
    for (int mt = 0; mt < 4; mt++) {
        int r0r = row0 + warp_m * 64 + mt * 16 + g;
        int r1r = r0r + 8;
        #pragma unroll
        for (int nt = 0; nt < 4; nt++) {
            int c = col0 + warp_n * 32 + nt * 8 + 2 * t4;
            float b0 = __ldg(bias + c), b1 = __ldg(bias + c + 1);
            float2 v0 = make_float2((acc[mt][nt][0] + b0) * scale,
                                    (acc[mt][nt][1] + b1) * scale);
            float2 v1 = make_float2((acc[mt][nt][2] + b0) * scale,
                                    (acc[mt][nt][3] + b1) * scale);
            if (scatter) {
                int h_ = c >> 6, d_ = c & 63;
                int b0_ = r0r >> 9, l0_ = r0r & 511;
                int b1_ = r1r >> 9, l1_ = r1r & 511;
                *(float2*)(C + (((size_t)(b0_ * Hh + h_) * Ll) + l0_) * 64 + d_) = v0;
                *(float2*)(C + (((size_t)(b1_ * Hh + h_) * Ll) + l1_) * 64 + d_) = v1;
            } else {
                *(float2*)(C + (size_t)r0r * 1024 + c) = v0;
                *(float2*)(C + (size_t)r1r * 1024 + c) = v1;
            }
        }
    }
}

// ---------------- 3xTF32 batched QK^T: per bh [512,64]x[512,64]^T -> S ----------------
__global__ __launch_bounds__(256, 2) void score_mma() {
    extern __shared__ float sm[];
    int bh = blockIdx.z;
    const float* A  = g_q + (size_t)bh * Ll * DKk;
    const float* Bt = g_k + (size_t)bh * Ll * DKk;
    float* Sp = g_S + (size_t)bh * Ll * Ll;
    int tid = threadIdx.x;
    int lane = tid & 31, wid = tid >> 5;
    int g = lane >> 2, t4 = lane & 3;
    int warp_m = wid & 1;
    int warp_n = wid >> 1;
    int row0 = blockIdx.y * 128;
    int col0 = blockIdx.x * 128;

    float acc[4][4][4];
    #pragma unroll
    for (int mt = 0; mt < 4; mt++)
        #pragma unroll
        for (int nt = 0; nt < 4; nt++)
            #pragma unroll
            for (int q = 0; q < 4; q++) acc[mt][nt][q] = 0.f;

    int r0i = tid >> 2, s0i = tid & 3;
    const float* pA0 = A  + (size_t)(row0 + r0i) * 64 + s0i * 4;
    const float* pA1 = A  + (size_t)(row0 + 64 + r0i) * 64 + s0i * 4;
    const float* pB0 = Bt + (size_t)(col0 + r0i) * 64 + s0i * 4;
    const float* pB1 = Bt + (size_t)(col0 + 64 + r0i) * 64 + s0i * 4;
    int so0 = r0i * KSTR + s0i * 4;
    int so1 = (r0i + 64) * KSTR + s0i * 4;

    *(float4*)(sm + so0)        = *(const float4*)(pA0);
    *(float4*)(sm + so1)        = *(const float4*)(pA1);
    *(float4*)(sm + MATF + so0) = *(const float4*)(pB0);
    *(float4*)(sm + MATF + so1) = *(const float4*)(pB1);
    __syncthreads();

    const int NSTAGE = 64 / KB;    // 4
    for (int ks = 0; ks < NSTAGE; ks++) {
        int buf = ks & 1;
        float4 va0, va1, vb0, vb1;
        bool more = (ks + 1 < NSTAGE);
        if (more) {
            int k0 = (ks + 1) * KB;
            va0 = *(const float4*)(pA0 + k0);
            va1 = *(const float4*)(pA1 + k0);
            vb0 = *(const float4*)(pB0 + k0);
            vb1 = *(const float4*)(pB1 + k0);
        }

        const float* Asmp = sm + buf * STAGEF + warp_m * 64 * KSTR;
        const float* Bsmp = sm + buf * STAGEF + MATF + warp_n * 32 * KSTR;

        #pragma unroll
        for (int step = 0; step < 2; step++) {
            int k8 = step * 8;
            uint32_t bhf[4][2], blf[4][2];
            #pragma unroll
            for (int nt = 0; nt < 4; nt++) {
                int rN = (nt * 8 + g) * KSTR + k8 + t4;
                split2(Bsmp[rN],     bhf[nt][0], blf[nt][0]);
                split2(Bsmp[rN + 4], bhf[nt][1], blf[nt][1]);
            }
            #pragma unroll
            for (int mt = 0; mt < 4; mt++) {
                int rA = (mt * 16 + g) * KSTR + k8 + t4;
                int rB = rA + 8 * KSTR;
                uint32_t ah[4], al[4];
                split2(Asmp[rA],     ah[0], al[0]);
                split2(Asmp[rB],     ah[1], al[1]);
                split2(Asmp[rA + 4], ah[2], al[2]);
                split2(Asmp[rB + 4], ah[3], al[3]);
                #pragma unroll
                for (int nt = 0; nt < 4; nt++) mma_tf32(acc[mt][nt], ah, bhf[nt]);
                #pragma unroll
                for (int nt = 0; nt < 4; nt++) mma_tf32(acc[mt][nt], ah, blf[nt]);
                #pragma unroll
                for (int nt = 0; nt < 4; nt++) mma_tf32(acc[mt][nt], al, bhf[nt]);
            }
        }

        if (more) {
            float* nb = sm + ((ks + 1) & 1) * STAGEF;
            __syncthreads();
            *(float4*)(nb + so0)        = va0;
            *(float4*)(nb + so1)        = va1;
            *(float4*)(nb + MATF + so0) = vb0;
            *(float4*)(nb + MATF + so1) = vb1;
            __syncthreads();
        }
    }

    #pragma unroll
    for (int mt = 0; mt < 4; mt++) {
        int r0r = row0 + warp_m * 64 + mt * 16 + g;
        int r1r = r0r + 8;
        #pragma unroll
        for (int nt = 0; nt < 4; nt++) {
            int c = col0 + warp_n * 32 + nt * 8 + 2 * t4;
            *(float2*)(Sp + (size_t)r0r * 512 + c) = make_float2(acc[mt][nt][0], acc[mt][nt][1]);
            *(float2*)(Sp + (size_t)r1r * 512 + c) = make_float2(acc[mt][nt][2], acc[mt][nt][3]);
        }
    }
}

// ---------------- 3xTF32 batched att_s @ V -> g_ao ----------------
// A = att_s [512,512] K-major; B = V [512,64] row-major fed directly as B-frag (k=row).
#define VSTR 72
#define PAF 2560              // A tile 128*20
#define PBF (16*VSTR)         // 1152
#define PSTAGEF (PAF + PBF)   // 3712
__global__ __launch_bounds__(256, 2) void pv_mma() {
    extern __shared__ float sm[];
    int bh = blockIdx.y;
    int b_ = bh >> 4, h_ = bh & 15;
    const float* A  = g_S + (size_t)bh * Ll * Ll;
    const float* Bv = g_v + (size_t)bh * Ll * DVv;
    int tid = threadIdx.x;
    int lane = tid & 31, wid = tid >> 5;
    int g = lane >> 2, t4 = lane & 3;
    int warp_m = wid & 3;     // 4 warps over M (32 rows)
    int warp_n = wid >> 2;    // 2 warps over N (32 cols)
    int row0 = blockIdx.x * 128;

    float acc[2][4][4];
    #pragma unroll
    for (int mt = 0; mt < 2; mt++)
        #pragma unroll
        for (int nt = 0; nt < 4; nt++)
            #pragma unroll
            for (int q = 0; q < 4; q++) acc[mt][nt][q] = 0.f;

    int r0i = tid >> 2, s0i = tid & 3;
    const float* pA0 = A + (size_t)(row0 + r0i) * 512 + s0i * 4;
    const float* pA1 = A + (size_t)(row0 + 64 + r0i) * 512 + s0i * 4;
    int rowb = tid >> 4, segb = tid & 15;      // 16 rows x 16 float4
    const float* pBv = Bv + (size_t)rowb * 64 + segb * 4;
    int so0 = r0i * KSTR + s0i * 4;
    int so1 = (r0i + 64) * KSTR + s0i * 4;
    int sob = PAF + rowb * VSTR + segb * 4;

    *(float4*)(sm + so0) = *(const float4*)(pA0);
    *(float4*)(sm + so1) = *(const float4*)(pA1);
    *(float4*)(sm + sob) = *(const float4*)(pBv);
    __syncthreads();

    const int NSTAGE = 512 / KB;   // 32
    for (int ks = 0; ks < NSTAGE; ks++) {
        int buf = ks & 1;
        float4 va0, va1, vb0;
        bool more = (ks + 1 < NSTAGE);
        if (more) {
            int k0 = (ks + 1) * KB;
            va0 = *(const float4*)(pA0 + k0);
            va1 = *(const float4*)(pA1 + k0);
            vb0 = *(const float4*)(pBv + (size_t)k0 * 64);
        }

        const float* Asmp = sm + buf * PSTAGEF + warp_m * 32 * KSTR;
        const float* Bsmp = sm + buf * PSTAGEF + PAF;

        #pragma unroll
        for (int step = 0; step < 2; step++) {
            int k8 = step * 8;
            uint32_t bhf[4][2], blf[4][2];
            #pragma unroll
            for (int nt = 0; nt < 4; nt++) {
                int col = warp_n * 32 + nt * 8 + g;
                split2(Bsmp[(k8 + t4) * VSTR + col],     bhf[nt][0], blf[nt][0]);
                split2(Bsmp[(k8 + t4 + 4) * VSTR + col], bhf[nt][1], blf[nt][1]);
            }
            #pragma unroll
            for (int mt = 0; mt < 2; mt++) {
                int rA = (mt * 16 + g) * KSTR + k8 + t4;
                int rB = rA + 8 * KSTR;
                uint32_t ah[4], al[4];
                split2(Asmp[rA],     ah[0], al[0]);
                split2(Asmp[rB],     ah[1], al[1]);
                split2(Asmp[rA + 4], ah[2], al[2]);
                split2(Asmp[rB + 4], ah[3], al[3]);
                #pragma unroll
                for (int nt = 0; nt < 4; nt++) mma_tf32(acc[mt][nt], ah, bhf[nt]);
                #pragma unroll
                for (int nt = 0; nt < 4; nt++) mma_tf32(acc[mt][nt], ah, blf[nt]);
                #pragma unroll
                for (int nt = 0; nt < 4; nt++) mma_tf32(acc[mt][nt], al, bhf[nt]);
            }
        }

        if (more) {
            float* nb = sm + ((ks + 1) & 1) * PSTAGEF;
            __syncthreads();
            *(float4*)(nb + so0) = va0;
            *(float4*)(nb + so1) = va1;
            *(float4*)(nb + sob) = vb0;
            __syncthreads();
        }
    }

    #pragma unroll
    for (int mt = 0; mt < 2; mt++) {
        int r0r = row0 + warp_m * 32 + mt * 16 + g;
        int r1r = r0r + 8;
        #pragma unroll
        for (int nt = 0; nt < 4; nt++) {
            int c = warp_n * 32 + nt * 8 + 2 * t4;
            *(float2*)(g_ao + ((size_t)b_ * Ll + r0r) * Dd + h_ * DVv + c) =
                make_float2(acc[mt][nt][0], acc[mt][nt][1]);
            *(float2*)(g_ao + ((size_t)b_ * Ll + r1r) * Dd + h_ * DVv + c) =
                make_float2(acc[mt][nt][2], acc[mt][nt][3]);
        }
    }
}

// ---------------- block reduction helper ----------------
__device__ __forceinline__ float blkred(float v, bool ismax, float* sred) {
    #pragma unroll
    for (int o = 16; o; o >>= 1) {
        float w = __shfl_xor_sync(0xffffffffu, v, o);
        v = ismax ? fmaxf(v, w) : v + w;
    }
    int wid = threadIdx.x >> 5, lid = threadIdx.x & 31;
    int nw = blockDim.x >> 5;
    if (lid == 0) sred[wid] = v;
    __syncthreads();
    if (wid == 0) {
        v = (lid < nw) ? sred[lid] : (ismax ? -3.402823e38f : 0.f);
        #pragma unroll
        for (int o = 16; o; o >>= 1) {
            float w = __shfl_xor_sync(0xffffffffu, v, o);
            v = ismax ? fmaxf(v, w) : v + w;
        }
        if (lid == 0) sred[0] = v;
    }
    __syncthreads();
    float r = sred[0];
    __syncthreads();
    return r;
}

// ---------------- fast branchless lgamma ----------------
__device__ __forceinline__ float lgamma_fast(float x) {
    bool refl = (x < 0.5f);
    float z = refl ? 1.0f - x : x;
    float p = 1.0f;
    #pragma unroll
    for (int i = 0; i < 8; i++) {
        if (z < 8.0f) { p *= z; z += 1.0f; }
    }
    float invz  = 1.0f / z;
    float invz2 = invz * invz;
    float lz = __logf(z);
    float lg = (z - 0.5f) * lz - z + 0.91893853320467274f
             + invz * (8.3333333333e-2f
             + invz2 * (-2.7777777778e-3f + 7.9365079365e-4f * invz2));
    lg -= __logf(p);
    if (refl) {
        float s = sinpif(x);
        lg = 1.1447298858494002f - __logf(fabsf(s)) - lg;
    }
    return lg;
}

// ---------------- prior MLP GEMM (SIMT) ----------------
__global__ __launch_bounds__(256, 2) void prior_gemm(const float* __restrict__ Wp1,
                                                     const float* __restrict__ bp1,
                                                     const float* __restrict__ Wp2)
{
    __shared__ float As[2][8][128];
    __shared__ float Bs[2][8][128];
    int tid = threadIdx.x;
    int row0 = blockIdx.y * 128;
    int col0 = blockIdx.x * 128;
    int tx = tid & 15, ty = tid >> 4;

    float acc[8][8];
    #pragma unroll
    for (int i = 0; i < 8; i++)
        #pragma unroll
        for (int j = 0; j < 8; j++) acc[i][j] = 0.f;

    int arow = tid >> 1, acol = (tid & 1) * 4;
    int brow = tid >> 5, bcol = (tid & 31) * 4;
    const float* Aptr = g_k + (size_t)(row0 + arow) * 64 + acol;
    const float* Bptr = Wp1 + (size_t)brow * 1024 + col0 + bcol;

    {
        float4 av = *(const float4*)(Aptr);
        As[0][acol + 0][arow] = av.x;
        As[0][acol + 1][arow] = av.y;
        As[0][acol + 2][arow] = av.z;
        As[0][acol + 3][arow] = av.w;
        *(float4*)&Bs[0][brow][bcol] = *(const float4*)(Bptr);
    }
    __syncthreads();

    for (int kb = 0; kb < 8; kb++) {
        int cur = kb & 1;
        float4 av2, bv2;
        bool more = (kb + 1 < 8);
        if (more) {
            av2 = *(const float4*)(Aptr + (kb + 1) * 8);
            bv2 = *(const float4*)(Bptr + (size_t)(kb + 1) * 8 * 1024);
        }
        #pragma unroll
        for (int kk = 0; kk < 8; kk++) {
            float a[8], b[8];
            *(float4*)(a)     = *(const float4*)&As[cur][kk][ty * 4];
            *(float4*)(a + 4) = *(const float4*)&As[cur][kk][64 + ty * 4];
            *(float4*)(b)     = *(const float4*)&Bs[cur][kk][tx * 4];
            *(float4*)(b + 4) = *(const float4*)&Bs[cur][kk][64 + tx * 4];
            #pragma unroll
            for (int i = 0; i < 8; i++)
                #pragma unroll
                for (int j = 0; j < 8; j++)
                    acc[i][j] = fmaf(a[i], b[j], acc[i][j]);
        }
        if (more) {
            int nxt = cur ^ 1;
            As[nxt][acol + 0][arow] = av2.x;
            As[nxt][acol + 1][arow] = av2.y;
            As[nxt][acol + 2][arow] = av2.z;
            As[nxt][acol + 3][arow] = av2.w;
            *(float4*)&Bs[nxt][brow][bcol] = bv2;
            __syncthreads();
        }
    }

    #pragma unroll
    for (int i = 0; i < 8; i++) {
        int rl = (i < 4) ? ty * 4 + i : 64 + ty * 4 + i - 4;
        float s = 0.f;
        #pragma unroll
        for (int j = 0; j < 8; j++) {
            int c = col0 + ((j < 4) ? tx * 4 + j : 64 + tx * 4 + j - 4);
            float hv = acc[i][j] + bp1[c];
            hv = (hv >= 0.f) ? hv : 0.01f * hv;
            s = fmaf(hv, Wp2[c], s);
        }
        #pragma unroll
        for (int o = 8; o; o >>= 1) s += __shfl_xor_sync(0xffffffffu, s, o);
        if (tx == 0) g_pp[(size_t)blockIdx.x * NPOS + row0 + rl] = s;
    }
}

__global__ void combine_dotg(const float* __restrict__ bp2) {
    int i = blockIdx.x * 256 + threadIdx.x;
    float s = 0.f;
    #pragma unroll
    for (int t = 0; t < 8; t++) s += g_pp[(size_t)t * NPOS + i];
    g_dotg[i] = s + bp2[0];
}

// ---------------- alpha softmax + per-(b,h) KL constant terms ----------------
__global__ __launch_bounds__(512) void alpha_kernel() {
    __shared__ float sred[32];
    int bh = blockIdx.x;
    int t = threadIdx.x;
    float x = g_dotg[bh * Ll + t];
    float m = blkred(x, true, sred);
    float e = expf(x - m);
    float den = blkred(e, false, sred);
    float a = e / den;
    g_alpha[bh * Ll + t] = a;
    const float lg1 = 0.69314718f;
    const float EG  = 0.5772156649f;
    float C = a * lg1 + 2.f * EG * a + lgammaf(a + EPSF);
    float sc = blkred(C, false, sred);
    if (t == 0) atomicAdd(&g_kl, (double)(512.0f * sc));
}

// ---------------- fused row pass: warp per row, shfl-only reductions ----------------
__global__ __launch_bounds__(256) void row_fused(const float* __restrict__ U) {
    int lane = threadIdx.x & 31;
    int wrp = threadIdx.x >> 5;
    int row = blockIdx.x * 8 + wrp;
    int bh = row >> 9;
    size_t base = (size_t)row * 512;

    float s[16];
    float m = -3.402823e38f;
    #pragma unroll
    for (int i = 0; i < 16; i++) {
        s[i] = g_S[base + lane + 32 * i];
        m = fmaxf(m, s[i]);
    }
    #pragma unroll
    for (int o = 16; o; o >>= 1) m = fmaxf(m, __shfl_xor_sync(0xffffffffu, m, o));

    float e[16], den = 0.f;
    #pragma unroll
    for (int i = 0; i < 16; i++) { e[i] = __expf(s[i] - m); den += e[i]; }
    #pragma unroll
    for (int o = 16; o; o >>= 1) den += __shfl_xor_sync(0xffffffffu, den, o);

    float inv = 1.f / den;
    float logden = __logf(den);
    float p[16], lp[16];
    #pragma unroll
    for (int i = 0; i < 16; i++) {
        p[i] = e[i] * inv;
        float r = s[i] - m - logden;
        lp[i] = (r >= -36.f) ? r : __logf(p[i] + EPSF);
    }

    float t[16];
    #pragma unroll
    for (int i = 0; i < 16; i++) {
        float u = U[base + lane + 32 * i];
        float w = -logf(1.f - u + EPSF);
        float gw = __logf(w + EPSF);
        t[i] = lp[i] - lgamma_fast(3.f + 2.f * gw);
    }

    float m2 = -3.402823e38f;
    #pragma unroll
    for (int i = 0; i < 16; i++) m2 = fmaxf(m2, t[i]);
    #pragma unroll
    for (int o = 16; o; o >>= 1) m2 = fmaxf(m2, __shfl_xor_sync(0xffffffffu, m2, o));

    float q[16], d2 = 0.f;
    #pragma unroll
    for (int i = 0; i < 16; i++) { q[i] = __expf(t[i] - m2); d2 += q[i]; }
    #pragma unroll
    for (int o = 16; o; o >>= 1) d2 += __shfl_xor_sync(0xffffffffu, d2, o);
    float i2 = 1.f / d2;

    float kl = 0.f;
    #pragma unroll
    for (int i = 0; i < 16; i++) {
        g_S[base + lane + 32 * i] = q[i] * i2;
        float a = g_alpha[bh * 512 + lane + 32 * i];
        kl += fmaf(-a, lp[i], p[i]);
    }
    #pragma unroll
    for (int o = 16; o; o >>= 1) kl += __shfl_xor_sync(0xffffffffu, kl, o);
    if (lane == 0) atomicAdd(&g_kl, (double)kl);
}

// ---------------- misc ----------------
__global__ void zero_kernel() { g_kl = 0.0; }

__global__ void finalize_kernel(float* out, int out_size) {
    if (out_size > Bb * Ll * Dd)
        out[Bb * Ll * Dd] = (float)(g_kl / 33554432.0);
}

// ---------------- launch ----------------
extern "C" void kernel_launch(void* const* d_in, const int* in_sizes, int n_in,
                              void* d_out, int out_size) {
    const float* queries = (const float*)d_in[0];
    const float* keys    = (const float*)d_in[1];
    const float* values  = (const float*)d_in[2];
    const float* unif    = (const float*)d_in[3];
    const float* Wq = (const float*)d_in[4];
    const float* bq = (const float*)d_in[5];
    const float* Wk = (const float*)d_in[6];
    const float* bk = (const float*)d_in[7];
    const float* Wv = (const float*)d_in[8];
    const float* bv = (const float*)d_in[9];
    const float* Wo = (const float*)d_in[10];
    const float* bo = (const float*)d_in[11];
    const float* Wp1 = (const float*)d_in[12];
    const float* bp1 = (const float*)d_in[13];
    const float* Wp2 = (const float*)d_in[14];
    const float* bp2 = (const float*)d_in[15];
    float* out = (float*)d_out;

    float *pq, *pk, *pv_, *pao, *pwt;
    cudaGetSymbolAddress((void**)&pq, g_q);
    cudaGetSymbolAddress((void**)&pk, g_k);
    cudaGetSymbolAddress((void**)&pv_, g_v);
    cudaGetSymbolAddress((void**)&pao, g_ao);
    cudaGetSymbolAddress((void**)&pwt, g_wt);

    const int GSMEM = 2 * STAGEF * 4;    // 40960 B
    const int PSMEM = 2 * PSTAGEF * 4;   // 29696 B
    static int smem_set = 0;
    if (!smem_set) {
        cudaFuncSetAttribute(mma_gemm, cudaFuncAttributeMaxDynamicSharedMemorySize, GSMEM);
        cudaFuncSetAttribute(score_mma, cudaFuncAttributeMaxDynamicSharedMemorySize, GSMEM);
        cudaFuncSetAttribute(pv_mma, cudaFuncAttributeMaxDynamicSharedMemorySize, PSMEM);
        smem_set = 1;
    }

    zero_kernel<<<1, 1>>>();

    dim3 gmm(8, 32);
    dim3 tr(32, 8);

    // Q projection (scale 8 = sqrt(DK))
    w_transpose<<<dim3(32, 32), tr>>>(Wq, pwt);
    mma_gemm<<<gmm, 256, GSMEM>>>(queries, pwt, bq, pq, 1, 8.0f);

    // K projection
    w_transpose<<<dim3(32, 32), tr>>>(Wk, pwt);
    mma_gemm<<<gmm, 256, GSMEM>>>(keys, pwt, bk, pk, 1, 1.0f);

    // V projection
    w_transpose<<<dim3(32, 32), tr>>>(Wv, pwt);
    mma_gemm<<<gmm, 256, GSMEM>>>(values, pwt, bv, pv_, 1, 1.0f);

    prior_gemm<<<dim3(8, 512), 256>>>(Wp1, bp1, Wp2);
    combine_dotg<<<256, 256>>>(bp2);
    alpha_kernel<<<BH, 512>>>();

    score_mma<<<dim3(4, 4, BH), 256, GSMEM>>>();
    row_fused<<<NPOS / 8, 256>>>(unif);
    pv_mma<<<dim3(4, BH), 256, PSMEM>>>();

    // out projection
    w_transpose<<<dim3(32, 32), tr>>>(Wo, pwt);
    mma_gemm<<<gmm, 256, GSMEM>>>(pao, pwt, bo, out, 0, 1.0f);

    finalize_kernel<<<1, 1>>>(out, out_size);
}

// round 8
// speedup vs baseline: 1.4573x; 1.2528x over previous
#include <cuda_runtime.h>
#include <math.h>
#include <stdint.h>

#define Bb 8
#define Ll 512
#define Dd 1024
#define Hh 16
#define DKk 64
#define DVv 64
#define EPSF 1e-20f

#define BH (Bb*Hh)           // 128
#define NPOS (Bb*Hh*Ll)      // 65536
#define MROWS (Bb*Ll)        // 4096

// ---------------- scratch ----------------
__device__ float g_q[NPOS*DKk];          // [B,H,L,DK] (pre-scaled by 8)
__device__ float g_k[NPOS*DKk];
__device__ float g_v[NPOS*DVv];
__device__ float g_S[(size_t)BH*Ll*Ll];  // scores -> att_s
__device__ float g_ao[MROWS*Dd];         // attn out [B,L,H*DV]
__device__ float g_pp[(size_t)32*NPOS];  // prior partials (32 col groups)
__device__ float g_dotg[NPOS];
__device__ float g_alpha[NPOS];
__device__ double g_kl;
__device__ float g_wt[Dd*Dd];            // transposed weights (reused sequentially)

// ---------------- helpers ----------------
__device__ __forceinline__ void mma_tf32(float* c, const uint32_t* a, const uint32_t* b) {
    asm volatile(
        "mma.sync.aligned.m16n8k8.row.col.f32.tf32.tf32.f32 "
        "{%0,%1,%2,%3}, {%4,%5,%6,%7}, {%8,%9}, {%0,%1,%2,%3};"
        : "+f"(c[0]), "+f"(c[1]), "+f"(c[2]), "+f"(c[3])
        : "r"(a[0]), "r"(a[1]), "r"(a[2]), "r"(a[3]), "r"(b[0]), "r"(b[1]));
}

// cheap split: hi = mantissa-truncated x (tf32 bits), lo = exact residual
// (MMA datapath reads only the tf32 field, so the residual's low bits
//  truncate in HW; total extra error ~2^-20 relative — negligible)
__device__ __forceinline__ void split2(float x, uint32_t& h, uint32_t& l) {
    uint32_t xb = __float_as_uint(x);
    h = xb & 0xFFFFE000u;
    l = __float_as_uint(x - __uint_as_float(h));
}

// generic 32x32-tiled transpose: T[c*rows + r] = W[r*cols + c]
__global__ void transpose_k(const float* __restrict__ W, float* __restrict__ T,
                            int rows, int cols) {
    __shared__ float t[32][33];
    int bx = blockIdx.x * 32, by = blockIdx.y * 32;
    int tx = threadIdx.x, ty = threadIdx.y;     // 32 x 8
    #pragma unroll
    for (int j = 0; j < 4; j++)
        t[ty + 8 * j][tx] = W[(size_t)(by + ty + 8 * j) * cols + bx + tx];
    __syncthreads();
    #pragma unroll
    for (int j = 0; j < 4; j++)
        T[(size_t)(bx + ty + 8 * j) * rows + by + tx] = t[tx][ty + 8 * j];
}

// ---------------- 3xTF32 projection GEMM ----------------
#define KB 16
#define KSTR 20
#define MATF 2560
#define STAGEF 5120
__global__ __launch_bounds__(256, 2) void mma_gemm(const float* __restrict__ A,
                                                   const float* __restrict__ Bt,
                                                   const float* __restrict__ bias,
                                                   float* __restrict__ C,
                                                   int scatter, float scale)
{
    extern __shared__ float sm[];
    int tid = threadIdx.x;
    int lane = tid & 31, wid = tid >> 5;
    int g = lane >> 2, t4 = lane & 3;
    int warp_m = wid & 1;
    int warp_n = wid >> 1;
    int row0 = blockIdx.y * 128;
    int col0 = blockIdx.x * 128;

    float acc[4][4][4];
    #pragma unroll
    for (int mt = 0; mt < 4; mt++)
        #pragma unroll
        for (int nt = 0; nt < 4; nt++)
            #pragma unroll
            for (int q = 0; q < 4; q++) acc[mt][nt][q] = 0.f;

    int r0i = tid >> 2, s0i = tid & 3;
    const float* pA0 = A  + (size_t)(row0 + r0i) * 1024 + s0i * 4;
    const float* pA1 = A  + (size_t)(row0 + 64 + r0i) * 1024 + s0i * 4;
    const float* pB0 = Bt + (size_t)(col0 + r0i) * 1024 + s0i * 4;
    const float* pB1 = Bt + (size_t)(col0 + 64 + r0i) * 1024 + s0i * 4;
    int so0 = r0i * KSTR + s0i * 4;
    int so1 = (r0i + 64) * KSTR + s0i * 4;

    *(float4*)(sm + so0)        = *(const float4*)(pA0);
    *(float4*)(sm + so1)        = *(const float4*)(pA1);
    *(float4*)(sm + MATF + so0) = *(const float4*)(pB0);
    *(float4*)(sm + MATF + so1) = *(const float4*)(pB1);
    __syncthreads();

    const int NSTAGE = 1024 / KB;
    for (int ks = 0; ks < NSTAGE; ks++) {
        int buf = ks & 1;
        float4 va0, va1, vb0, vb1;
        bool more = (ks + 1 < NSTAGE);
        if (more) {
            int k0 = (ks + 1) * KB;
            va0 = *(const float4*)(pA0 + k0);
            va1 = *(const float4*)(pA1 + k0);
            vb0 = *(const float4*)(pB0 + k0);
            vb1 = *(const float4*)(pB1 + k0);
        }

        const float* Asmp = sm + buf * STAGEF + warp_m * 64 * KSTR;
        const float* Bsmp = sm + buf * STAGEF + MATF + warp_n * 32 * KSTR;

        #pragma unroll
        for (int step = 0; step < 2; step++) {
            int k8 = step * 8;
            uint32_t bhf[4][2], blf[4][2];
            #pragma unroll
            for (int nt = 0; nt < 4; nt++) {
                int rN = (nt * 8 + g) * KSTR + k8 + t4;
                split2(Bsmp[rN],     bhf[nt][0], blf[nt][0]);
                split2(Bsmp[rN + 4], bhf[nt][1], blf[nt][1]);
            }
            #pragma unroll
            for (int mt = 0; mt < 4; mt++) {
                int rA = (mt * 16 + g) * KSTR + k8 + t4;
                int rB = rA + 8 * KSTR;
                uint32_t ah[4], al[4];
                split2(Asmp[rA],     ah[0], al[0]);
                split2(Asmp[rB],     ah[1], al[1]);
                split2(Asmp[rA + 4], ah[2], al[2]);
                split2(Asmp[rB + 4], ah[3], al[3]);
                #pragma unroll
                for (int nt = 0; nt < 4; nt++) mma_tf32(acc[mt][nt], ah, bhf[nt]);
                #pragma unroll
                for (int nt = 0; nt < 4; nt++) mma_tf32(acc[mt][nt], ah, blf[nt]);
                #pragma unroll
                for (int nt = 0; nt < 4; nt++) mma_tf32(acc[mt][nt], al, bhf[nt]);
            }
        }

        if (more) {
            float* nb = sm + ((ks + 1) & 1) * STAGEF;
            __syncthreads();
            *(float4*)(nb + so0)        = va0;
            *(float4*)(nb + so1)        = va1;
            *(float4*)(nb + MATF + so0) = vb0;
            *(float4*)(nb + MATF + so1) = vb1;
            __syncthreads();
        }
    }

    #pragma unroll
    for (int mt = 0; mt < 4; mt++) {
        int r0r = row0 + warp_m * 64 + mt * 16 + g;
        int r1r = r0r + 8;
        #pragma unroll
        for (int nt = 0; nt < 4; nt++) {
            int c = col0 + warp_n * 32 + nt * 8 + 2 * t4;
            float b0 = __ldg(bias + c), b1 = __ldg(bias + c + 1);
            float2 v0 = make_float2((acc[mt][nt][0] + b0) * scale,
                                    (acc[mt][nt][1] + b1) * scale);
            float2 v1 = make_float2((acc[mt][nt][2] + b0) * scale,
                                    (acc[mt][nt][3] + b1) * scale);
            if (scatter) {
                int h_ = c >> 6, d_ = c & 63;
                int b0_ = r0r >> 9, l0_ = r0r & 511;
                int b1_ = r1r >> 9, l1_ = r1r & 511;
                *(float2*)(C + (((size_t)(b0_ * Hh + h_) * Ll) + l0_) * 64 + d_) = v0;
                *(float2*)(C + (((size_t)(b1_ * Hh + h_) * Ll) + l1_) * 64 + d_) = v1;
            } else {
                *(float2*)(C + (size_t)r0r * 1024 + c) = v0;
                *(float2*)(C + (size_t)r1r * 1024 + c) = v1;
            }
        }
    }
}

// ---------------- 3xTF32 batched QK^T ----------------
__global__ __launch_bounds__(256, 2) void score_mma() {
    extern __shared__ float sm[];
    int bh = blockIdx.z;
    const float* A  = g_q + (size_t)bh * Ll * DKk;
    const float* Bt = g_k + (size_t)bh * Ll * DKk;
    float* Sp = g_S + (size_t)bh * Ll * Ll;
    int tid = threadIdx.x;
    int lane = tid & 31, wid = tid >> 5;
    int g = lane >> 2, t4 = lane & 3;
    int warp_m = wid & 1;
    int warp_n = wid >> 1;
    int row0 = blockIdx.y * 128;
    int col0 = blockIdx.x * 128;

    float acc[4][4][4];
    #pragma unroll
    for (int mt = 0; mt < 4; mt++)
        #pragma unroll
        for (int nt = 0; nt < 4; nt++)
            #pragma unroll
            for (int q = 0; q < 4; q++) acc[mt][nt][q] = 0.f;

    int r0i = tid >> 2, s0i = tid & 3;
    const float* pA0 = A  + (size_t)(row0 + r0i) * 64 + s0i * 4;
    const float* pA1 = A  + (size_t)(row0 + 64 + r0i) * 64 + s0i * 4;
    const float* pB0 = Bt + (size_t)(col0 + r0i) * 64 + s0i * 4;
    const float* pB1 = Bt + (size_t)(col0 + 64 + r0i) * 64 + s0i * 4;
    int so0 = r0i * KSTR + s0i * 4;
    int so1 = (r0i + 64) * KSTR + s0i * 4;

    *(float4*)(sm + so0)        = *(const float4*)(pA0);
    *(float4*)(sm + so1)        = *(const float4*)(pA1);
    *(float4*)(sm + MATF + so0) = *(const float4*)(pB0);
    *(float4*)(sm + MATF + so1) = *(const float4*)(pB1);
    __syncthreads();

    const int NSTAGE = 64 / KB;    // 4
    for (int ks = 0; ks < NSTAGE; ks++) {
        int buf = ks & 1;
        float4 va0, va1, vb0, vb1;
        bool more = (ks + 1 < NSTAGE);
        if (more) {
            int k0 = (ks + 1) * KB;
            va0 = *(const float4*)(pA0 + k0);
            va1 = *(const float4*)(pA1 + k0);
            vb0 = *(const float4*)(pB0 + k0);
            vb1 = *(const float4*)(pB1 + k0);
        }

        const float* Asmp = sm + buf * STAGEF + warp_m * 64 * KSTR;
        const float* Bsmp = sm + buf * STAGEF + MATF + warp_n * 32 * KSTR;

        #pragma unroll
        for (int step = 0; step < 2; step++) {
            int k8 = step * 8;
            uint32_t bhf[4][2], blf[4][2];
            #pragma unroll
            for (int nt = 0; nt < 4; nt++) {
                int rN = (nt * 8 + g) * KSTR + k8 + t4;
                split2(Bsmp[rN],     bhf[nt][0], blf[nt][0]);
                split2(Bsmp[rN + 4], bhf[nt][1], blf[nt][1]);
            }
            #pragma unroll
            for (int mt = 0; mt < 4; mt++) {
                int rA = (mt * 16 + g) * KSTR + k8 + t4;
                int rB = rA + 8 * KSTR;
                uint32_t ah[4], al[4];
                split2(Asmp[rA],     ah[0], al[0]);
                split2(Asmp[rB],     ah[1], al[1]);
                split2(Asmp[rA + 4], ah[2], al[2]);
                split2(Asmp[rB + 4], ah[3], al[3]);
                #pragma unroll
                for (int nt = 0; nt < 4; nt++) mma_tf32(acc[mt][nt], ah, bhf[nt]);
                #pragma unroll
                for (int nt = 0; nt < 4; nt++) mma_tf32(acc[mt][nt], ah, blf[nt]);
                #pragma unroll
                for (int nt = 0; nt < 4; nt++) mma_tf32(acc[mt][nt], al, bhf[nt]);
            }
        }

        if (more) {
            float* nb = sm + ((ks + 1) & 1) * STAGEF;
            __syncthreads();
            *(float4*)(nb + so0)        = va0;
            *(float4*)(nb + so1)        = va1;
            *(float4*)(nb + MATF + so0) = vb0;
            *(float4*)(nb + MATF + so1) = vb1;
            __syncthreads();
        }
    }

    #pragma unroll
    for (int mt = 0; mt < 4; mt++) {
        int r0r = row0 + warp_m * 64 + mt * 16 + g;
        int r1r = r0r + 8;
        #pragma unroll
        for (int nt = 0; nt < 4; nt++) {
            int c = col0 + warp_n * 32 + nt * 8 + 2 * t4;
            *(float2*)(Sp + (size_t)r0r * 512 + c) = make_float2(acc[mt][nt][0], acc[mt][nt][1]);
            *(float2*)(Sp + (size_t)r1r * 512 + c) = make_float2(acc[mt][nt][2], acc[mt][nt][3]);
        }
    }
}

// ---------------- 3xTF32 prior MLP: dotg partials ----------------
// A = g_k [65536,64]; Bt = Wp1^T [1024,64]; epilogue: leaky(acc+bp1)*Wp2, row-reduce.
__global__ __launch_bounds__(256, 2) void prior_mma(const float* __restrict__ Bt,
                                                    const float* __restrict__ bp1,
                                                    const float* __restrict__ Wp2)
{
    extern __shared__ float sm[];
    const float* A = g_k;
    int tid = threadIdx.x;
    int lane = tid & 31, wid = tid >> 5;
    int g = lane >> 2, t4 = lane & 3;
    int warp_m = wid & 1;
    int warp_n = wid >> 1;
    int row0 = blockIdx.y * 128;
    int col0 = blockIdx.x * 128;

    float acc[4][4][4];
    #pragma unroll
    for (int mt = 0; mt < 4; mt++)
        #pragma unroll
        for (int nt = 0; nt < 4; nt++)
            #pragma unroll
            for (int q = 0; q < 4; q++) acc[mt][nt][q] = 0.f;

    int r0i = tid >> 2, s0i = tid & 3;
    const float* pA0 = A  + (size_t)(row0 + r0i) * 64 + s0i * 4;
    const float* pA1 = A  + (size_t)(row0 + 64 + r0i) * 64 + s0i * 4;
    const float* pB0 = Bt + (size_t)(col0 + r0i) * 64 + s0i * 4;
    const float* pB1 = Bt + (size_t)(col0 + 64 + r0i) * 64 + s0i * 4;
    int so0 = r0i * KSTR + s0i * 4;
    int so1 = (r0i + 64) * KSTR + s0i * 4;

    *(float4*)(sm + so0)        = *(const float4*)(pA0);
    *(float4*)(sm + so1)        = *(const float4*)(pA1);
    *(float4*)(sm + MATF + so0) = *(const float4*)(pB0);
    *(float4*)(sm + MATF + so1) = *(const float4*)(pB1);
    __syncthreads();

    const int NSTAGE = 64 / KB;    // 4
    for (int ks = 0; ks < NSTAGE; ks++) {
        int buf = ks & 1;
        float4 va0, va1, vb0, vb1;
        bool more = (ks + 1 < NSTAGE);
        if (more) {
            int k0 = (ks + 1) * KB;
            va0 = *(const float4*)(pA0 + k0);
            va1 = *(const float4*)(pA1 + k0);
            vb0 = *(const float4*)(pB0 + k0);
            vb1 = *(const float4*)(pB1 + k0);
        }

        const float* Asmp = sm + buf * STAGEF + warp_m * 64 * KSTR;
        const float* Bsmp = sm + buf * STAGEF + MATF + warp_n * 32 * KSTR;

        #pragma unroll
        for (int step = 0; step < 2; step++) {
            int k8 = step * 8;
            uint32_t bhf[4][2], blf[4][2];
            #pragma unroll
            for (int nt = 0; nt < 4; nt++) {
                int rN = (nt * 8 + g) * KSTR + k8 + t4;
                split2(Bsmp[rN],     bhf[nt][0], blf[nt][0]);
                split2(Bsmp[rN + 4], bhf[nt][1], blf[nt][1]);
            }
            #pragma unroll
            for (int mt = 0; mt < 4; mt++) {
                int rA = (mt * 16 + g) * KSTR + k8 + t4;
                int rB = rA + 8 * KSTR;
                uint32_t ah[4], al[4];
                split2(Asmp[rA],     ah[0], al[0]);
                split2(Asmp[rB],     ah[1], al[1]);
                split2(Asmp[rA + 4], ah[2], al[2]);
                split2(Asmp[rB + 4], ah[3], al[3]);
                #pragma unroll
                for (int nt = 0; nt < 4; nt++) mma_tf32(acc[mt][nt], ah, bhf[nt]);
                #pragma unroll
                for (int nt = 0; nt < 4; nt++) mma_tf32(acc[mt][nt], ah, blf[nt]);
                #pragma unroll
                for (int nt = 0; nt < 4; nt++) mma_tf32(acc[mt][nt], al, bhf[nt]);
            }
        }

        if (more) {
            float* nb = sm + ((ks + 1) & 1) * STAGEF;
            __syncthreads();
            *(float4*)(nb + so0)        = va0;
            *(float4*)(nb + so1)        = va1;
            *(float4*)(nb + MATF + so0) = vb0;
            *(float4*)(nb + MATF + so1) = vb1;
            __syncthreads();
        }
    }

    // epilogue: leaky + Wp2, quad-reduce, write col-group partial
    size_t grp = (size_t)(blockIdx.x * 4 + warp_n) * NPOS;
    #pragma unroll
    for (int mt = 0; mt < 4; mt++) {
        float rs0 = 0.f, rs1 = 0.f;
        #pragma unroll
        for (int nt = 0; nt < 4; nt++) {
            int c = col0 + warp_n * 32 + nt * 8 + 2 * t4;
            float b0 = __ldg(bp1 + c), b1 = __ldg(bp1 + c + 1);
            float w0 = __ldg(Wp2 + c), w1 = __ldg(Wp2 + c + 1);
            float hv;
            hv = acc[mt][nt][0] + b0; hv = (hv >= 0.f) ? hv : 0.01f * hv; rs0 = fmaf(hv, w0, rs0);
            hv = acc[mt][nt][1] + b1; hv = (hv >= 0.f) ? hv : 0.01f * hv; rs0 = fmaf(hv, w1, rs0);
            hv = acc[mt][nt][2] + b0; hv = (hv >= 0.f) ? hv : 0.01f * hv; rs1 = fmaf(hv, w0, rs1);
            hv = acc[mt][nt][3] + b1; hv = (hv >= 0.f) ? hv : 0.01f * hv; rs1 = fmaf(hv, w1, rs1);
        }
        rs0 += __shfl_xor_sync(0xffffffffu, rs0, 1);
        rs0 += __shfl_xor_sync(0xffffffffu, rs0, 2);
        rs1 += __shfl_xor_sync(0xffffffffu, rs1, 1);
        rs1 += __shfl_xor_sync(0xffffffffu, rs1, 2);
        if (t4 == 0) {
            int r0r = row0 + warp_m * 64 + mt * 16 + g;
            g_pp[grp + r0r]     = rs0;
            g_pp[grp + r0r + 8] = rs1;
        }
    }
}

__global__ void combine_dotg(const float* __restrict__ bp2) {
    int i = blockIdx.x * 256 + threadIdx.x;
    float s = 0.f;
    #pragma unroll
    for (int t = 0; t < 32; t++) s += g_pp[(size_t)t * NPOS + i];
    g_dotg[i] = s + bp2[0];
}

// ---------------- 3xTF32 batched att_s @ V -> g_ao ----------------
#define VSTR 72
#define PAF 2560
#define PBF (16*VSTR)
#define PSTAGEF (PAF + PBF)
__global__ __launch_bounds__(256, 2) void pv_mma() {
    extern __shared__ float sm[];
    int bh = blockIdx.y;
    int b_ = bh >> 4, h_ = bh & 15;
    const float* A  = g_S + (size_t)bh * Ll * Ll;
    const float* Bv = g_v + (size_t)bh * Ll * DVv;
    int tid = threadIdx.x;
    int lane = tid & 31, wid = tid >> 5;
    int g = lane >> 2, t4 = lane & 3;
    int warp_m = wid & 3;
    int warp_n = wid >> 2;
    int row0 = blockIdx.x * 128;

    float acc[2][4][4];
    #pragma unroll
    for (int mt = 0; mt < 2; mt++)
        #pragma unroll
        for (int nt = 0; nt < 4; nt++)
            #pragma unroll
            for (int q = 0; q < 4; q++) acc[mt][nt][q] = 0.f;

    int r0i = tid >> 2, s0i = tid & 3;
    const float* pA0 = A + (size_t)(row0 + r0i) * 512 + s0i * 4;
    const float* pA1 = A + (size_t)(row0 + 64 + r0i) * 512 + s0i * 4;
    int rowb = tid >> 4, segb = tid & 15;
    const float* pBv = Bv + (size_t)rowb * 64 + segb * 4;
    int so0 = r0i * KSTR + s0i * 4;
    int so1 = (r0i + 64) * KSTR + s0i * 4;
    int sob = PAF + rowb * VSTR + segb * 4;

    *(float4*)(sm + so0) = *(const float4*)(pA0);
    *(float4*)(sm + so1) = *(const float4*)(pA1);
    *(float4*)(sm + sob) = *(const float4*)(pBv);
    __syncthreads();

    const int NSTAGE = 512 / KB;   // 32
    for (int ks = 0; ks < NSTAGE; ks++) {
        int buf = ks & 1;
        float4 va0, va1, vb0;
        bool more = (ks + 1 < NSTAGE);
        if (more) {
            int k0 = (ks + 1) * KB;
            va0 = *(const float4*)(pA0 + k0);
            va1 = *(const float4*)(pA1 + k0);
            vb0 = *(const float4*)(pBv + (size_t)k0 * 64);
        }

        const float* Asmp = sm + buf * PSTAGEF + warp_m * 32 * KSTR;
        const float* Bsmp = sm + buf * PSTAGEF + PAF;

        #pragma unroll
        for (int step = 0; step < 2; step++) {
            int k8 = step * 8;
            uint32_t bhf[4][2], blf[4][2];
            #pragma unroll
            for (int nt = 0; nt < 4; nt++) {
                int col = warp_n * 32 + nt * 8 + g;
                split2(Bsmp[(k8 + t4) * VSTR + col],     bhf[nt][0], blf[nt][0]);
                split2(Bsmp[(k8 + t4 + 4) * VSTR + col], bhf[nt][1], blf[nt][1]);
            }
            #pragma unroll
            for (int mt = 0; mt < 2; mt++) {
                int rA = (mt * 16 + g) * KSTR + k8 + t4;
                int rB = rA + 8 * KSTR;
                uint32_t ah[4], al[4];
                split2(Asmp[rA],     ah[0], al[0]);
                split2(Asmp[rB],     ah[1], al[1]);
                split2(Asmp[rA + 4], ah[2], al[2]);
                split2(Asmp[rB + 4], ah[3], al[3]);
                #pragma unroll
                for (int nt = 0; nt < 4; nt++) mma_tf32(acc[mt][nt], ah, bhf[nt]);
                #pragma unroll
                for (int nt = 0; nt < 4; nt++) mma_tf32(acc[mt][nt], ah, blf[nt]);
                #pragma unroll
                for (int nt = 0; nt < 4; nt++) mma_tf32(acc[mt][nt], al, bhf[nt]);
            }
        }

        if (more) {
            float* nb = sm + ((ks + 1) & 1) * PSTAGEF;
            __syncthreads();
            *(float4*)(nb + so0) = va0;
            *(float4*)(nb + so1) = va1;
            *(float4*)(nb + sob) = vb0;
            __syncthreads();
        }
    }

    #pragma unroll
    for (int mt = 0; mt < 2; mt++) {
        int r0r = row0 + warp_m * 32 + mt * 16 + g;
        int r1r = r0r + 8;
        #pragma unroll
        for (int nt = 0; nt < 4; nt++) {
            int c = warp_n * 32 + nt * 8 + 2 * t4;
            *(float2*)(g_ao + ((size_t)b_ * Ll + r0r) * Dd + h_ * DVv + c) =
                make_float2(acc[mt][nt][0], acc[mt][nt][1]);
            *(float2*)(g_ao + ((size_t)b_ * Ll + r1r) * Dd + h_ * DVv + c) =
                make_float2(acc[mt][nt][2], acc[mt][nt][3]);
        }
    }
}

// ---------------- block reduction helper ----------------
__device__ __forceinline__ float blkred(float v, bool ismax, float* sred) {
    #pragma unroll
    for (int o = 16; o; o >>= 1) {
        float w = __shfl_xor_sync(0xffffffffu, v, o);
        v = ismax ? fmaxf(v, w) : v + w;
    }
    int wid = threadIdx.x >> 5, lid = threadIdx.x & 31;
    int nw = blockDim.x >> 5;
    if (lid == 0) sred[wid] = v;
    __syncthreads();
    if (wid == 0) {
        v = (lid < nw) ? sred[lid] : (ismax ? -3.402823e38f : 0.f);
        #pragma unroll
        for (int o = 16; o; o >>= 1) {
            float w = __shfl_xor_sync(0xffffffffu, v, o);
            v = ismax ? fmaxf(v, w) : v + w;
        }
        if (lid == 0) sred[0] = v;
    }
    __syncthreads();
    float r = sred[0];
    __syncthreads();
    return r;
}

// ---------------- fast branchless lgamma ----------------
__device__ __forceinline__ float lgamma_fast(float x) {
    bool refl = (x < 0.5f);
    float z = refl ? 1.0f - x : x;
    float p = 1.0f;
    #pragma unroll
    for (int i = 0; i < 8; i++) {
        if (z < 8.0f) { p *= z; z += 1.0f; }
    }
    float invz  = 1.0f / z;
    float invz2 = invz * invz;
    float lz = __logf(z);
    float lg = (z - 0.5f) * lz - z + 0.91893853320467274f
             + invz * (8.3333333333e-2f
             + invz2 * (-2.7777777778e-3f + 7.9365079365e-4f * invz2));
    lg -= __logf(p);
    if (refl) {
        float s = sinpif(x);
        lg = 1.1447298858494002f - __logf(fabsf(s)) - lg;
    }
    return lg;
}

// ---------------- alpha softmax + per-(b,h) KL constant terms ----------------
__global__ __launch_bounds__(512) void alpha_kernel() {
    __shared__ float sred[32];
    int bh = blockIdx.x;
    int t = threadIdx.x;
    float x = g_dotg[bh * Ll + t];
    float m = blkred(x, true, sred);
    float e = expf(x - m);
    float den = blkred(e, false, sred);
    float a = e / den;
    g_alpha[bh * Ll + t] = a;
    const float lg1 = 0.69314718f;
    const float EG  = 0.5772156649f;
    float C = a * lg1 + 2.f * EG * a + lgammaf(a + EPSF);
    float sc = blkred(C, false, sred);
    if (t == 0) atomicAdd(&g_kl, (double)(512.0f * sc));
}

// ---------------- fused row pass: warp per row, 2 live arrays ----------------
__global__ __launch_bounds__(256) void row_fused(const float* __restrict__ U) {
    int lane = threadIdx.x & 31;
    int wrp = threadIdx.x >> 5;
    int row = blockIdx.x * 8 + wrp;
    int bh = row >> 9;
    size_t base = (size_t)row * 512;

    float s[16];
    float m = -3.402823e38f;
    #pragma unroll
    for (int i = 0; i < 16; i++) {
        s[i] = g_S[base + lane + 32 * i];
        m = fmaxf(m, s[i]);
    }
    #pragma unroll
    for (int o = 16; o; o >>= 1) m = fmaxf(m, __shfl_xor_sync(0xffffffffu, m, o));

    float den = 0.f;
    #pragma unroll
    for (int i = 0; i < 16; i++) den += __expf(s[i] - m);
    #pragma unroll
    for (int o = 16; o; o >>= 1) den += __shfl_xor_sync(0xffffffffu, den, o);
    float logden = __logf(den);

    float t[16];
    float kl = 0.f;
    #pragma unroll
    for (int i = 0; i < 16; i++) {
        float r = s[i] - m - logden;
        float p = __expf(r);
        float lp = (r > -41.4f) ? r : __logf(p + EPSF);
        float a = g_alpha[bh * 512 + lane + 32 * i];
        kl += fmaf(-a, lp, p);
        float u = U[base + lane + 32 * i];
        // -log(1-u+EPS): series (relative-accurate) for small u, fast log otherwise
        float ws = u * (1.f + u * (0.5f + 0.33333333f * u));
        float wl = -__logf(1.f - u + EPSF);
        float w = (u < 0.015f) ? ws : wl;
        float gw = __logf(w + EPSF);
        t[i] = lp - lgamma_fast(3.f + 2.f * gw);
    }

    float m2 = -3.402823e38f;
    #pragma unroll
    for (int i = 0; i < 16; i++) m2 = fmaxf(m2, t[i]);
    #pragma unroll
    for (int o = 16; o; o >>= 1) m2 = fmaxf(m2, __shfl_xor_sync(0xffffffffu, m2, o));

    float d2 = 0.f;
    #pragma unroll
    for (int i = 0; i < 16; i++) d2 += __expf(t[i] - m2);
    #pragma unroll
    for (int o = 16; o; o >>= 1) d2 += __shfl_xor_sync(0xffffffffu, d2, o);
    float i2 = 1.f / d2;

    #pragma unroll
    for (int i = 0; i < 16; i++)
        g_S[base + lane + 32 * i] = __expf(t[i] - m2) * i2;

    #pragma unroll
    for (int o = 16; o; o >>= 1) kl += __shfl_xor_sync(0xffffffffu, kl, o);
    if (lane == 0) atomicAdd(&g_kl, (double)kl);
}

// ---------------- misc ----------------
__global__ void zero_kernel() { g_kl = 0.0; }

__global__ void finalize_kernel(float* out, int out_size) {
    if (out_size > Bb * Ll * Dd)
        out[Bb * Ll * Dd] = (float)(g_kl / 33554432.0);
}

// ---------------- launch ----------------
extern "C" void kernel_launch(void* const* d_in, const int* in_sizes, int n_in,
                              void* d_out, int out_size) {
    const float* queries = (const float*)d_in[0];
    const float* keys    = (const float*)d_in[1];
    const float* values  = (const float*)d_in[2];
    const float* unif    = (const float*)d_in[3];
    const float* Wq = (const float*)d_in[4];
    const float* bq = (const float*)d_in[5];
    const float* Wk = (const float*)d_in[6];
    const float* bk = (const float*)d_in[7];
    const float* Wv = (const float*)d_in[8];
    const float* bv = (const float*)d_in[9];
    const float* Wo = (const float*)d_in[10];
    const float* bo = (const float*)d_in[11];
    const float* Wp1 = (const float*)d_in[12];
    const float* bp1 = (const float*)d_in[13];
    const float* Wp2 = (const float*)d_in[14];
    const float* bp2 = (const float*)d_in[15];
    float* out = (float*)d_out;

    float *pq, *pk, *pv_, *pao, *pwt;
    cudaGetSymbolAddress((void**)&pq, g_q);
    cudaGetSymbolAddress((void**)&pk, g_k);
    cudaGetSymbolAddress((void**)&pv_, g_v);
    cudaGetSymbolAddress((void**)&pao, g_ao);
    cudaGetSymbolAddress((void**)&pwt, g_wt);

    const int GSMEM = 2 * STAGEF * 4;    // 40960 B
    const int PSMEM = 2 * PSTAGEF * 4;   // 29696 B
    static int smem_set = 0;
    if (!smem_set) {
        cudaFuncSetAttribute(mma_gemm, cudaFuncAttributeMaxDynamicSharedMemorySize, GSMEM);
        cudaFuncSetAttribute(score_mma, cudaFuncAttributeMaxDynamicSharedMemorySize, GSMEM);
        cudaFuncSetAttribute(prior_mma, cudaFuncAttributeMaxDynamicSharedMemorySize, GSMEM);
        cudaFuncSetAttribute(pv_mma, cudaFuncAttributeMaxDynamicSharedMemorySize, PSMEM);
        smem_set = 1;
    }

    zero_kernel<<<1, 1>>>();

    dim3 gmm(8, 32);
    dim3 tr(32, 8);

    // Q projection (scale 8 = sqrt(DK))
    transpose_k<<<dim3(32, 32), tr>>>(Wq, pwt, 1024, 1024);
    mma_gemm<<<gmm, 256, GSMEM>>>(queries, pwt, bq, pq, 1, 8.0f);

    // K projection
    transpose_k<<<dim3(32, 32), tr>>>(Wk, pwt, 1024, 1024);
    mma_gemm<<<gmm, 256, GSMEM>>>(keys, pwt, bk, pk, 1, 1.0f);

    // V projection
    transpose_k<<<dim3(32, 32), tr>>>(Wv, pwt, 1024, 1024);
    mma_gemm<<<gmm, 256, GSMEM>>>(values, pwt, bv, pv_, 1, 1.0f);

    // prior MLP (needs g_k)
    transpose_k<<<dim3(32, 2), tr>>>(Wp1, pwt, 64, 1024);
    prior_mma<<<dim3(8, 512), 256, GSMEM>>>(pwt, bp1, Wp2);
    combine_dotg<<<256, 256>>>(bp2);
    alpha_kernel<<<BH, 512>>>();

    score_mma<<<dim3(4, 4, BH), 256, GSMEM>>>();
    row_fused<<<NPOS / 8, 256>>>(unif);
    pv_mma<<<dim3(4, BH), 256, PSMEM>>>();

    // out projection
    transpose_k<<<dim3(32, 32), tr>>>(Wo, pwt, 1024, 1024);
    mma_gemm<<<gmm, 256, GSMEM>>>(pao, pwt, bo, out, 0, 1.0f);

    finalize_kernel<<<1, 1>>>(out, out_size);
}

// round 9
// speedup vs baseline: 1.4908x; 1.0230x over previous
#include <cuda_runtime.h>
#include <math.h>
#include <stdint.h>

#define Bb 8
#define Ll 512
#define Dd 1024
#define Hh 16
#define DKk 64
#define DVv 64
#define EPSF 1e-20f

#define BH (Bb*Hh)           // 128
#define NPOS (Bb*Hh*Ll)      // 65536
#define MROWS (Bb*Ll)        // 4096

// ---------------- scratch ----------------
__device__ float g_q[NPOS*DKk];
__device__ float g_k[NPOS*DKk];
__device__ float g_v[NPOS*DVv];
__device__ float g_S[(size_t)BH*Ll*Ll];
__device__ float g_ao[MROWS*Dd];
__device__ float g_pp[(size_t)32*NPOS];
__device__ float g_dotg[NPOS];
__device__ float g_alpha[NPOS];
__device__ double g_kl;
__device__ float g_wt[4*Dd*Dd];          // W^T for Wq,Wk,Wv,Wo
__device__ float g_wtp[DKk*Dd];          // Wp1^T [1024,64]

// ---------------- helpers ----------------
__device__ __forceinline__ void mma_tf32(float* c, const uint32_t* a, const uint32_t* b) {
    asm volatile(
        "mma.sync.aligned.m16n8k8.row.col.f32.tf32.tf32.f32 "
        "{%0,%1,%2,%3}, {%4,%5,%6,%7}, {%8,%9}, {%0,%1,%2,%3};"
        : "+f"(c[0]), "+f"(c[1]), "+f"(c[2]), "+f"(c[3])
        : "r"(a[0]), "r"(a[1]), "r"(a[2]), "r"(a[3]), "r"(b[0]), "r"(b[1]));
}

__device__ __forceinline__ void split2(float x, uint32_t& h, uint32_t& l) {
    uint32_t xb = __float_as_uint(x);
    h = xb & 0xFFFFE000u;
    l = __float_as_uint(x - __uint_as_float(h));
}

__device__ __forceinline__ void cp16(uint32_t s, const void* g) {
    asm volatile("cp.async.ca.shared.global [%0], [%1], 16;" :: "r"(s), "l"(g));
}
#define CP_COMMIT() asm volatile("cp.async.commit_group;" ::: "memory")
#define CP_WAIT1()  asm volatile("cp.async.wait_group 1;" ::: "memory")

// batched 32x32-tiled transposes of the 4 big weights [1024,1024]
__global__ void transpose4(const float* __restrict__ W0, const float* __restrict__ W1,
                           const float* __restrict__ W2, const float* __restrict__ W3) {
    __shared__ float t[32][33];
    int z = blockIdx.z;
    const float* W = (z == 0) ? W0 : (z == 1) ? W1 : (z == 2) ? W2 : W3;
    float* T = g_wt + (size_t)z * Dd * Dd;
    int bx = blockIdx.x * 32, by = blockIdx.y * 32;
    int tx = threadIdx.x, ty = threadIdx.y;     // 32 x 8
    #pragma unroll
    for (int j = 0; j < 4; j++)
        t[ty + 8 * j][tx] = W[(size_t)(by + ty + 8 * j) * 1024 + bx + tx];
    __syncthreads();
    #pragma unroll
    for (int j = 0; j < 4; j++)
        T[(size_t)(bx + ty + 8 * j) * 1024 + by + tx] = t[tx][ty + 8 * j];
}

// Wp1 [64,1024] -> Wp1^T [1024,64]
__global__ void transpose_p(const float* __restrict__ W) {
    __shared__ float t[32][33];
    int bx = blockIdx.x * 32, by = blockIdx.y * 32;
    int tx = threadIdx.x, ty = threadIdx.y;
    #pragma unroll
    for (int j = 0; j < 4; j++)
        t[ty + 8 * j][tx] = W[(size_t)(by + ty + 8 * j) * 1024 + bx + tx];
    __syncthreads();
    #pragma unroll
    for (int j = 0; j < 4; j++)
        g_wtp[(size_t)(bx + ty + 8 * j) * 64 + by + tx] = t[tx][ty + 8 * j];
}

// ---------------- 3xTF32 GEMM core, cp.async 3-stage ring (K=1024) ----------------
#define KB 16
#define KSTR 20
#define MATF 2560
#define STAGEF 5120
#define NPIPE 3

__device__ __forceinline__ void gemm_core(const float* A, const float* Bt,
                                          const float* bias, float* C,
                                          int scatter, float scale, float* sm) {
    int tid = threadIdx.x;
    int lane = tid & 31, wid = tid >> 5;
    int g = lane >> 2, t4 = lane & 3;
    int warp_m = wid & 1;
    int warp_n = wid >> 1;
    int row0 = blockIdx.y * 128;
    int col0 = blockIdx.x * 128;

    float acc[4][4][4];
    #pragma unroll
    for (int mt = 0; mt < 4; mt++)
        #pragma unroll
        for (int nt = 0; nt < 4; nt++)
            #pragma unroll
            for (int q = 0; q < 4; q++) acc[mt][nt][q] = 0.f;

    int r0i = tid >> 2, s0i = tid & 3;
    const float* pA0 = A  + (size_t)(row0 + r0i) * 1024 + s0i * 4;
    const float* pA1 = A  + (size_t)(row0 + 64 + r0i) * 1024 + s0i * 4;
    const float* pB0 = Bt + (size_t)(col0 + r0i) * 1024 + s0i * 4;
    const float* pB1 = Bt + (size_t)(col0 + 64 + r0i) * 1024 + s0i * 4;
    uint32_t smb = (uint32_t)__cvta_generic_to_shared(sm);
    uint32_t ad0 = smb + (r0i * KSTR + s0i * 4) * 4;
    uint32_t ad1 = smb + ((r0i + 64) * KSTR + s0i * 4) * 4;

    const int NSTAGE = 1024 / KB;      // 64

    // prologue: stages 0,1
    #pragma unroll
    for (int st = 0; st < 2; st++) {
        uint32_t b = (uint32_t)(st * STAGEF * 4);
        int k0 = st * KB;
        cp16(ad0 + b, pA0 + k0);
        cp16(ad1 + b, pA1 + k0);
        cp16(ad0 + b + MATF * 4, pB0 + k0);
        cp16(ad1 + b + MATF * 4, pB1 + k0);
        CP_COMMIT();
    }

    for (int ks = 0; ks < NSTAGE; ks++) {
        CP_WAIT1();
        __syncthreads();
        int buf = ks % NPIPE;
        const float* Asmp = sm + buf * STAGEF + warp_m * 64 * KSTR;
        const float* Bsmp = sm + buf * STAGEF + MATF + warp_n * 32 * KSTR;

        #pragma unroll
        for (int step = 0; step < 2; step++) {
            int k8 = step * 8;
            uint32_t bhf[4][2], blf[4][2];
            #pragma unroll
            for (int nt = 0; nt < 4; nt++) {
                int rN = (nt * 8 + g) * KSTR + k8 + t4;
                split2(Bsmp[rN],     bhf[nt][0], blf[nt][0]);
                split2(Bsmp[rN + 4], bhf[nt][1], blf[nt][1]);
            }
            #pragma unroll
            for (int mt = 0; mt < 4; mt++) {
                int rA = (mt * 16 + g) * KSTR + k8 + t4;
                int rB = rA + 8 * KSTR;
                uint32_t ah[4], al[4];
                split2(Asmp[rA],     ah[0], al[0]);
                split2(Asmp[rB],     ah[1], al[1]);
                split2(Asmp[rA + 4], ah[2], al[2]);
                split2(Asmp[rB + 4], ah[3], al[3]);
                #pragma unroll
                for (int nt = 0; nt < 4; nt++) mma_tf32(acc[mt][nt], ah, bhf[nt]);
                #pragma unroll
                for (int nt = 0; nt < 4; nt++) mma_tf32(acc[mt][nt], ah, blf[nt]);
                #pragma unroll
                for (int nt = 0; nt < 4; nt++) mma_tf32(acc[mt][nt], al, bhf[nt]);
            }
        }

        int ns = ks + 2;
        if (ns < NSTAGE) {
            uint32_t b = (uint32_t)((ns % NPIPE) * STAGEF * 4);
            int k0 = ns * KB;
            cp16(ad0 + b, pA0 + k0);
            cp16(ad1 + b, pA1 + k0);
            cp16(ad0 + b + MATF * 4, pB0 + k0);
            cp16(ad1 + b + MATF * 4, pB1 + k0);
        }
        CP_COMMIT();
    }

    #pragma unroll
    for (int mt = 0; mt < 4; mt++) {
        int r0r = row0 + warp_m * 64 + mt * 16 + g;
        int r1r = r0r + 8;
        #pragma unroll
        for (int nt = 0; nt < 4; nt++) {
            int c = col0 + warp_n * 32 + nt * 8 + 2 * t4;
            float b0 = __ldg(bias + c), b1 = __ldg(bias + c + 1);
            float2 v0 = make_float2((acc[mt][nt][0] + b0) * scale,
                                    (acc[mt][nt][1] + b1) * scale);
            float2 v1 = make_float2((acc[mt][nt][2] + b0) * scale,
                                    (acc[mt][nt][3] + b1) * scale);
            if (scatter) {
                int h_ = c >> 6, d_ = c & 63;
                int b0_ = r0r >> 9, l0_ = r0r & 511;
                int b1_ = r1r >> 9, l1_ = r1r & 511;
                *(float2*)(C + (((size_t)(b0_ * Hh + h_) * Ll) + l0_) * 64 + d_) = v0;
                *(float2*)(C + (((size_t)(b1_ * Hh + h_) * Ll) + l1_) * 64 + d_) = v1;
            } else {
                *(float2*)(C + (size_t)r0r * 1024 + c) = v0;
                *(float2*)(C + (size_t)r1r * 1024 + c) = v1;
            }
        }
    }
}

// merged Q/K/V projections (z selects), scatter to head layout
__global__ __launch_bounds__(256, 2) void qkv_mma(const float* __restrict__ Aq,
                                                  const float* __restrict__ Ak,
                                                  const float* __restrict__ Av,
                                                  const float* __restrict__ bq,
                                                  const float* __restrict__ bk,
                                                  const float* __restrict__ bv,
                                                  float* __restrict__ Cq,
                                                  float* __restrict__ Ck,
                                                  float* __restrict__ Cv) {
    extern __shared__ float sm[];
    int z = blockIdx.z;
    const float* A    = (z == 0) ? Aq : (z == 1) ? Ak : Av;
    const float* bias = (z == 0) ? bq : (z == 1) ? bk : bv;
    float* C          = (z == 0) ? Cq : (z == 1) ? Ck : Cv;
    const float* Bt   = g_wt + (size_t)z * Dd * Dd;
    float scale       = (z == 0) ? 8.0f : 1.0f;
    gemm_core(A, Bt, bias, C, 1, scale, sm);
}

// out projection
__global__ __launch_bounds__(256, 2) void out_mma(const float* __restrict__ bias,
                                                  float* __restrict__ C) {
    extern __shared__ float sm[];
    gemm_core(g_ao, g_wt + (size_t)3 * Dd * Dd, bias, C, 0, 1.0f, sm);
}

// ---------------- 3xTF32 batched QK^T (double-buffered, K=64) ----------------
__global__ __launch_bounds__(256, 2) void score_mma() {
    extern __shared__ float sm[];
    int bh = blockIdx.z;
    const float* A  = g_q + (size_t)bh * Ll * DKk;
    const float* Bt = g_k + (size_t)bh * Ll * DKk;
    float* Sp = g_S + (size_t)bh * Ll * Ll;
    int tid = threadIdx.x;
    int lane = tid & 31, wid = tid >> 5;
    int g = lane >> 2, t4 = lane & 3;
    int warp_m = wid & 1;
    int warp_n = wid >> 1;
    int row0 = blockIdx.y * 128;
    int col0 = blockIdx.x * 128;

    float acc[4][4][4];
    #pragma unroll
    for (int mt = 0; mt < 4; mt++)
        #pragma unroll
        for (int nt = 0; nt < 4; nt++)
            #pragma unroll
            for (int q = 0; q < 4; q++) acc[mt][nt][q] = 0.f;

    int r0i = tid >> 2, s0i = tid & 3;
    const float* pA0 = A  + (size_t)(row0 + r0i) * 64 + s0i * 4;
    const float* pA1 = A  + (size_t)(row0 + 64 + r0i) * 64 + s0i * 4;
    const float* pB0 = Bt + (size_t)(col0 + r0i) * 64 + s0i * 4;
    const float* pB1 = Bt + (size_t)(col0 + 64 + r0i) * 64 + s0i * 4;
    int so0 = r0i * KSTR + s0i * 4;
    int so1 = (r0i + 64) * KSTR + s0i * 4;

    *(float4*)(sm + so0)        = *(const float4*)(pA0);
    *(float4*)(sm + so1)        = *(const float4*)(pA1);
    *(float4*)(sm + MATF + so0) = *(const float4*)(pB0);
    *(float4*)(sm + MATF + so1) = *(const float4*)(pB1);
    __syncthreads();

    const int NSTAGE = 64 / KB;    // 4
    for (int ks = 0; ks < NSTAGE; ks++) {
        int buf = ks & 1;
        float4 va0, va1, vb0, vb1;
        bool more = (ks + 1 < NSTAGE);
        if (more) {
            int k0 = (ks + 1) * KB;
            va0 = *(const float4*)(pA0 + k0);
            va1 = *(const float4*)(pA1 + k0);
            vb0 = *(const float4*)(pB0 + k0);
            vb1 = *(const float4*)(pB1 + k0);
        }

        const float* Asmp = sm + buf * STAGEF + warp_m * 64 * KSTR;
        const float* Bsmp = sm + buf * STAGEF + MATF + warp_n * 32 * KSTR;

        #pragma unroll
        for (int step = 0; step < 2; step++) {
            int k8 = step * 8;
            uint32_t bhf[4][2], blf[4][2];
            #pragma unroll
            for (int nt = 0; nt < 4; nt++) {
                int rN = (nt * 8 + g) * KSTR + k8 + t4;
                split2(Bsmp[rN],     bhf[nt][0], blf[nt][0]);
                split2(Bsmp[rN + 4], bhf[nt][1], blf[nt][1]);
            }
            #pragma unroll
            for (int mt = 0; mt < 4; mt++) {
                int rA = (mt * 16 + g) * KSTR + k8 + t4;
                int rB = rA + 8 * KSTR;
                uint32_t ah[4], al[4];
                split2(Asmp[rA],     ah[0], al[0]);
                split2(Asmp[rB],     ah[1], al[1]);
                split2(Asmp[rA + 4], ah[2], al[2]);
                split2(Asmp[rB + 4], ah[3], al[3]);
                #pragma unroll
                for (int nt = 0; nt < 4; nt++) mma_tf32(acc[mt][nt], ah, bhf[nt]);
                #pragma unroll
                for (int nt = 0; nt < 4; nt++) mma_tf32(acc[mt][nt], ah, blf[nt]);
                #pragma unroll
                for (int nt = 0; nt < 4; nt++) mma_tf32(acc[mt][nt], al, bhf[nt]);
            }
        }

        if (more) {
            float* nb = sm + ((ks + 1) & 1) * STAGEF;
            __syncthreads();
            *(float4*)(nb + so0)        = va0;
            *(float4*)(nb + so1)        = va1;
            *(float4*)(nb + MATF + so0) = vb0;
            *(float4*)(nb + MATF + so1) = vb1;
            __syncthreads();
        }
    }

    #pragma unroll
    for (int mt = 0; mt < 4; mt++) {
        int r0r = row0 + warp_m * 64 + mt * 16 + g;
        int r1r = r0r + 8;
        #pragma unroll
        for (int nt = 0; nt < 4; nt++) {
            int c = col0 + warp_n * 32 + nt * 8 + 2 * t4;
            *(float2*)(Sp + (size_t)r0r * 512 + c) = make_float2(acc[mt][nt][0], acc[mt][nt][1]);
            *(float2*)(Sp + (size_t)r1r * 512 + c) = make_float2(acc[mt][nt][2], acc[mt][nt][3]);
        }
    }
}

// ---------------- 3xTF32 prior MLP (double-buffered, K=64) ----------------
__global__ __launch_bounds__(256, 2) void prior_mma(const float* __restrict__ bp1,
                                                    const float* __restrict__ Wp2)
{
    extern __shared__ float sm[];
    const float* A = g_k;
    const float* Bt = g_wtp;
    int tid = threadIdx.x;
    int lane = tid & 31, wid = tid >> 5;
    int g = lane >> 2, t4 = lane & 3;
    int warp_m = wid & 1;
    int warp_n = wid >> 1;
    int row0 = blockIdx.y * 128;
    int col0 = blockIdx.x * 128;

    float acc[4][4][4];
    #pragma unroll
    for (int mt = 0; mt < 4; mt++)
        #pragma unroll
        for (int nt = 0; nt < 4; nt++)
            #pragma unroll
            for (int q = 0; q < 4; q++) acc[mt][nt][q] = 0.f;

    int r0i = tid >> 2, s0i = tid & 3;
    const float* pA0 = A  + (size_t)(row0 + r0i) * 64 + s0i * 4;
    const float* pA1 = A  + (size_t)(row0 + 64 + r0i) * 64 + s0i * 4;
    const float* pB0 = Bt + (size_t)(col0 + r0i) * 64 + s0i * 4;
    const float* pB1 = Bt + (size_t)(col0 + 64 + r0i) * 64 + s0i * 4;
    int so0 = r0i * KSTR + s0i * 4;
    int so1 = (r0i + 64) * KSTR + s0i * 4;

    *(float4*)(sm + so0)        = *(const float4*)(pA0);
    *(float4*)(sm + so1)        = *(const float4*)(pA1);
    *(float4*)(sm + MATF + so0) = *(const float4*)(pB0);
    *(float4*)(sm + MATF + so1) = *(const float4*)(pB1);
    __syncthreads();

    const int NSTAGE = 64 / KB;    // 4
    for (int ks = 0; ks < NSTAGE; ks++) {
        int buf = ks & 1;
        float4 va0, va1, vb0, vb1;
        bool more = (ks + 1 < NSTAGE);
        if (more) {
            int k0 = (ks + 1) * KB;
            va0 = *(const float4*)(pA0 + k0);
            va1 = *(const float4*)(pA1 + k0);
            vb0 = *(const float4*)(pB0 + k0);
            vb1 = *(const float4*)(pB1 + k0);
        }

        const float* Asmp = sm + buf * STAGEF + warp_m * 64 * KSTR;
        const float* Bsmp = sm + buf * STAGEF + MATF + warp_n * 32 * KSTR;

        #pragma unroll
        for (int step = 0; step < 2; step++) {
            int k8 = step * 8;
            uint32_t bhf[4][2], blf[4][2];
            #pragma unroll
            for (int nt = 0; nt < 4; nt++) {
                int rN = (nt * 8 + g) * KSTR + k8 + t4;
                split2(Bsmp[rN],     bhf[nt][0], blf[nt][0]);
                split2(Bsmp[rN + 4], bhf[nt][1], blf[nt][1]);
            }
            #pragma unroll
            for (int mt = 0; mt < 4; mt++) {
                int rA = (mt * 16 + g) * KSTR + k8 + t4;
                int rB = rA + 8 * KSTR;
                uint32_t ah[4], al[4];
                split2(Asmp[rA],     ah[0], al[0]);
                split2(Asmp[rB],     ah[1], al[1]);
                split2(Asmp[rA + 4], ah[2], al[2]);
                split2(Asmp[rB + 4], ah[3], al[3]);
                #pragma unroll
                for (int nt = 0; nt < 4; nt++) mma_tf32(acc[mt][nt], ah, bhf[nt]);
                #pragma unroll
                for (int nt = 0; nt < 4; nt++) mma_tf32(acc[mt][nt], ah, blf[nt]);
                #pragma unroll
                for (int nt = 0; nt < 4; nt++) mma_tf32(acc[mt][nt], al, bhf[nt]);
            }
        }

        if (more) {
            float* nb = sm + ((ks + 1) & 1) * STAGEF;
            __syncthreads();
            *(float4*)(nb + so0)        = va0;
            *(float4*)(nb + so1)        = va1;
            *(float4*)(nb + MATF + so0) = vb0;
            *(float4*)(nb + MATF + so1) = vb1;
            __syncthreads();
        }
    }

    size_t grp = (size_t)(blockIdx.x * 4 + warp_n) * NPOS;
    #pragma unroll
    for (int mt = 0; mt < 4; mt++) {
        float rs0 = 0.f, rs1 = 0.f;
        #pragma unroll
        for (int nt = 0; nt < 4; nt++) {
            int c = col0 + warp_n * 32 + nt * 8 + 2 * t4;
            float b0 = __ldg(bp1 + c), b1 = __ldg(bp1 + c + 1);
            float w0 = __ldg(Wp2 + c), w1 = __ldg(Wp2 + c + 1);
            float hv;
            hv = acc[mt][nt][0] + b0; hv = (hv >= 0.f) ? hv : 0.01f * hv; rs0 = fmaf(hv, w0, rs0);
            hv = acc[mt][nt][1] + b1; hv = (hv >= 0.f) ? hv : 0.01f * hv; rs0 = fmaf(hv, w1, rs0);
            hv = acc[mt][nt][2] + b0; hv = (hv >= 0.f) ? hv : 0.01f * hv; rs1 = fmaf(hv, w0, rs1);
            hv = acc[mt][nt][3] + b1; hv = (hv >= 0.f) ? hv : 0.01f * hv; rs1 = fmaf(hv, w1, rs1);
        }
        rs0 += __shfl_xor_sync(0xffffffffu, rs0, 1);
        rs0 += __shfl_xor_sync(0xffffffffu, rs0, 2);
        rs1 += __shfl_xor_sync(0xffffffffu, rs1, 1);
        rs1 += __shfl_xor_sync(0xffffffffu, rs1, 2);
        if (t4 == 0) {
            int r0r = row0 + warp_m * 64 + mt * 16 + g;
            g_pp[grp + r0r]     = rs0;
            g_pp[grp + r0r + 8] = rs1;
        }
    }
}

__global__ void combine_dotg(const float* __restrict__ bp2) {
    int i = blockIdx.x * 256 + threadIdx.x;
    float s = 0.f;
    #pragma unroll
    for (int t = 0; t < 32; t++) s += g_pp[(size_t)t * NPOS + i];
    g_dotg[i] = s + bp2[0];
}

// ---------------- 3xTF32 att_s @ V, cp.async 3-stage ----------------
#define VSTR 72
#define PAF 2560
#define PBF (16*VSTR)
#define PSTAGEF (PAF + PBF)
__global__ __launch_bounds__(256, 2) void pv_mma() {
    extern __shared__ float sm[];
    int bh = blockIdx.y;
    int b_ = bh >> 4, h_ = bh & 15;
    const float* A  = g_S + (size_t)bh * Ll * Ll;
    const float* Bv = g_v + (size_t)bh * Ll * DVv;
    int tid = threadIdx.x;
    int lane = tid & 31, wid = tid >> 5;
    int g = lane >> 2, t4 = lane & 3;
    int warp_m = wid & 3;
    int warp_n = wid >> 2;
    int row0 = blockIdx.x * 128;

    float acc[2][4][4];
    #pragma unroll
    for (int mt = 0; mt < 2; mt++)
        #pragma unroll
        for (int nt = 0; nt < 4; nt++)
            #pragma unroll
            for (int q = 0; q < 4; q++) acc[mt][nt][q] = 0.f;

    int r0i = tid >> 2, s0i = tid & 3;
    const float* pA0 = A + (size_t)(row0 + r0i) * 512 + s0i * 4;
    const float* pA1 = A + (size_t)(row0 + 64 + r0i) * 512 + s0i * 4;
    int rowb = tid >> 4, segb = tid & 15;
    const float* pBv = Bv + (size_t)rowb * 64 + segb * 4;
    uint32_t smb = (uint32_t)__cvta_generic_to_shared(sm);
    uint32_t ad0 = smb + (r0i * KSTR + s0i * 4) * 4;
    uint32_t ad1 = smb + ((r0i + 64) * KSTR + s0i * 4) * 4;
    uint32_t adb = smb + (PAF + rowb * VSTR + segb * 4) * 4;

    const int NSTAGE = 512 / KB;   // 32

    #pragma unroll
    for (int st = 0; st < 2; st++) {
        uint32_t b = (uint32_t)(st * PSTAGEF * 4);
        int k0 = st * KB;
        cp16(ad0 + b, pA0 + k0);
        cp16(ad1 + b, pA1 + k0);
        cp16(adb + b, pBv + (size_t)k0 * 64);
        CP_COMMIT();
    }

    for (int ks = 0; ks < NSTAGE; ks++) {
        CP_WAIT1();
        __syncthreads();
        int buf = ks % NPIPE;
        const float* Asmp = sm + buf * PSTAGEF + warp_m * 32 * KSTR;
        const float* Bsmp = sm + buf * PSTAGEF + PAF;

        #pragma unroll
        for (int step = 0; step < 2; step++) {
            int k8 = step * 8;
            uint32_t bhf[4][2], blf[4][2];
            #pragma unroll
            for (int nt = 0; nt < 4; nt++) {
                int col = warp_n * 32 + nt * 8 + g;
                split2(Bsmp[(k8 + t4) * VSTR + col],     bhf[nt][0], blf[nt][0]);
                split2(Bsmp[(k8 + t4 + 4) * VSTR + col], bhf[nt][1], blf[nt][1]);
            }
            #pragma unroll
            for (int mt = 0; mt < 2; mt++) {
                int rA = (mt * 16 + g) * KSTR + k8 + t4;
                int rB = rA + 8 * KSTR;
                uint32_t ah[4], al[4];
                split2(Asmp[rA],     ah[0], al[0]);
                split2(Asmp[rB],     ah[1], al[1]);
                split2(Asmp[rA + 4], ah[2], al[2]);
                split2(Asmp[rB + 4], ah[3], al[3]);
                #pragma unroll
                for (int nt = 0; nt < 4; nt++) mma_tf32(acc[mt][nt], ah, bhf[nt]);
                #pragma unroll
                for (int nt = 0; nt < 4; nt++) mma_tf32(acc[mt][nt], ah, blf[nt]);
                #pragma unroll
                for (int nt = 0; nt < 4; nt++) mma_tf32(acc[mt][nt], al, bhf[nt]);
            }
        }

        int ns = ks + 2;
        if (ns < NSTAGE) {
            uint32_t b = (uint32_t)((ns % NPIPE) * PSTAGEF * 4);
            int k0 = ns * KB;
            cp16(ad0 + b, pA0 + k0);
            cp16(ad1 + b, pA1 + k0);
            cp16(adb + b, pBv + (size_t)k0 * 64);
        }
        CP_COMMIT();
    }

    #pragma unroll
    for (int mt = 0; mt < 2; mt++) {
        int r0r = row0 + warp_m * 32 + mt * 16 + g;
        int r1r = r0r + 8;
        #pragma unroll
        for (int nt = 0; nt < 4; nt++) {
            int c = warp_n * 32 + nt * 8 + 2 * t4;
            *(float2*)(g_ao + ((size_t)b_ * Ll + r0r) * Dd + h_ * DVv + c) =
                make_float2(acc[mt][nt][0], acc[mt][nt][1]);
            *(float2*)(g_ao + ((size_t)b_ * Ll + r1r) * Dd + h_ * DVv + c) =
                make_float2(acc[mt][nt][2], acc[mt][nt][3]);
        }
    }
}

// ---------------- block reduction helper ----------------
__device__ __forceinline__ float blkred(float v, bool ismax, float* sred) {
    #pragma unroll
    for (int o = 16; o; o >>= 1) {
        float w = __shfl_xor_sync(0xffffffffu, v, o);
        v = ismax ? fmaxf(v, w) : v + w;
    }
    int wid = threadIdx.x >> 5, lid = threadIdx.x & 31;
    int nw = blockDim.x >> 5;
    if (lid == 0) sred[wid] = v;
    __syncthreads();
    if (wid == 0) {
        v = (lid < nw) ? sred[lid] : (ismax ? -3.402823e38f : 0.f);
        #pragma unroll
        for (int o = 16; o; o >>= 1) {
            float w = __shfl_xor_sync(0xffffffffu, v, o);
            v = ismax ? fmaxf(v, w) : v + w;
        }
        if (lid == 0) sred[0] = v;
    }
    __syncthreads();
    float r = sred[0];
    __syncthreads();
    return r;
}

// ---------------- fast branchless lgamma ----------------
__device__ __forceinline__ float lgamma_fast(float x) {
    bool refl = (x < 0.5f);
    float z = refl ? 1.0f - x : x;
    float p = 1.0f;
    #pragma unroll
    for (int i = 0; i < 8; i++) {
        if (z < 8.0f) { p *= z; z += 1.0f; }
    }
    float invz  = 1.0f / z;
    float invz2 = invz * invz;
    float lz = __logf(z);
    float lg = (z - 0.5f) * lz - z + 0.91893853320467274f
             + invz * (8.3333333333e-2f
             + invz2 * (-2.7777777778e-3f + 7.9365079365e-4f * invz2));
    lg -= __logf(p);
    if (refl) {
        float s = sinpif(x);
        lg = 1.1447298858494002f - __logf(fabsf(s)) - lg;
    }
    return lg;
}

// ---------------- alpha softmax + per-(b,h) KL constant terms ----------------
__global__ __launch_bounds__(512) void alpha_kernel() {
    __shared__ float sred[32];
    int bh = blockIdx.x;
    int t = threadIdx.x;
    float x = g_dotg[bh * Ll + t];
    float m = blkred(x, true, sred);
    float e = expf(x - m);
    float den = blkred(e, false, sred);
    float a = e / den;
    g_alpha[bh * Ll + t] = a;
    const float lg1 = 0.69314718f;
    const float EG  = 0.5772156649f;
    float C = a * lg1 + 2.f * EG * a + lgammaf(a + EPSF);
    float sc = blkred(C, false, sred);
    if (t == 0) atomicAdd(&g_kl, (double)(512.0f * sc));
}

// ---------------- fused row pass: warp per row ----------------
__global__ __launch_bounds__(256) void row_fused(const float* __restrict__ U) {
    int lane = threadIdx.x & 31;
    int wrp = threadIdx.x >> 5;
    int row = blockIdx.x * 8 + wrp;
    int bh = row >> 9;
    size_t base = (size_t)row * 512;

    float s[16];
    float m = -3.402823e38f;
    #pragma unroll
    for (int i = 0; i < 16; i++) {
        s[i] = g_S[base + lane + 32 * i];
        m = fmaxf(m, s[i]);
    }
    #pragma unroll
    for (int o = 16; o; o >>= 1) m = fmaxf(m, __shfl_xor_sync(0xffffffffu, m, o));

    float den = 0.f;
    #pragma unroll
    for (int i = 0; i < 16; i++) den += __expf(s[i] - m);
    #pragma unroll
    for (int o = 16; o; o >>= 1) den += __shfl_xor_sync(0xffffffffu, den, o);
    float logden = __logf(den);

    float t[16];
    float kl = 0.f;
    #pragma unroll
    for (int i = 0; i < 16; i++) {
        float r = s[i] - m - logden;
        float p = __expf(r);
        float lp = (r > -41.4f) ? r : __logf(p + EPSF);
        float a = g_alpha[bh * 512 + lane + 32 * i];
        kl += fmaf(-a, lp, p);
        float u = U[base + lane + 32 * i];
        float ws = u * (1.f + u * (0.5f + 0.33333333f * u));
        float wl = -__logf(1.f - u + EPSF);
        float w = (u < 0.015f) ? ws : wl;
        float gw = __logf(w + EPSF);
        t[i] = lp - lgamma_fast(3.f + 2.f * gw);
    }

    float m2 = -3.402823e38f;
    #pragma unroll
    for (int i = 0; i < 16; i++) m2 = fmaxf(m2, t[i]);
    #pragma unroll
    for (int o = 16; o; o >>= 1) m2 = fmaxf(m2, __shfl_xor_sync(0xffffffffu, m2, o));

    float d2 = 0.f;
    #pragma unroll
    for (int i = 0; i < 16; i++) d2 += __expf(t[i] - m2);
    #pragma unroll
    for (int o = 16; o; o >>= 1) d2 += __shfl_xor_sync(0xffffffffu, d2, o);
    float i2 = 1.f / d2;

    #pragma unroll
    for (int i = 0; i < 16; i++)
        g_S[base + lane + 32 * i] = __expf(t[i] - m2) * i2;

    #pragma unroll
    for (int o = 16; o; o >>= 1) kl += __shfl_xor_sync(0xffffffffu, kl, o);
    if (lane == 0) atomicAdd(&g_kl, (double)kl);
}

// ---------------- misc ----------------
__global__ void zero_kernel() { g_kl = 0.0; }

__global__ void finalize_kernel(float* out, int out_size) {
    if (out_size > Bb * Ll * Dd)
        out[Bb * Ll * Dd] = (float)(g_kl / 33554432.0);
}

// ---------------- launch ----------------
extern "C" void kernel_launch(void* const* d_in, const int* in_sizes, int n_in,
                              void* d_out, int out_size) {
    const float* queries = (const float*)d_in[0];
    const float* keys    = (const float*)d_in[1];
    const float* values  = (const float*)d_in[2];
    const float* unif    = (const float*)d_in[3];
    const float* Wq = (const float*)d_in[4];
    const float* bq = (const float*)d_in[5];
    const float* Wk = (const float*)d_in[6];
    const float* bk = (const float*)d_in[7];
    const float* Wv = (const float*)d_in[8];
    const float* bv = (const float*)d_in[9];
    const float* Wo = (const float*)d_in[10];
    const float* bo = (const float*)d_in[11];
    const float* Wp1 = (const float*)d_in[12];
    const float* bp1 = (const float*)d_in[13];
    const float* Wp2 = (const float*)d_in[14];
    const float* bp2 = (const float*)d_in[15];
    float* out = (float*)d_out;

    float *pq, *pk, *pv_;
    cudaGetSymbolAddress((void**)&pq, g_q);
    cudaGetSymbolAddress((void**)&pk, g_k);
    cudaGetSymbolAddress((void**)&pv_, g_v);

    const int GSMEM  = NPIPE * STAGEF * 4;    // 61440 B
    const int DBSMEM = 2 * STAGEF * 4;        // 40960 B
    const int PSMEM  = NPIPE * PSTAGEF * 4;   // 44544 B
    static int smem_set = 0;
    if (!smem_set) {
        cudaFuncSetAttribute(qkv_mma, cudaFuncAttributeMaxDynamicSharedMemorySize, GSMEM);
        cudaFuncSetAttribute(out_mma, cudaFuncAttributeMaxDynamicSharedMemorySize, GSMEM);
        cudaFuncSetAttribute(score_mma, cudaFuncAttributeMaxDynamicSharedMemorySize, DBSMEM);
        cudaFuncSetAttribute(prior_mma, cudaFuncAttributeMaxDynamicSharedMemorySize, DBSMEM);
        cudaFuncSetAttribute(pv_mma, cudaFuncAttributeMaxDynamicSharedMemorySize, PSMEM);
        smem_set = 1;
    }

    zero_kernel<<<1, 1>>>();

    dim3 tr(32, 8);
    transpose4<<<dim3(32, 32, 4), tr>>>(Wq, Wk, Wv, Wo);
    transpose_p<<<dim3(32, 2), tr>>>(Wp1);

    qkv_mma<<<dim3(8, 32, 3), 256, GSMEM>>>(queries, keys, values, bq, bk, bv, pq, pk, pv_);

    prior_mma<<<dim3(8, 512), 256, DBSMEM>>>(bp1, Wp2);
    combine_dotg<<<256, 256>>>(bp2);
    alpha_kernel<<<BH, 512>>>();

    score_mma<<<dim3(4, 4, BH), 256, DBSMEM>>>();
    row_fused<<<NPOS / 8, 256>>>(unif);
    pv_mma<<<dim3(4, BH), 256, PSMEM>>>();

    out_mma<<<dim3(8, 32), 256, GSMEM>>>(bo, out);

    finalize_kernel<<<1, 1>>>(out, out_size);
}

// round 10
// speedup vs baseline: 1.5887x; 1.0657x over previous
#include <cuda_runtime.h>
#include <math.h>
#include <stdint.h>

#define Bb 8
#define Ll 512
#define Dd 1024
#define Hh 16
#define DKk 64
#define DVv 64
#define EPSF 1e-20f

#define BH (Bb*Hh)           // 128
#define NPOS (Bb*Hh*Ll)      // 65536
#define MROWS (Bb*Ll)        // 4096

// ---------------- scratch ----------------
__device__ float g_q[NPOS*DKk];
__device__ float g_k[NPOS*DKk];
__device__ float g_v[NPOS*DVv];
__device__ float g_S[(size_t)BH*Ll*Ll];
__device__ float g_ao[MROWS*Dd];
__device__ float g_pp[(size_t)32*NPOS];
__device__ float g_dotg[NPOS];
__device__ float g_alpha[NPOS];
__device__ double g_kl;
__device__ float g_wt[4*Dd*Dd];          // W^T for Wq,Wk,Wv,Wo
__device__ float g_wtp[DKk*Dd];          // Wp1^T [1024,64]

// ---------------- helpers ----------------
__device__ __forceinline__ void mma_tf32(float* c, const uint32_t* a, const uint32_t* b) {
    asm volatile(
        "mma.sync.aligned.m16n8k8.row.col.f32.tf32.tf32.f32 "
        "{%0,%1,%2,%3}, {%4,%5,%6,%7}, {%8,%9}, {%0,%1,%2,%3};"
        : "+f"(c[0]), "+f"(c[1]), "+f"(c[2]), "+f"(c[3])
        : "r"(a[0]), "r"(a[1]), "r"(a[2]), "r"(a[3]), "r"(b[0]), "r"(b[1]));
}

__device__ __forceinline__ void mma_bf16(float* c, const uint32_t* a, const uint32_t* b) {
    asm volatile(
        "mma.sync.aligned.m16n8k16.row.col.f32.bf16.bf16.f32 "
        "{%0,%1,%2,%3}, {%4,%5,%6,%7}, {%8,%9}, {%0,%1,%2,%3};"
        : "+f"(c[0]), "+f"(c[1]), "+f"(c[2]), "+f"(c[3])
        : "r"(a[0]), "r"(a[1]), "r"(a[2]), "r"(a[3]), "r"(b[0]), "r"(b[1]));
}

// tf32 split (hi truncated to tf32 bits, lo exact residual)
__device__ __forceinline__ void split2(float x, uint32_t& h, uint32_t& l) {
    uint32_t xb = __float_as_uint(x);
    h = xb & 0xFFFFE000u;
    l = __float_as_uint(x - __uint_as_float(h));
}

// bf16 pair split: pack (x0,x1) hi-bf16s into hi, residual-bf16s into lo
__device__ __forceinline__ void splitpair(float x0, float x1, uint32_t& hi, uint32_t& lo) {
    uint32_t b0 = __float_as_uint(x0), b1 = __float_as_uint(x1);
    hi = __byte_perm(b0, b1, 0x7632);
    float l0 = x0 - __uint_as_float(b0 & 0xFFFF0000u);
    float l1 = x1 - __uint_as_float(b1 & 0xFFFF0000u);
    lo = __byte_perm(__float_as_uint(l0), __float_as_uint(l1), 0x7632);
}

__device__ __forceinline__ void cp16(uint32_t s, const void* g) {
    asm volatile("cp.async.ca.shared.global [%0], [%1], 16;" :: "r"(s), "l"(g));
}
#define CP_COMMIT() asm volatile("cp.async.commit_group;" ::: "memory")
#define CP_WAIT1()  asm volatile("cp.async.wait_group 1;" ::: "memory")

// batched 32x32-tiled transposes of the 4 big weights [1024,1024]
__global__ void transpose4(const float* __restrict__ W0, const float* __restrict__ W1,
                           const float* __restrict__ W2, const float* __restrict__ W3) {
    __shared__ float t[32][33];
    int z = blockIdx.z;
    const float* W = (z == 0) ? W0 : (z == 1) ? W1 : (z == 2) ? W2 : W3;
    float* T = g_wt + (size_t)z * Dd * Dd;
    int bx = blockIdx.x * 32, by = blockIdx.y * 32;
    int tx = threadIdx.x, ty = threadIdx.y;
    #pragma unroll
    for (int j = 0; j < 4; j++)
        t[ty + 8 * j][tx] = W[(size_t)(by + ty + 8 * j) * 1024 + bx + tx];
    __syncthreads();
    #pragma unroll
    for (int j = 0; j < 4; j++)
        T[(size_t)(bx + ty + 8 * j) * 1024 + by + tx] = t[tx][ty + 8 * j];
}

__global__ void transpose_p(const float* __restrict__ W) {
    __shared__ float t[32][33];
    int bx = blockIdx.x * 32, by = blockIdx.y * 32;
    int tx = threadIdx.x, ty = threadIdx.y;
    #pragma unroll
    for (int j = 0; j < 4; j++)
        t[ty + 8 * j][tx] = W[(size_t)(by + ty + 8 * j) * 1024 + bx + tx];
    __syncthreads();
    #pragma unroll
    for (int j = 0; j < 4; j++)
        g_wtp[(size_t)(bx + ty + 8 * j) * 64 + by + tx] = t[tx][ty + 8 * j];
}

// ---------------- GEMM core, cp.async 3-stage ring (K=1024), tf32x3 or bf16x3 ----------------
#define KB 16
#define KSTR 20
#define MATF 2560
#define STAGEF 5120
#define NPIPE 3

template<int BF16>
__device__ __forceinline__ void gemm_core(const float* A, const float* Bt,
                                          const float* bias, float* C,
                                          int scatter, float scale, float* sm) {
    int tid = threadIdx.x;
    int lane = tid & 31, wid = tid >> 5;
    int g = lane >> 2, t4 = lane & 3;
    int warp_m = wid & 1;
    int warp_n = wid >> 1;
    int row0 = blockIdx.y * 128;
    int col0 = blockIdx.x * 128;

    float acc[4][4][4];
    #pragma unroll
    for (int mt = 0; mt < 4; mt++)
        #pragma unroll
        for (int nt = 0; nt < 4; nt++)
            #pragma unroll
            for (int q = 0; q < 4; q++) acc[mt][nt][q] = 0.f;

    int r0i = tid >> 2, s0i = tid & 3;
    const float* pA0 = A  + (size_t)(row0 + r0i) * 1024 + s0i * 4;
    const float* pA1 = A  + (size_t)(row0 + 64 + r0i) * 1024 + s0i * 4;
    const float* pB0 = Bt + (size_t)(col0 + r0i) * 1024 + s0i * 4;
    const float* pB1 = Bt + (size_t)(col0 + 64 + r0i) * 1024 + s0i * 4;
    uint32_t smb = (uint32_t)__cvta_generic_to_shared(sm);
    uint32_t ad0 = smb + (r0i * KSTR + s0i * 4) * 4;
    uint32_t ad1 = smb + ((r0i + 64) * KSTR + s0i * 4) * 4;

    const int NSTAGE = 1024 / KB;      // 64

    #pragma unroll
    for (int st = 0; st < 2; st++) {
        uint32_t b = (uint32_t)(st * STAGEF * 4);
        int k0 = st * KB;
        cp16(ad0 + b, pA0 + k0);
        cp16(ad1 + b, pA1 + k0);
        cp16(ad0 + b + MATF * 4, pB0 + k0);
        cp16(ad1 + b + MATF * 4, pB1 + k0);
        CP_COMMIT();
    }

    for (int ks = 0; ks < NSTAGE; ks++) {
        CP_WAIT1();
        __syncthreads();
        int buf = ks % NPIPE;
        const float* Asmp = sm + buf * STAGEF + warp_m * 64 * KSTR;
        const float* Bsmp = sm + buf * STAGEF + MATF + warp_n * 32 * KSTR;

        if (BF16) {
            // one k16 bf16x3 block
            uint32_t bhf[4][2], blf[4][2];
            #pragma unroll
            for (int nt = 0; nt < 4; nt++) {
                const float* bp = Bsmp + (nt * 8 + g) * KSTR + 2 * t4;
                float2 p0 = *(const float2*)bp;
                float2 p1 = *(const float2*)(bp + 8);
                splitpair(p0.x, p0.y, bhf[nt][0], blf[nt][0]);
                splitpair(p1.x, p1.y, bhf[nt][1], blf[nt][1]);
            }
            #pragma unroll
            for (int mt = 0; mt < 4; mt++) {
                const float* ap = Asmp + (mt * 16 + g) * KSTR + 2 * t4;
                float2 q0 = *(const float2*)ap;
                float2 q1 = *(const float2*)(ap + 8 * KSTR);
                float2 q2 = *(const float2*)(ap + 8);
                float2 q3 = *(const float2*)(ap + 8 * KSTR + 8);
                uint32_t ah[4], al[4];
                splitpair(q0.x, q0.y, ah[0], al[0]);
                splitpair(q1.x, q1.y, ah[1], al[1]);
                splitpair(q2.x, q2.y, ah[2], al[2]);
                splitpair(q3.x, q3.y, ah[3], al[3]);
                #pragma unroll
                for (int nt = 0; nt < 4; nt++) mma_bf16(acc[mt][nt], ah, bhf[nt]);
                #pragma unroll
                for (int nt = 0; nt < 4; nt++) mma_bf16(acc[mt][nt], ah, blf[nt]);
                #pragma unroll
                for (int nt = 0; nt < 4; nt++) mma_bf16(acc[mt][nt], al, bhf[nt]);
            }
        } else {
            // two k8 tf32x3 steps
            #pragma unroll
            for (int step = 0; step < 2; step++) {
                int k8 = step * 8;
                uint32_t bhf[4][2], blf[4][2];
                #pragma unroll
                for (int nt = 0; nt < 4; nt++) {
                    int rN = (nt * 8 + g) * KSTR + k8 + t4;
                    split2(Bsmp[rN],     bhf[nt][0], blf[nt][0]);
                    split2(Bsmp[rN + 4], bhf[nt][1], blf[nt][1]);
                }
                #pragma unroll
                for (int mt = 0; mt < 4; mt++) {
                    int rA = (mt * 16 + g) * KSTR + k8 + t4;
                    int rB = rA + 8 * KSTR;
                    uint32_t ah[4], al[4];
                    split2(Asmp[rA],     ah[0], al[0]);
                    split2(Asmp[rB],     ah[1], al[1]);
                    split2(Asmp[rA + 4], ah[2], al[2]);
                    split2(Asmp[rB + 4], ah[3], al[3]);
                    #pragma unroll
                    for (int nt = 0; nt < 4; nt++) mma_tf32(acc[mt][nt], ah, bhf[nt]);
                    #pragma unroll
                    for (int nt = 0; nt < 4; nt++) mma_tf32(acc[mt][nt], ah, blf[nt]);
                    #pragma unroll
                    for (int nt = 0; nt < 4; nt++) mma_tf32(acc[mt][nt], al, bhf[nt]);
                }
            }
        }

        int ns = ks + 2;
        if (ns < NSTAGE) {
            uint32_t b = (uint32_t)((ns % NPIPE) * STAGEF * 4);
            int k0 = ns * KB;
            cp16(ad0 + b, pA0 + k0);
            cp16(ad1 + b, pA1 + k0);
            cp16(ad0 + b + MATF * 4, pB0 + k0);
            cp16(ad1 + b + MATF * 4, pB1 + k0);
        }
        CP_COMMIT();
    }

    #pragma unroll
    for (int mt = 0; mt < 4; mt++) {
        int r0r = row0 + warp_m * 64 + mt * 16 + g;
        int r1r = r0r + 8;
        #pragma unroll
        for (int nt = 0; nt < 4; nt++) {
            int c = col0 + warp_n * 32 + nt * 8 + 2 * t4;
            float b0 = __ldg(bias + c), b1 = __ldg(bias + c + 1);
            float2 v0 = make_float2((acc[mt][nt][0] + b0) * scale,
                                    (acc[mt][nt][1] + b1) * scale);
            float2 v1 = make_float2((acc[mt][nt][2] + b0) * scale,
                                    (acc[mt][nt][3] + b1) * scale);
            if (scatter) {
                int h_ = c >> 6, d_ = c & 63;
                int b0_ = r0r >> 9, l0_ = r0r & 511;
                int b1_ = r1r >> 9, l1_ = r1r & 511;
                *(float2*)(C + (((size_t)(b0_ * Hh + h_) * Ll) + l0_) * 64 + d_) = v0;
                *(float2*)(C + (((size_t)(b1_ * Hh + h_) * Ll) + l1_) * 64 + d_) = v1;
            } else {
                *(float2*)(C + (size_t)r0r * 1024 + c) = v0;
                *(float2*)(C + (size_t)r1r * 1024 + c) = v1;
            }
        }
    }
}

// Q,K projections: tf32x3 (score path is softmax-sensitive)
__global__ __launch_bounds__(256, 2) void qk_mma(const float* __restrict__ Aq,
                                                 const float* __restrict__ Ak,
                                                 const float* __restrict__ bq,
                                                 const float* __restrict__ bk,
                                                 float* __restrict__ Cq,
                                                 float* __restrict__ Ck) {
    extern __shared__ float sm[];
    int z = blockIdx.z;
    gemm_core<0>((z == 0) ? Aq : Ak, g_wt + (size_t)z * Dd * Dd,
                 (z == 0) ? bq : bk, (z == 0) ? Cq : Ck, 1,
                 (z == 0) ? 8.0f : 1.0f, sm);
}

// V projection: bf16x3 (linear error path)
__global__ __launch_bounds__(256, 2) void v_mma(const float* __restrict__ Av,
                                                const float* __restrict__ bv,
                                                float* __restrict__ Cv) {
    extern __shared__ float sm[];
    gemm_core<1>(Av, g_wt + (size_t)2 * Dd * Dd, bv, Cv, 1, 1.0f, sm);
}

// out projection: bf16x3
__global__ __launch_bounds__(256, 2) void out_mma(const float* __restrict__ bias,
                                                  float* __restrict__ C) {
    extern __shared__ float sm[];
    gemm_core<1>(g_ao, g_wt + (size_t)3 * Dd * Dd, bias, C, 0, 1.0f, sm);
}

// ---------------- tf32x3 batched QK^T (double-buffered, K=64) ----------------
__global__ __launch_bounds__(256, 2) void score_mma() {
    extern __shared__ float sm[];
    int bh = blockIdx.z;
    const float* A  = g_q + (size_t)bh * Ll * DKk;
    const float* Bt = g_k + (size_t)bh * Ll * DKk;
    float* Sp = g_S + (size_t)bh * Ll * Ll;
    int tid = threadIdx.x;
    int lane = tid & 31, wid = tid >> 5;
    int g = lane >> 2, t4 = lane & 3;
    int warp_m = wid & 1;
    int warp_n = wid >> 1;
    int row0 = blockIdx.y * 128;
    int col0 = blockIdx.x * 128;

    float acc[4][4][4];
    #pragma unroll
    for (int mt = 0; mt < 4; mt++)
        #pragma unroll
        for (int nt = 0; nt < 4; nt++)
            #pragma unroll
            for (int q = 0; q < 4; q++) acc[mt][nt][q] = 0.f;

    int r0i = tid >> 2, s0i = tid & 3;
    const float* pA0 = A  + (size_t)(row0 + r0i) * 64 + s0i * 4;
    const float* pA1 = A  + (size_t)(row0 + 64 + r0i) * 64 + s0i * 4;
    const float* pB0 = Bt + (size_t)(col0 + r0i) * 64 + s0i * 4;
    const float* pB1 = Bt + (size_t)(col0 + 64 + r0i) * 64 + s0i * 4;
    int so0 = r0i * KSTR + s0i * 4;
    int so1 = (r0i + 64) * KSTR + s0i * 4;

    *(float4*)(sm + so0)        = *(const float4*)(pA0);
    *(float4*)(sm + so1)        = *(const float4*)(pA1);
    *(float4*)(sm + MATF + so0) = *(const float4*)(pB0);
    *(float4*)(sm + MATF + so1) = *(const float4*)(pB1);
    __syncthreads();

    const int NSTAGE = 64 / KB;    // 4
    for (int ks = 0; ks < NSTAGE; ks++) {
        int buf = ks & 1;
        float4 va0, va1, vb0, vb1;
        bool more = (ks + 1 < NSTAGE);
        if (more) {
            int k0 = (ks + 1) * KB;
            va0 = *(const float4*)(pA0 + k0);
            va1 = *(const float4*)(pA1 + k0);
            vb0 = *(const float4*)(pB0 + k0);
            vb1 = *(const float4*)(pB1 + k0);
        }

        const float* Asmp = sm + buf * STAGEF + warp_m * 64 * KSTR;
        const float* Bsmp = sm + buf * STAGEF + MATF + warp_n * 32 * KSTR;

        #pragma unroll
        for (int step = 0; step < 2; step++) {
            int k8 = step * 8;
            uint32_t bhf[4][2], blf[4][2];
            #pragma unroll
            for (int nt = 0; nt < 4; nt++) {
                int rN = (nt * 8 + g) * KSTR + k8 + t4;
                split2(Bsmp[rN],     bhf[nt][0], blf[nt][0]);
                split2(Bsmp[rN + 4], bhf[nt][1], blf[nt][1]);
            }
            #pragma unroll
            for (int mt = 0; mt < 4; mt++) {
                int rA = (mt * 16 + g) * KSTR + k8 + t4;
                int rB = rA + 8 * KSTR;
                uint32_t ah[4], al[4];
                split2(Asmp[rA],     ah[0], al[0]);
                split2(Asmp[rB],     ah[1], al[1]);
                split2(Asmp[rA + 4], ah[2], al[2]);
                split2(Asmp[rB + 4], ah[3], al[3]);
                #pragma unroll
                for (int nt = 0; nt < 4; nt++) mma_tf32(acc[mt][nt], ah, bhf[nt]);
                #pragma unroll
                for (int nt = 0; nt < 4; nt++) mma_tf32(acc[mt][nt], ah, blf[nt]);
                #pragma unroll
                for (int nt = 0; nt < 4; nt++) mma_tf32(acc[mt][nt], al, bhf[nt]);
            }
        }

        if (more) {
            float* nb = sm + ((ks + 1) & 1) * STAGEF;
            __syncthreads();
            *(float4*)(nb + so0)        = va0;
            *(float4*)(nb + so1)        = va1;
            *(float4*)(nb + MATF + so0) = vb0;
            *(float4*)(nb + MATF + so1) = vb1;
            __syncthreads();
        }
    }

    #pragma unroll
    for (int mt = 0; mt < 4; mt++) {
        int r0r = row0 + warp_m * 64 + mt * 16 + g;
        int r1r = r0r + 8;
        #pragma unroll
        for (int nt = 0; nt < 4; nt++) {
            int c = col0 + warp_n * 32 + nt * 8 + 2 * t4;
            *(float2*)(Sp + (size_t)r0r * 512 + c) = make_float2(acc[mt][nt][0], acc[mt][nt][1]);
            *(float2*)(Sp + (size_t)r1r * 512 + c) = make_float2(acc[mt][nt][2], acc[mt][nt][3]);
        }
    }
}

// ---------------- bf16x3 prior MLP (double-buffered, K=64) ----------------
__global__ __launch_bounds__(256, 2) void prior_mma(const float* __restrict__ bp1,
                                                    const float* __restrict__ Wp2)
{
    extern __shared__ float sm[];
    const float* A = g_k;
    const float* Bt = g_wtp;
    int tid = threadIdx.x;
    int lane = tid & 31, wid = tid >> 5;
    int g = lane >> 2, t4 = lane & 3;
    int warp_m = wid & 1;
    int warp_n = wid >> 1;
    int row0 = blockIdx.y * 128;
    int col0 = blockIdx.x * 128;

    float acc[4][4][4];
    #pragma unroll
    for (int mt = 0; mt < 4; mt++)
        #pragma unroll
        for (int nt = 0; nt < 4; nt++)
            #pragma unroll
            for (int q = 0; q < 4; q++) acc[mt][nt][q] = 0.f;

    int r0i = tid >> 2, s0i = tid & 3;
    const float* pA0 = A  + (size_t)(row0 + r0i) * 64 + s0i * 4;
    const float* pA1 = A  + (size_t)(row0 + 64 + r0i) * 64 + s0i * 4;
    const float* pB0 = Bt + (size_t)(col0 + r0i) * 64 + s0i * 4;
    const float* pB1 = Bt + (size_t)(col0 + 64 + r0i) * 64 + s0i * 4;
    int so0 = r0i * KSTR + s0i * 4;
    int so1 = (r0i + 64) * KSTR + s0i * 4;

    *(float4*)(sm + so0)        = *(const float4*)(pA0);
    *(float4*)(sm + so1)        = *(const float4*)(pA1);
    *(float4*)(sm + MATF + so0) = *(const float4*)(pB0);
    *(float4*)(sm + MATF + so1) = *(const float4*)(pB1);
    __syncthreads();

    const int NSTAGE = 64 / KB;    // 4
    for (int ks = 0; ks < NSTAGE; ks++) {
        int buf = ks & 1;
        float4 va0, va1, vb0, vb1;
        bool more = (ks + 1 < NSTAGE);
        if (more) {
            int k0 = (ks + 1) * KB;
            va0 = *(const float4*)(pA0 + k0);
            va1 = *(const float4*)(pA1 + k0);
            vb0 = *(const float4*)(pB0 + k0);
            vb1 = *(const float4*)(pB1 + k0);
        }

        const float* Asmp = sm + buf * STAGEF + warp_m * 64 * KSTR;
        const float* Bsmp = sm + buf * STAGEF + MATF + warp_n * 32 * KSTR;

        {
            uint32_t bhf[4][2], blf[4][2];
            #pragma unroll
            for (int nt = 0; nt < 4; nt++) {
                const float* bp = Bsmp + (nt * 8 + g) * KSTR + 2 * t4;
                float2 p0 = *(const float2*)bp;
                float2 p1 = *(const float2*)(bp + 8);
                splitpair(p0.x, p0.y, bhf[nt][0], blf[nt][0]);
                splitpair(p1.x, p1.y, bhf[nt][1], blf[nt][1]);
            }
            #pragma unroll
            for (int mt = 0; mt < 4; mt++) {
                const float* ap = Asmp + (mt * 16 + g) * KSTR + 2 * t4;
                float2 q0 = *(const float2*)ap;
                float2 q1 = *(const float2*)(ap + 8 * KSTR);
                float2 q2 = *(const float2*)(ap + 8);
                float2 q3 = *(const float2*)(ap + 8 * KSTR + 8);
                uint32_t ah[4], al[4];
                splitpair(q0.x, q0.y, ah[0], al[0]);
                splitpair(q1.x, q1.y, ah[1], al[1]);
                splitpair(q2.x, q2.y, ah[2], al[2]);
                splitpair(q3.x, q3.y, ah[3], al[3]);
                #pragma unroll
                for (int nt = 0; nt < 4; nt++) mma_bf16(acc[mt][nt], ah, bhf[nt]);
                #pragma unroll
                for (int nt = 0; nt < 4; nt++) mma_bf16(acc[mt][nt], ah, blf[nt]);
                #pragma unroll
                for (int nt = 0; nt < 4; nt++) mma_bf16(acc[mt][nt], al, bhf[nt]);
            }
        }

        if (more) {
            float* nb = sm + ((ks + 1) & 1) * STAGEF;
            __syncthreads();
            *(float4*)(nb + so0)        = va0;
            *(float4*)(nb + so1)        = va1;
            *(float4*)(nb + MATF + so0) = vb0;
            *(float4*)(nb + MATF + so1) = vb1;
            __syncthreads();
        }
    }

    size_t grp = (size_t)(blockIdx.x * 4 + warp_n) * NPOS;
    #pragma unroll
    for (int mt = 0; mt < 4; mt++) {
        float rs0 = 0.f, rs1 = 0.f;
        #pragma unroll
        for (int nt = 0; nt < 4; nt++) {
            int c = col0 + warp_n * 32 + nt * 8 + 2 * t4;
            float b0 = __ldg(bp1 + c), b1 = __ldg(bp1 + c + 1);
            float w0 = __ldg(Wp2 + c), w1 = __ldg(Wp2 + c + 1);
            float hv;
            hv = acc[mt][nt][0] + b0; hv = (hv >= 0.f) ? hv : 0.01f * hv; rs0 = fmaf(hv, w0, rs0);
            hv = acc[mt][nt][1] + b1; hv = (hv >= 0.f) ? hv : 0.01f * hv; rs0 = fmaf(hv, w1, rs0);
            hv = acc[mt][nt][2] + b0; hv = (hv >= 0.f) ? hv : 0.01f * hv; rs1 = fmaf(hv, w0, rs1);
            hv = acc[mt][nt][3] + b1; hv = (hv >= 0.f) ? hv : 0.01f * hv; rs1 = fmaf(hv, w1, rs1);
        }
        rs0 += __shfl_xor_sync(0xffffffffu, rs0, 1);
        rs0 += __shfl_xor_sync(0xffffffffu, rs0, 2);
        rs1 += __shfl_xor_sync(0xffffffffu, rs1, 1);
        rs1 += __shfl_xor_sync(0xffffffffu, rs1, 2);
        if (t4 == 0) {
            int r0r = row0 + warp_m * 64 + mt * 16 + g;
            g_pp[grp + r0r]     = rs0;
            g_pp[grp + r0r + 8] = rs1;
        }
    }
}

__global__ void combine_dotg(const float* __restrict__ bp2) {
    int i = blockIdx.x * 256 + threadIdx.x;
    float s = 0.f;
    #pragma unroll
    for (int t = 0; t < 32; t++) s += g_pp[(size_t)t * NPOS + i];
    g_dotg[i] = s + bp2[0];
}

// ---------------- bf16x3 att_s @ V, cp.async 3-stage ----------------
#define VSTR 72
#define PAF 2560
#define PBF (16*VSTR)
#define PSTAGEF (PAF + PBF)
__global__ __launch_bounds__(256, 2) void pv_mma() {
    extern __shared__ float sm[];
    int bh = blockIdx.y;
    int b_ = bh >> 4, h_ = bh & 15;
    const float* A  = g_S + (size_t)bh * Ll * Ll;
    const float* Bv = g_v + (size_t)bh * Ll * DVv;
    int tid = threadIdx.x;
    int lane = tid & 31, wid = tid >> 5;
    int g = lane >> 2, t4 = lane & 3;
    int warp_m = wid & 3;
    int warp_n = wid >> 2;
    int row0 = blockIdx.x * 128;

    float acc[2][4][4];
    #pragma unroll
    for (int mt = 0; mt < 2; mt++)
        #pragma unroll
        for (int nt = 0; nt < 4; nt++)
            #pragma unroll
            for (int q = 0; q < 4; q++) acc[mt][nt][q] = 0.f;

    int r0i = tid >> 2, s0i = tid & 3;
    const float* pA0 = A + (size_t)(row0 + r0i) * 512 + s0i * 4;
    const float* pA1 = A + (size_t)(row0 + 64 + r0i) * 512 + s0i * 4;
    int rowb = tid >> 4, segb = tid & 15;
    const float* pBv = Bv + (size_t)rowb * 64 + segb * 4;
    uint32_t smb = (uint32_t)__cvta_generic_to_shared(sm);
    uint32_t ad0 = smb + (r0i * KSTR + s0i * 4) * 4;
    uint32_t ad1 = smb + ((r0i + 64) * KSTR + s0i * 4) * 4;
    uint32_t adb = smb + (PAF + rowb * VSTR + segb * 4) * 4;

    const int NSTAGE = 512 / KB;   // 32

    #pragma unroll
    for (int st = 0; st < 2; st++) {
        uint32_t b = (uint32_t)(st * PSTAGEF * 4);
        int k0 = st * KB;
        cp16(ad0 + b, pA0 + k0);
        cp16(ad1 + b, pA1 + k0);
        cp16(adb + b, pBv + (size_t)k0 * 64);
        CP_COMMIT();
    }

    for (int ks = 0; ks < NSTAGE; ks++) {
        CP_WAIT1();
        __syncthreads();
        int buf = ks % NPIPE;
        const float* Asmp = sm + buf * PSTAGEF + warp_m * 32 * KSTR;
        const float* Bsmp = sm + buf * PSTAGEF + PAF;

        {
            uint32_t bhf[4][2], blf[4][2];
            #pragma unroll
            for (int nt = 0; nt < 4; nt++) {
                int col = warp_n * 32 + nt * 8 + g;
                float b00 = Bsmp[(2 * t4) * VSTR + col];
                float b01 = Bsmp[(2 * t4 + 1) * VSTR + col];
                float b10 = Bsmp[(2 * t4 + 8) * VSTR + col];
                float b11 = Bsmp[(2 * t4 + 9) * VSTR + col];
                splitpair(b00, b01, bhf[nt][0], blf[nt][0]);
                splitpair(b10, b11, bhf[nt][1], blf[nt][1]);
            }
            #pragma unroll
            for (int mt = 0; mt < 2; mt++) {
                const float* ap = Asmp + (mt * 16 + g) * KSTR + 2 * t4;
                float2 q0 = *(const float2*)ap;
                float2 q1 = *(const float2*)(ap + 8 * KSTR);
                float2 q2 = *(const float2*)(ap + 8);
                float2 q3 = *(const float2*)(ap + 8 * KSTR + 8);
                uint32_t ah[4], al[4];
                splitpair(q0.x, q0.y, ah[0], al[0]);
                splitpair(q1.x, q1.y, ah[1], al[1]);
                splitpair(q2.x, q2.y, ah[2], al[2]);
                splitpair(q3.x, q3.y, ah[3], al[3]);
                #pragma unroll
                for (int nt = 0; nt < 4; nt++) mma_bf16(acc[mt][nt], ah, bhf[nt]);
                #pragma unroll
                for (int nt = 0; nt < 4; nt++) mma_bf16(acc[mt][nt], ah, blf[nt]);
                #pragma unroll
                for (int nt = 0; nt < 4; nt++) mma_bf16(acc[mt][nt], al, bhf[nt]);
            }
        }

        int ns = ks + 2;
        if (ns < NSTAGE) {
            uint32_t b = (uint32_t)((ns % NPIPE) * PSTAGEF * 4);
            int k0 = ns * KB;
            cp16(ad0 + b, pA0 + k0);
            cp16(ad1 + b, pA1 + k0);
            cp16(adb + b, pBv + (size_t)k0 * 64);
        }
        CP_COMMIT();
    }

    #pragma unroll
    for (int mt = 0; mt < 2; mt++) {
        int r0r = row0 + warp_m * 32 + mt * 16 + g;
        int r1r = r0r + 8;
        #pragma unroll
        for (int nt = 0; nt < 4; nt++) {
            int c = warp_n * 32 + nt * 8 + 2 * t4;
            *(float2*)(g_ao + ((size_t)b_ * Ll + r0r) * Dd + h_ * DVv + c) =
                make_float2(acc[mt][nt][0], acc[mt][nt][1]);
            *(float2*)(g_ao + ((size_t)b_ * Ll + r1r) * Dd + h_ * DVv + c) =
                make_float2(acc[mt][nt][2], acc[mt][nt][3]);
        }
    }
}

// ---------------- block reduction helper ----------------
__device__ __forceinline__ float blkred(float v, bool ismax, float* sred) {
    #pragma unroll
    for (int o = 16; o; o >>= 1) {
        float w = __shfl_xor_sync(0xffffffffu, v, o);
        v = ismax ? fmaxf(v, w) : v + w;
    }
    int wid = threadIdx.x >> 5, lid = threadIdx.x & 31;
    int nw = blockDim.x >> 5;
    if (lid == 0) sred[wid] = v;
    __syncthreads();
    if (wid == 0) {
        v = (lid < nw) ? sred[lid] : (ismax ? -3.402823e38f : 0.f);
        #pragma unroll
        for (int o = 16; o; o >>= 1) {
            float w = __shfl_xor_sync(0xffffffffu, v, o);
            v = ismax ? fmaxf(v, w) : v + w;
        }
        if (lid == 0) sred[0] = v;
    }
    __syncthreads();
    float r = sred[0];
    __syncthreads();
    return r;
}

// ---------------- fast branchless lgamma ----------------
__device__ __forceinline__ float lgamma_fast(float x) {
    bool refl = (x < 0.5f);
    float z = refl ? 1.0f - x : x;
    float p = 1.0f;
    #pragma unroll
    for (int i = 0; i < 8; i++) {
        if (z < 8.0f) { p *= z; z += 1.0f; }
    }
    float invz  = 1.0f / z;
    float invz2 = invz * invz;
    float lz = __logf(z);
    float lg = (z - 0.5f) * lz - z + 0.91893853320467274f
             + invz * (8.3333333333e-2f
             + invz2 * (-2.7777777778e-3f + 7.9365079365e-4f * invz2));
    lg -= __logf(p);
    if (refl) {
        float s = sinpif(x);
        lg = 1.1447298858494002f - __logf(fabsf(s)) - lg;
    }
    return lg;
}

// ---------------- alpha softmax + per-(b,h) KL constant terms ----------------
__global__ __launch_bounds__(512) void alpha_kernel() {
    __shared__ float sred[32];
    int bh = blockIdx.x;
    int t = threadIdx.x;
    float x = g_dotg[bh * Ll + t];
    float m = blkred(x, true, sred);
    float e = expf(x - m);
    float den = blkred(e, false, sred);
    float a = e / den;
    g_alpha[bh * Ll + t] = a;
    const float lg1 = 0.69314718f;
    const float EG  = 0.5772156649f;
    float C = a * lg1 + 2.f * EG * a + lgammaf(a + EPSF);
    float sc = blkred(C, false, sred);
    if (t == 0) atomicAdd(&g_kl, (double)(512.0f * sc));
}

// ---------------- fused row pass: warp per row ----------------
__global__ __launch_bounds__(256) void row_fused(const float* __restrict__ U) {
    int lane = threadIdx.x & 31;
    int wrp = threadIdx.x >> 5;
    int row = blockIdx.x * 8 + wrp;
    int bh = row >> 9;
    size_t base = (size_t)row * 512;

    float s[16];
    float m = -3.402823e38f;
    #pragma unroll
    for (int i = 0; i < 16; i++) {
        s[i] = g_S[base + lane + 32 * i];
        m = fmaxf(m, s[i]);
    }
    #pragma unroll
    for (int o = 16; o; o >>= 1) m = fmaxf(m, __shfl_xor_sync(0xffffffffu, m, o));

    float den = 0.f;
    #pragma unroll
    for (int i = 0; i < 16; i++) den += __expf(s[i] - m);
    #pragma unroll
    for (int o = 16; o; o >>= 1) den += __shfl_xor_sync(0xffffffffu, den, o);
    float logden = __logf(den);

    float t[16];
    float kl = 0.f;
    #pragma unroll
    for (int i = 0; i < 16; i++) {
        float r = s[i] - m - logden;
        float p = __expf(r);
        float lp = (r > -41.4f) ? r : __logf(p + EPSF);
        float a = g_alpha[bh * 512 + lane + 32 * i];
        kl += fmaf(-a, lp, p);
        float u = U[base + lane + 32 * i];
        float ws = u * (1.f + u * (0.5f + 0.33333333f * u));
        float wl = -__logf(1.f - u + EPSF);
        float w = (u < 0.015f) ? ws : wl;
        float gw = __logf(w + EPSF);
        t[i] = lp - lgamma_fast(3.f + 2.f * gw);
    }

    float m2 = -3.402823e38f;
    #pragma unroll
    for (int i = 0; i < 16; i++) m2 = fmaxf(m2, t[i]);
    #pragma unroll
    for (int o = 16; o; o >>= 1) m2 = fmaxf(m2, __shfl_xor_sync(0xffffffffu, m2, o));

    float d2 = 0.f;
    #pragma unroll
    for (int i = 0; i < 16; i++) d2 += __expf(t[i] - m2);
    #pragma unroll
    for (int o = 16; o; o >>= 1) d2 += __shfl_xor_sync(0xffffffffu, d2, o);
    float i2 = 1.f / d2;

    #pragma unroll
    for (int i = 0; i < 16; i++)
        g_S[base + lane + 32 * i] = __expf(t[i] - m2) * i2;

    #pragma unroll
    for (int o = 16; o; o >>= 1) kl += __shfl_xor_sync(0xffffffffu, kl, o);
    if (lane == 0) atomicAdd(&g_kl, (double)kl);
}

// ---------------- misc ----------------
__global__ void zero_kernel() { g_kl = 0.0; }

__global__ void finalize_kernel(float* out, int out_size) {
    if (out_size > Bb * Ll * Dd)
        out[Bb * Ll * Dd] = (float)(g_kl / 33554432.0);
}

// ---------------- launch ----------------
extern "C" void kernel_launch(void* const* d_in, const int* in_sizes, int n_in,
                              void* d_out, int out_size) {
    const float* queries = (const float*)d_in[0];
    const float* keys    = (const float*)d_in[1];
    const float* values  = (const float*)d_in[2];
    const float* unif    = (const float*)d_in[3];
    const float* Wq = (const float*)d_in[4];
    const float* bq = (const float*)d_in[5];
    const float* Wk = (const float*)d_in[6];
    const float* bk = (const float*)d_in[7];
    const float* Wv = (const float*)d_in[8];
    const float* bv = (const float*)d_in[9];
    const float* Wo = (const float*)d_in[10];
    const float* bo = (const float*)d_in[11];
    const float* Wp1 = (const float*)d_in[12];
    const float* bp1 = (const float*)d_in[13];
    const float* Wp2 = (const float*)d_in[14];
    const float* bp2 = (const float*)d_in[15];
    float* out = (float*)d_out;

    float *pq, *pk, *pv_;
    cudaGetSymbolAddress((void**)&pq, g_q);
    cudaGetSymbolAddress((void**)&pk, g_k);
    cudaGetSymbolAddress((void**)&pv_, g_v);

    const int GSMEM  = NPIPE * STAGEF * 4;    // 61440 B
    const int DBSMEM = 2 * STAGEF * 4;        // 40960 B
    const int PSMEM  = NPIPE * PSTAGEF * 4;   // 44544 B
    static int smem_set = 0;
    if (!smem_set) {
        cudaFuncSetAttribute(qk_mma, cudaFuncAttributeMaxDynamicSharedMemorySize, GSMEM);
        cudaFuncSetAttribute(v_mma, cudaFuncAttributeMaxDynamicSharedMemorySize, GSMEM);
        cudaFuncSetAttribute(out_mma, cudaFuncAttributeMaxDynamicSharedMemorySize, GSMEM);
        cudaFuncSetAttribute(score_mma, cudaFuncAttributeMaxDynamicSharedMemorySize, DBSMEM);
        cudaFuncSetAttribute(prior_mma, cudaFuncAttributeMaxDynamicSharedMemorySize, DBSMEM);
        cudaFuncSetAttribute(pv_mma, cudaFuncAttributeMaxDynamicSharedMemorySize, PSMEM);
        smem_set = 1;
    }

    zero_kernel<<<1, 1>>>();

    dim3 tr(32, 8);
    transpose4<<<dim3(32, 32, 4), tr>>>(Wq, Wk, Wv, Wo);
    transpose_p<<<dim3(32, 2), tr>>>(Wp1);

    qk_mma<<<dim3(8, 32, 2), 256, GSMEM>>>(queries, keys, bq, bk, pq, pk);
    v_mma<<<dim3(8, 32), 256, GSMEM>>>(values, bv, pv_);

    prior_mma<<<dim3(8, 512), 256, DBSMEM>>>(bp1, Wp2);
    combine_dotg<<<256, 256>>>(bp2);
    alpha_kernel<<<BH, 512>>>();

    score_mma<<<dim3(4, 4, BH), 256, DBSMEM>>>();
    row_fused<<<NPOS / 8, 256>>>(unif);
    pv_mma<<<dim3(4, BH), 256, PSMEM>>>();

    out_mma<<<dim3(8, 32), 256, GSMEM>>>(bo, out);

    finalize_kernel<<<1, 1>>>(out, out_size);
}

// round 11
// speedup vs baseline: 1.7569x; 1.1059x over previous
#include <cuda_runtime.h>
#include <math.h>
#include <stdint.h>

#define Bb 8
#define Ll 512
#define Dd 1024
#define Hh 16
#define DKk 64
#define DVv 64
#define EPSF 1e-20f

#define BH (Bb*Hh)           // 128
#define NPOS (Bb*Hh*Ll)      // 65536
#define MROWS (Bb*Ll)        // 4096

// ---------------- scratch ----------------
__device__ float g_q[NPOS*DKk];
__device__ float g_k[NPOS*DKk];
__device__ float g_v[NPOS*DVv];
__device__ float g_S[(size_t)BH*Ll*Ll];
__device__ float g_ao[MROWS*Dd];
__device__ float g_pp[(size_t)32*NPOS];
__device__ float g_dotg[NPOS];
__device__ float g_alpha[NPOS];
__device__ double g_kl;
__device__ float g_wt[4*Dd*Dd];          // W^T for Wq,Wk,Wv,Wo
__device__ float g_wtp[DKk*Dd];          // Wp1^T [1024,64]

// ---------------- helpers ----------------
__device__ __forceinline__ void mma_bf16(float* c, const uint32_t* a, const uint32_t* b) {
    asm volatile(
        "mma.sync.aligned.m16n8k16.row.col.f32.bf16.bf16.f32 "
        "{%0,%1,%2,%3}, {%4,%5,%6,%7}, {%8,%9}, {%0,%1,%2,%3};"
        : "+f"(c[0]), "+f"(c[1]), "+f"(c[2]), "+f"(c[3])
        : "r"(a[0]), "r"(a[1]), "r"(a[2]), "r"(a[3]), "r"(b[0]), "r"(b[1]));
}

// bf16 pair split: pack (x0,x1) hi-bf16s into hi, residual-bf16s into lo
__device__ __forceinline__ void splitpair(float x0, float x1, uint32_t& hi, uint32_t& lo) {
    uint32_t b0 = __float_as_uint(x0), b1 = __float_as_uint(x1);
    hi = __byte_perm(b0, b1, 0x7632);
    float l0 = x0 - __uint_as_float(b0 & 0xFFFF0000u);
    float l1 = x1 - __uint_as_float(b1 & 0xFFFF0000u);
    lo = __byte_perm(__float_as_uint(l0), __float_as_uint(l1), 0x7632);
}

__device__ __forceinline__ void cp16(uint32_t s, const void* g) {
    asm volatile("cp.async.ca.shared.global [%0], [%1], 16;" :: "r"(s), "l"(g));
}
#define CP_COMMIT() asm volatile("cp.async.commit_group;" ::: "memory")
#define CP_WAIT1()  asm volatile("cp.async.wait_group 1;" ::: "memory")

// batched 32x32-tiled transposes of the 4 big weights [1024,1024]
__global__ void transpose4(const float* __restrict__ W0, const float* __restrict__ W1,
                           const float* __restrict__ W2, const float* __restrict__ W3) {
    __shared__ float t[32][33];
    int z = blockIdx.z;
    const float* W = (z == 0) ? W0 : (z == 1) ? W1 : (z == 2) ? W2 : W3;
    float* T = g_wt + (size_t)z * Dd * Dd;
    int bx = blockIdx.x * 32, by = blockIdx.y * 32;
    int tx = threadIdx.x, ty = threadIdx.y;
    #pragma unroll
    for (int j = 0; j < 4; j++)
        t[ty + 8 * j][tx] = W[(size_t)(by + ty + 8 * j) * 1024 + bx + tx];
    __syncthreads();
    #pragma unroll
    for (int j = 0; j < 4; j++)
        T[(size_t)(bx + ty + 8 * j) * 1024 + by + tx] = t[tx][ty + 8 * j];
}

__global__ void transpose_p(const float* __restrict__ W) {
    __shared__ float t[32][33];
    int bx = blockIdx.x * 32, by = blockIdx.y * 32;
    int tx = threadIdx.x, ty = threadIdx.y;
    #pragma unroll
    for (int j = 0; j < 4; j++)
        t[ty + 8 * j][tx] = W[(size_t)(by + ty + 8 * j) * 1024 + bx + tx];
    __syncthreads();
    #pragma unroll
    for (int j = 0; j < 4; j++)
        g_wtp[(size_t)(bx + ty + 8 * j) * 64 + by + tx] = t[tx][ty + 8 * j];
}

// ---------------- bf16x3 GEMM core, cp.async 3-stage ring (K=1024) ----------------
#define KB 16
#define KSTR 20
#define MATF 2560
#define STAGEF 5120
#define NPIPE 3

__device__ __forceinline__ void gemm_core(const float* A, const float* Bt,
                                          const float* bias, float* C,
                                          int scatter, float scale, float* sm) {
    int tid = threadIdx.x;
    int lane = tid & 31, wid = tid >> 5;
    int g = lane >> 2, t4 = lane & 3;
    int warp_m = wid & 1;
    int warp_n = wid >> 1;
    int row0 = blockIdx.y * 128;
    int col0 = blockIdx.x * 128;

    float acc[4][4][4];
    #pragma unroll
    for (int mt = 0; mt < 4; mt++)
        #pragma unroll
        for (int nt = 0; nt < 4; nt++)
            #pragma unroll
            for (int q = 0; q < 4; q++) acc[mt][nt][q] = 0.f;

    int r0i = tid >> 2, s0i = tid & 3;
    const float* pA0 = A  + (size_t)(row0 + r0i) * 1024 + s0i * 4;
    const float* pA1 = A  + (size_t)(row0 + 64 + r0i) * 1024 + s0i * 4;
    const float* pB0 = Bt + (size_t)(col0 + r0i) * 1024 + s0i * 4;
    const float* pB1 = Bt + (size_t)(col0 + 64 + r0i) * 1024 + s0i * 4;
    uint32_t smb = (uint32_t)__cvta_generic_to_shared(sm);
    uint32_t ad0 = smb + (r0i * KSTR + s0i * 4) * 4;
    uint32_t ad1 = smb + ((r0i + 64) * KSTR + s0i * 4) * 4;

    const int NSTAGE = 1024 / KB;      // 64

    #pragma unroll
    for (int st = 0; st < 2; st++) {
        uint32_t b = (uint32_t)(st * STAGEF * 4);
        int k0 = st * KB;
        cp16(ad0 + b, pA0 + k0);
        cp16(ad1 + b, pA1 + k0);
        cp16(ad0 + b + MATF * 4, pB0 + k0);
        cp16(ad1 + b + MATF * 4, pB1 + k0);
        CP_COMMIT();
    }

    for (int ks = 0; ks < NSTAGE; ks++) {
        CP_WAIT1();
        __syncthreads();
        int buf = ks % NPIPE;
        const float* Asmp = sm + buf * STAGEF + warp_m * 64 * KSTR;
        const float* Bsmp = sm + buf * STAGEF + MATF + warp_n * 32 * KSTR;

        {
            uint32_t bhf[4][2], blf[4][2];
            #pragma unroll
            for (int nt = 0; nt < 4; nt++) {
                const float* bp = Bsmp + (nt * 8 + g) * KSTR + 2 * t4;
                float2 p0 = *(const float2*)bp;
                float2 p1 = *(const float2*)(bp + 8);
                splitpair(p0.x, p0.y, bhf[nt][0], blf[nt][0]);
                splitpair(p1.x, p1.y, bhf[nt][1], blf[nt][1]);
            }
            #pragma unroll
            for (int mt = 0; mt < 4; mt++) {
                const float* ap = Asmp + (mt * 16 + g) * KSTR + 2 * t4;
                float2 q0 = *(const float2*)ap;
                float2 q1 = *(const float2*)(ap + 8 * KSTR);
                float2 q2 = *(const float2*)(ap + 8);
                float2 q3 = *(const float2*)(ap + 8 * KSTR + 8);
                uint32_t ah[4], al[4];
                splitpair(q0.x, q0.y, ah[0], al[0]);
                splitpair(q1.x, q1.y, ah[1], al[1]);
                splitpair(q2.x, q2.y, ah[2], al[2]);
                splitpair(q3.x, q3.y, ah[3], al[3]);
                #pragma unroll
                for (int nt = 0; nt < 4; nt++) mma_bf16(acc[mt][nt], ah, bhf[nt]);
                #pragma unroll
                for (int nt = 0; nt < 4; nt++) mma_bf16(acc[mt][nt], ah, blf[nt]);
                #pragma unroll
                for (int nt = 0; nt < 4; nt++) mma_bf16(acc[mt][nt], al, bhf[nt]);
            }
        }

        int ns = ks + 2;
        if (ns < NSTAGE) {
            uint32_t b = (uint32_t)((ns % NPIPE) * STAGEF * 4);
            int k0 = ns * KB;
            cp16(ad0 + b, pA0 + k0);
            cp16(ad1 + b, pA1 + k0);
            cp16(ad0 + b + MATF * 4, pB0 + k0);
            cp16(ad1 + b + MATF * 4, pB1 + k0);
        }
        CP_COMMIT();
    }

    #pragma unroll
    for (int mt = 0; mt < 4; mt++) {
        int r0r = row0 + warp_m * 64 + mt * 16 + g;
        int r1r = r0r + 8;
        #pragma unroll
        for (int nt = 0; nt < 4; nt++) {
            int c = col0 + warp_n * 32 + nt * 8 + 2 * t4;
            float b0 = __ldg(bias + c), b1 = __ldg(bias + c + 1);
            float2 v0 = make_float2((acc[mt][nt][0] + b0) * scale,
                                    (acc[mt][nt][1] + b1) * scale);
            float2 v1 = make_float2((acc[mt][nt][2] + b0) * scale,
                                    (acc[mt][nt][3] + b1) * scale);
            if (scatter) {
                int h_ = c >> 6, d_ = c & 63;
                int b0_ = r0r >> 9, l0_ = r0r & 511;
                int b1_ = r1r >> 9, l1_ = r1r & 511;
                *(float2*)(C + (((size_t)(b0_ * Hh + h_) * Ll) + l0_) * 64 + d_) = v0;
                *(float2*)(C + (((size_t)(b1_ * Hh + h_) * Ll) + l1_) * 64 + d_) = v1;
            } else {
                *(float2*)(C + (size_t)r0r * 1024 + c) = v0;
                *(float2*)(C + (size_t)r1r * 1024 + c) = v1;
            }
        }
    }
}

// merged Q/K/V projections, bf16x3
__global__ __launch_bounds__(256, 2) void qkv_mma(const float* __restrict__ Aq,
                                                  const float* __restrict__ Ak,
                                                  const float* __restrict__ Av,
                                                  const float* __restrict__ bq,
                                                  const float* __restrict__ bk,
                                                  const float* __restrict__ bv,
                                                  float* __restrict__ Cq,
                                                  float* __restrict__ Ck,
                                                  float* __restrict__ Cv) {
    extern __shared__ float sm[];
    int z = blockIdx.z;
    const float* A    = (z == 0) ? Aq : (z == 1) ? Ak : Av;
    const float* bias = (z == 0) ? bq : (z == 1) ? bk : bv;
    float* C          = (z == 0) ? Cq : (z == 1) ? Ck : Cv;
    gemm_core(A, g_wt + (size_t)z * Dd * Dd, bias, C, 1, (z == 0) ? 8.0f : 1.0f, sm);
}

// out projection, bf16x3
__global__ __launch_bounds__(256, 2) void out_mma(const float* __restrict__ bias,
                                                  float* __restrict__ C) {
    extern __shared__ float sm[];
    gemm_core(g_ao, g_wt + (size_t)3 * Dd * Dd, bias, C, 0, 1.0f, sm);
}

// ---------------- bf16x3 batched QK^T (double-buffered, K=64) ----------------
__global__ __launch_bounds__(256, 2) void score_mma() {
    extern __shared__ float sm[];
    int bh = blockIdx.z;
    const float* A  = g_q + (size_t)bh * Ll * DKk;
    const float* Bt = g_k + (size_t)bh * Ll * DKk;
    float* Sp = g_S + (size_t)bh * Ll * Ll;
    int tid = threadIdx.x;
    int lane = tid & 31, wid = tid >> 5;
    int g = lane >> 2, t4 = lane & 3;
    int warp_m = wid & 1;
    int warp_n = wid >> 1;
    int row0 = blockIdx.y * 128;
    int col0 = blockIdx.x * 128;

    float acc[4][4][4];
    #pragma unroll
    for (int mt = 0; mt < 4; mt++)
        #pragma unroll
        for (int nt = 0; nt < 4; nt++)
            #pragma unroll
            for (int q = 0; q < 4; q++) acc[mt][nt][q] = 0.f;

    int r0i = tid >> 2, s0i = tid & 3;
    const float* pA0 = A  + (size_t)(row0 + r0i) * 64 + s0i * 4;
    const float* pA1 = A  + (size_t)(row0 + 64 + r0i) * 64 + s0i * 4;
    const float* pB0 = Bt + (size_t)(col0 + r0i) * 64 + s0i * 4;
    const float* pB1 = Bt + (size_t)(col0 + 64 + r0i) * 64 + s0i * 4;
    int so0 = r0i * KSTR + s0i * 4;
    int so1 = (r0i + 64) * KSTR + s0i * 4;

    *(float4*)(sm + so0)        = *(const float4*)(pA0);
    *(float4*)(sm + so1)        = *(const float4*)(pA1);
    *(float4*)(sm + MATF + so0) = *(const float4*)(pB0);
    *(float4*)(sm + MATF + so1) = *(const float4*)(pB1);
    __syncthreads();

    const int NSTAGE = 64 / KB;    // 4
    for (int ks = 0; ks < NSTAGE; ks++) {
        int buf = ks & 1;
        float4 va0, va1, vb0, vb1;
        bool more = (ks + 1 < NSTAGE);
        if (more) {
            int k0 = (ks + 1) * KB;
            va0 = *(const float4*)(pA0 + k0);
            va1 = *(const float4*)(pA1 + k0);
            vb0 = *(const float4*)(pB0 + k0);
            vb1 = *(const float4*)(pB1 + k0);
        }

        const float* Asmp = sm + buf * STAGEF + warp_m * 64 * KSTR;
        const float* Bsmp = sm + buf * STAGEF + MATF + warp_n * 32 * KSTR;

        {
            uint32_t bhf[4][2], blf[4][2];
            #pragma unroll
            for (int nt = 0; nt < 4; nt++) {
                const float* bp = Bsmp + (nt * 8 + g) * KSTR + 2 * t4;
                float2 p0 = *(const float2*)bp;
                float2 p1 = *(const float2*)(bp + 8);
                splitpair(p0.x, p0.y, bhf[nt][0], blf[nt][0]);
                splitpair(p1.x, p1.y, bhf[nt][1], blf[nt][1]);
            }
            #pragma unroll
            for (int mt = 0; mt < 4; mt++) {
                const float* ap = Asmp + (mt * 16 + g) * KSTR + 2 * t4;
                float2 q0 = *(const float2*)ap;
                float2 q1 = *(const float2*)(ap + 8 * KSTR);
                float2 q2 = *(const float2*)(ap + 8);
                float2 q3 = *(const float2*)(ap + 8 * KSTR + 8);
                uint32_t ah[4], al[4];
                splitpair(q0.x, q0.y, ah[0], al[0]);
                splitpair(q1.x, q1.y, ah[1], al[1]);
                splitpair(q2.x, q2.y, ah[2], al[2]);
                splitpair(q3.x, q3.y, ah[3], al[3]);
                #pragma unroll
                for (int nt = 0; nt < 4; nt++) mma_bf16(acc[mt][nt], ah, bhf[nt]);
                #pragma unroll
                for (int nt = 0; nt < 4; nt++) mma_bf16(acc[mt][nt], ah, blf[nt]);
                #pragma unroll
                for (int nt = 0; nt < 4; nt++) mma_bf16(acc[mt][nt], al, bhf[nt]);
            }
        }

        if (more) {
            float* nb = sm + ((ks + 1) & 1) * STAGEF;
            __syncthreads();
            *(float4*)(nb + so0)        = va0;
            *(float4*)(nb + so1)        = va1;
            *(float4*)(nb + MATF + so0) = vb0;
            *(float4*)(nb + MATF + so1) = vb1;
            __syncthreads();
        }
    }

    #pragma unroll
    for (int mt = 0; mt < 4; mt++) {
        int r0r = row0 + warp_m * 64 + mt * 16 + g;
        int r1r = r0r + 8;
        #pragma unroll
        for (int nt = 0; nt < 4; nt++) {
            int c = col0 + warp_n * 32 + nt * 8 + 2 * t4;
            *(float2*)(Sp + (size_t)r0r * 512 + c) = make_float2(acc[mt][nt][0], acc[mt][nt][1]);
            *(float2*)(Sp + (size_t)r1r * 512 + c) = make_float2(acc[mt][nt][2], acc[mt][nt][3]);
        }
    }
}

// ---------------- bf16x3 prior MLP (double-buffered, K=64) ----------------
__global__ __launch_bounds__(256, 2) void prior_mma(const float* __restrict__ bp1,
                                                    const float* __restrict__ Wp2)
{
    extern __shared__ float sm[];
    const float* A = g_k;
    const float* Bt = g_wtp;
    int tid = threadIdx.x;
    int lane = tid & 31, wid = tid >> 5;
    int g = lane >> 2, t4 = lane & 3;
    int warp_m = wid & 1;
    int warp_n = wid >> 1;
    int row0 = blockIdx.y * 128;
    int col0 = blockIdx.x * 128;

    float acc[4][4][4];
    #pragma unroll
    for (int mt = 0; mt < 4; mt++)
        #pragma unroll
        for (int nt = 0; nt < 4; nt++)
            #pragma unroll
            for (int q = 0; q < 4; q++) acc[mt][nt][q] = 0.f;

    int r0i = tid >> 2, s0i = tid & 3;
    const float* pA0 = A  + (size_t)(row0 + r0i) * 64 + s0i * 4;
    const float* pA1 = A  + (size_t)(row0 + 64 + r0i) * 64 + s0i * 4;
    const float* pB0 = Bt + (size_t)(col0 + r0i) * 64 + s0i * 4;
    const float* pB1 = Bt + (size_t)(col0 + 64 + r0i) * 64 + s0i * 4;
    int so0 = r0i * KSTR + s0i * 4;
    int so1 = (r0i + 64) * KSTR + s0i * 4;

    *(float4*)(sm + so0)        = *(const float4*)(pA0);
    *(float4*)(sm + so1)        = *(const float4*)(pA1);
    *(float4*)(sm + MATF + so0) = *(const float4*)(pB0);
    *(float4*)(sm + MATF + so1) = *(const float4*)(pB1);
    __syncthreads();

    const int NSTAGE = 64 / KB;    // 4
    for (int ks = 0; ks < NSTAGE; ks++) {
        int buf = ks & 1;
        float4 va0, va1, vb0, vb1;
        bool more = (ks + 1 < NSTAGE);
        if (more) {
            int k0 = (ks + 1) * KB;
            va0 = *(const float4*)(pA0 + k0);
            va1 = *(const float4*)(pA1 + k0);
            vb0 = *(const float4*)(pB0 + k0);
            vb1 = *(const float4*)(pB1 + k0);
        }

        const float* Asmp = sm + buf * STAGEF + warp_m * 64 * KSTR;
        const float* Bsmp = sm + buf * STAGEF + MATF + warp_n * 32 * KSTR;

        {
            uint32_t bhf[4][2], blf[4][2];
            #pragma unroll
            for (int nt = 0; nt < 4; nt++) {
                const float* bp = Bsmp + (nt * 8 + g) * KSTR + 2 * t4;
                float2 p0 = *(const float2*)bp;
                float2 p1 = *(const float2*)(bp + 8);
                splitpair(p0.x, p0.y, bhf[nt][0], blf[nt][0]);
                splitpair(p1.x, p1.y, bhf[nt][1], blf[nt][1]);
            }
            #pragma unroll
            for (int mt = 0; mt < 4; mt++) {
                const float* ap = Asmp + (mt * 16 + g) * KSTR + 2 * t4;
                float2 q0 = *(const float2*)ap;
                float2 q1 = *(const float2*)(ap + 8 * KSTR);
                float2 q2 = *(const float2*)(ap + 8);
                float2 q3 = *(const float2*)(ap + 8 * KSTR + 8);
                uint32_t ah[4], al[4];
                splitpair(q0.x, q0.y, ah[0], al[0]);
                splitpair(q1.x, q1.y, ah[1], al[1]);
                splitpair(q2.x, q2.y, ah[2], al[2]);
                splitpair(q3.x, q3.y, ah[3], al[3]);
                #pragma unroll
                for (int nt = 0; nt < 4; nt++) mma_bf16(acc[mt][nt], ah, bhf[nt]);
                #pragma unroll
                for (int nt = 0; nt < 4; nt++) mma_bf16(acc[mt][nt], ah, blf[nt]);
                #pragma unroll
                for (int nt = 0; nt < 4; nt++) mma_bf16(acc[mt][nt], al, bhf[nt]);
            }
        }

        if (more) {
            float* nb = sm + ((ks + 1) & 1) * STAGEF;
            __syncthreads();
            *(float4*)(nb + so0)        = va0;
            *(float4*)(nb + so1)        = va1;
            *(float4*)(nb + MATF + so0) = vb0;
            *(float4*)(nb + MATF + so1) = vb1;
            __syncthreads();
        }
    }

    size_t grp = (size_t)(blockIdx.x * 4 + warp_n) * NPOS;
    #pragma unroll
    for (int mt = 0; mt < 4; mt++) {
        float rs0 = 0.f, rs1 = 0.f;
        #pragma unroll
        for (int nt = 0; nt < 4; nt++) {
            int c = col0 + warp_n * 32 + nt * 8 + 2 * t4;
            float b0 = __ldg(bp1 + c), b1 = __ldg(bp1 + c + 1);
            float w0 = __ldg(Wp2 + c), w1 = __ldg(Wp2 + c + 1);
            float hv;
            hv = acc[mt][nt][0] + b0; hv = (hv >= 0.f) ? hv : 0.01f * hv; rs0 = fmaf(hv, w0, rs0);
            hv = acc[mt][nt][1] + b1; hv = (hv >= 0.f) ? hv : 0.01f * hv; rs0 = fmaf(hv, w1, rs0);
            hv = acc[mt][nt][2] + b0; hv = (hv >= 0.f) ? hv : 0.01f * hv; rs1 = fmaf(hv, w0, rs1);
            hv = acc[mt][nt][3] + b1; hv = (hv >= 0.f) ? hv : 0.01f * hv; rs1 = fmaf(hv, w1, rs1);
        }
        rs0 += __shfl_xor_sync(0xffffffffu, rs0, 1);
        rs0 += __shfl_xor_sync(0xffffffffu, rs0, 2);
        rs1 += __shfl_xor_sync(0xffffffffu, rs1, 1);
        rs1 += __shfl_xor_sync(0xffffffffu, rs1, 2);
        if (t4 == 0) {
            int r0r = row0 + warp_m * 64 + mt * 16 + g;
            g_pp[grp + r0r]     = rs0;
            g_pp[grp + r0r + 8] = rs1;
        }
    }
}

__global__ void combine_dotg(const float* __restrict__ bp2) {
    int i = blockIdx.x * 256 + threadIdx.x;
    float s = 0.f;
    #pragma unroll
    for (int t = 0; t < 32; t++) s += g_pp[(size_t)t * NPOS + i];
    g_dotg[i] = s + bp2[0];
}

// ---------------- bf16x3 att_s @ V, cp.async 3-stage ----------------
#define VSTR 72
#define PAF 2560
#define PBF (16*VSTR)
#define PSTAGEF (PAF + PBF)
__global__ __launch_bounds__(256, 2) void pv_mma() {
    extern __shared__ float sm[];
    int bh = blockIdx.y;
    int b_ = bh >> 4, h_ = bh & 15;
    const float* A  = g_S + (size_t)bh * Ll * Ll;
    const float* Bv = g_v + (size_t)bh * Ll * DVv;
    int tid = threadIdx.x;
    int lane = tid & 31, wid = tid >> 5;
    int g = lane >> 2, t4 = lane & 3;
    int warp_m = wid & 3;
    int warp_n = wid >> 2;
    int row0 = blockIdx.x * 128;

    float acc[2][4][4];
    #pragma unroll
    for (int mt = 0; mt < 2; mt++)
        #pragma unroll
        for (int nt = 0; nt < 4; nt++)
            #pragma unroll
            for (int q = 0; q < 4; q++) acc[mt][nt][q] = 0.f;

    int r0i = tid >> 2, s0i = tid & 3;
    const float* pA0 = A + (size_t)(row0 + r0i) * 512 + s0i * 4;
    const float* pA1 = A + (size_t)(row0 + 64 + r0i) * 512 + s0i * 4;
    int rowb = tid >> 4, segb = tid & 15;
    const float* pBv = Bv + (size_t)rowb * 64 + segb * 4;
    uint32_t smb = (uint32_t)__cvta_generic_to_shared(sm);
    uint32_t ad0 = smb + (r0i * KSTR + s0i * 4) * 4;
    uint32_t ad1 = smb + ((r0i + 64) * KSTR + s0i * 4) * 4;
    uint32_t adb = smb + (PAF + rowb * VSTR + segb * 4) * 4;

    const int NSTAGE = 512 / KB;   // 32

    #pragma unroll
    for (int st = 0; st < 2; st++) {
        uint32_t b = (uint32_t)(st * PSTAGEF * 4);
        int k0 = st * KB;
        cp16(ad0 + b, pA0 + k0);
        cp16(ad1 + b, pA1 + k0);
        cp16(adb + b, pBv + (size_t)k0 * 64);
        CP_COMMIT();
    }

    for (int ks = 0; ks < NSTAGE; ks++) {
        CP_WAIT1();
        __syncthreads();
        int buf = ks % NPIPE;
        const float* Asmp = sm + buf * PSTAGEF + warp_m * 32 * KSTR;
        const float* Bsmp = sm + buf * PSTAGEF + PAF;

        {
            uint32_t bhf[4][2], blf[4][2];
            #pragma unroll
            for (int nt = 0; nt < 4; nt++) {
                int col = warp_n * 32 + nt * 8 + g;
                float b00 = Bsmp[(2 * t4) * VSTR + col];
                float b01 = Bsmp[(2 * t4 + 1) * VSTR + col];
                float b10 = Bsmp[(2 * t4 + 8) * VSTR + col];
                float b11 = Bsmp[(2 * t4 + 9) * VSTR + col];
                splitpair(b00, b01, bhf[nt][0], blf[nt][0]);
                splitpair(b10, b11, bhf[nt][1], blf[nt][1]);
            }
            #pragma unroll
            for (int mt = 0; mt < 2; mt++) {
                const float* ap = Asmp + (mt * 16 + g) * KSTR + 2 * t4;
                float2 q0 = *(const float2*)ap;
                float2 q1 = *(const float2*)(ap + 8 * KSTR);
                float2 q2 = *(const float2*)(ap + 8);
                float2 q3 = *(const float2*)(ap + 8 * KSTR + 8);
                uint32_t ah[4], al[4];
                splitpair(q0.x, q0.y, ah[0], al[0]);
                splitpair(q1.x, q1.y, ah[1], al[1]);
                splitpair(q2.x, q2.y, ah[2], al[2]);
                splitpair(q3.x, q3.y, ah[3], al[3]);
                #pragma unroll
                for (int nt = 0; nt < 4; nt++) mma_bf16(acc[mt][nt], ah, bhf[nt]);
                #pragma unroll
                for (int nt = 0; nt < 4; nt++) mma_bf16(acc[mt][nt], ah, blf[nt]);
                #pragma unroll
                for (int nt = 0; nt < 4; nt++) mma_bf16(acc[mt][nt], al, bhf[nt]);
            }
        }

        int ns = ks + 2;
        if (ns < NSTAGE) {
            uint32_t b = (uint32_t)((ns % NPIPE) * PSTAGEF * 4);
            int k0 = ns * KB;
            cp16(ad0 + b, pA0 + k0);
            cp16(ad1 + b, pA1 + k0);
            cp16(adb + b, pBv + (size_t)k0 * 64);
        }
        CP_COMMIT();
    }

    #pragma unroll
    for (int mt = 0; mt < 2; mt++) {
        int r0r = row0 + warp_m * 32 + mt * 16 + g;
        int r1r = r0r + 8;
        #pragma unroll
        for (int nt = 0; nt < 4; nt++) {
            int c = warp_n * 32 + nt * 8 + 2 * t4;
            *(float2*)(g_ao + ((size_t)b_ * Ll + r0r) * Dd + h_ * DVv + c) =
                make_float2(acc[mt][nt][0], acc[mt][nt][1]);
            *(float2*)(g_ao + ((size_t)b_ * Ll + r1r) * Dd + h_ * DVv + c) =
                make_float2(acc[mt][nt][2], acc[mt][nt][3]);
        }
    }
}

// ---------------- block reduction helper ----------------
__device__ __forceinline__ float blkred(float v, bool ismax, float* sred) {
    #pragma unroll
    for (int o = 16; o; o >>= 1) {
        float w = __shfl_xor_sync(0xffffffffu, v, o);
        v = ismax ? fmaxf(v, w) : v + w;
    }
    int wid = threadIdx.x >> 5, lid = threadIdx.x & 31;
    int nw = blockDim.x >> 5;
    if (lid == 0) sred[wid] = v;
    __syncthreads();
    if (wid == 0) {
        v = (lid < nw) ? sred[lid] : (ismax ? -3.402823e38f : 0.f);
        #pragma unroll
        for (int o = 16; o; o >>= 1) {
            float w = __shfl_xor_sync(0xffffffffu, v, o);
            v = ismax ? fmaxf(v, w) : v + w;
        }
        if (lid == 0) sred[0] = v;
    }
    __syncthreads();
    float r = sred[0];
    __syncthreads();
    return r;
}

// ---------------- fast branchless lgamma ----------------
__device__ __forceinline__ float lgamma_fast(float x) {
    bool refl = (x < 0.5f);
    float z = refl ? 1.0f - x : x;
    float p = 1.0f;
    #pragma unroll
    for (int i = 0; i < 8; i++) {
        if (z < 8.0f) { p *= z; z += 1.0f; }
    }
    float invz  = 1.0f / z;
    float invz2 = invz * invz;
    float lz = __logf(z);
    float lg = (z - 0.5f) * lz - z + 0.91893853320467274f
             + invz * (8.3333333333e-2f
             + invz2 * (-2.7777777778e-3f + 7.9365079365e-4f * invz2));
    lg -= __logf(p);
    if (refl) {
        float s = sinpif(x);
        lg = 1.1447298858494002f - __logf(fabsf(s)) - lg;
    }
    return lg;
}

// ---------------- alpha softmax + per-(b,h) KL constant terms ----------------
__global__ __launch_bounds__(512) void alpha_kernel() {
    __shared__ float sred[32];
    int bh = blockIdx.x;
    int t = threadIdx.x;
    float x = g_dotg[bh * Ll + t];
    float m = blkred(x, true, sred);
    float e = expf(x - m);
    float den = blkred(e, false, sred);
    float a = e / den;
    g_alpha[bh * Ll + t] = a;
    const float lg1 = 0.69314718f;
    const float EG  = 0.5772156649f;
    float C = a * lg1 + 2.f * EG * a + lgammaf(a + EPSF);
    float sc = blkred(C, false, sred);
    if (t == 0) atomicAdd(&g_kl, (double)(512.0f * sc));
}

// ---------------- fused row pass: warp per row ----------------
__global__ __launch_bounds__(256) void row_fused(const float* __restrict__ U) {
    int lane = threadIdx.x & 31;
    int wrp = threadIdx.x >> 5;
    int row = blockIdx.x * 8 + wrp;
    int bh = row >> 9;
    size_t base = (size_t)row * 512;

    float s[16];
    float m = -3.402823e38f;
    #pragma unroll
    for (int i = 0; i < 16; i++) {
        s[i] = g_S[base + lane + 32 * i];
        m = fmaxf(m, s[i]);
    }
    #pragma unroll
    for (int o = 16; o; o >>= 1) m = fmaxf(m, __shfl_xor_sync(0xffffffffu, m, o));

    float den = 0.f;
    #pragma unroll
    for (int i = 0; i < 16; i++) den += __expf(s[i] - m);
    #pragma unroll
    for (int o = 16; o; o >>= 1) den += __shfl_xor_sync(0xffffffffu, den, o);
    float logden = __logf(den);

    float t[16];
    float kl = 0.f;
    #pragma unroll
    for (int i = 0; i < 16; i++) {
        float r = s[i] - m - logden;
        float p = __expf(r);
        float lp = (r > -41.4f) ? r : __logf(p + EPSF);
        float a = g_alpha[bh * 512 + lane + 32 * i];
        kl += fmaf(-a, lp, p);
        float u = U[base + lane + 32 * i];
        float ws = u * (1.f + u * (0.5f + 0.33333333f * u));
        float wl = -__logf(1.f - u + EPSF);
        float w = (u < 0.015f) ? ws : wl;
        float gw = __logf(w + EPSF);
        t[i] = lp - lgamma_fast(3.f + 2.f * gw);
    }

    float m2 = -3.402823e38f;
    #pragma unroll
    for (int i = 0; i < 16; i++) m2 = fmaxf(m2, t[i]);
    #pragma unroll
    for (int o = 16; o; o >>= 1) m2 = fmaxf(m2, __shfl_xor_sync(0xffffffffu, m2, o));

    float d2 = 0.f;
    #pragma unroll
    for (int i = 0; i < 16; i++) d2 += __expf(t[i] - m2);
    #pragma unroll
    for (int o = 16; o; o >>= 1) d2 += __shfl_xor_sync(0xffffffffu, d2, o);
    float i2 = 1.f / d2;

    #pragma unroll
    for (int i = 0; i < 16; i++)
        g_S[base + lane + 32 * i] = __expf(t[i] - m2) * i2;

    #pragma unroll
    for (int o = 16; o; o >>= 1) kl += __shfl_xor_sync(0xffffffffu, kl, o);
    if (lane == 0) atomicAdd(&g_kl, (double)kl);
}

// ---------------- misc ----------------
__global__ void zero_kernel() { g_kl = 0.0; }

__global__ void finalize_kernel(float* out, int out_size) {
    if (out_size > Bb * Ll * Dd)
        out[Bb * Ll * Dd] = (float)(g_kl / 33554432.0);
}

// ---------------- launch ----------------
extern "C" void kernel_launch(void* const* d_in, const int* in_sizes, int n_in,
                              void* d_out, int out_size) {
    const float* queries = (const float*)d_in[0];
    const float* keys    = (const float*)d_in[1];
    const float* values  = (const float*)d_in[2];
    const float* unif    = (const float*)d_in[3];
    const float* Wq = (const float*)d_in[4];
    const float* bq = (const float*)d_in[5];
    const float* Wk = (const float*)d_in[6];
    const float* bk = (const float*)d_in[7];
    const float* Wv = (const float*)d_in[8];
    const float* bv = (const float*)d_in[9];
    const float* Wo = (const float*)d_in[10];
    const float* bo = (const float*)d_in[11];
    const float* Wp1 = (const float*)d_in[12];
    const float* bp1 = (const float*)d_in[13];
    const float* Wp2 = (const float*)d_in[14];
    const float* bp2 = (const float*)d_in[15];
    float* out = (float*)d_out;

    float *pq, *pk, *pv_;
    cudaGetSymbolAddress((void**)&pq, g_q);
    cudaGetSymbolAddress((void**)&pk, g_k);
    cudaGetSymbolAddress((void**)&pv_, g_v);

    const int GSMEM  = NPIPE * STAGEF * 4;    // 61440 B
    const int DBSMEM = 2 * STAGEF * 4;        // 40960 B
    const int PSMEM  = NPIPE * PSTAGEF * 4;   // 44544 B
    static int smem_set = 0;
    if (!smem_set) {
        cudaFuncSetAttribute(qkv_mma, cudaFuncAttributeMaxDynamicSharedMemorySize, GSMEM);
        cudaFuncSetAttribute(out_mma, cudaFuncAttributeMaxDynamicSharedMemorySize, GSMEM);
        cudaFuncSetAttribute(score_mma, cudaFuncAttributeMaxDynamicSharedMemorySize, DBSMEM);
        cudaFuncSetAttribute(prior_mma, cudaFuncAttributeMaxDynamicSharedMemorySize, DBSMEM);
        cudaFuncSetAttribute(pv_mma, cudaFuncAttributeMaxDynamicSharedMemorySize, PSMEM);
        smem_set = 1;
    }

    zero_kernel<<<1, 1>>>();

    dim3 tr(32, 8);
    transpose4<<<dim3(32, 32, 4), tr>>>(Wq, Wk, Wv, Wo);
    transpose_p<<<dim3(32, 2), tr>>>(Wp1);

    qkv_mma<<<dim3(8, 32, 3), 256, GSMEM>>>(queries, keys, values, bq, bk, bv, pq, pk, pv_);

    prior_mma<<<dim3(8, 512), 256, DBSMEM>>>(bp1, Wp2);
    combine_dotg<<<256, 256>>>(bp2);
    alpha_kernel<<<BH, 512>>>();

    score_mma<<<dim3(4, 4, BH), 256, DBSMEM>>>();
    row_fused<<<NPOS / 8, 256>>>(unif);
    pv_mma<<<dim3(4, BH), 256, PSMEM>>>();

    out_mma<<<dim3(8, 32), 256, GSMEM>>>(bo, out);

    finalize_kernel<<<1, 1>>>(out, out_size);
}